// round 8
// baseline (speedup 1.0000x reference)
#include <cuda_runtime.h>
#include <cstdint>
#include <cstddef>

#define MAXN 10000
#define MAXE 160000
#define NSM  148

typedef unsigned long long ull;

__device__ float g_x0[MAXN * 16];
__device__ float g_x1[MAXN * 12];
__device__ float g_qd0[MAXN * 8];
__device__ float g_qd1[MAXN * 6];
__device__ float g_logit[MAXE];
__device__ float g_v[MAXE * 28];       // SoA: [j*E + e]
__device__ float g_m[MAXN];
__device__ float g_z[MAXN];
__device__ float g_agg[MAXN * 28];     // AoS
__device__ float g_h2k[(size_t)MAXE * 64];   // TRANSPOSED: [c*E + e]
__device__ float g_h2v[(size_t)MAXE * 64];   // TRANSPOSED: [c*E + e]

__device__ __forceinline__ float frelu(float x) { return x > 0.f ? x : 0.f; }

// ---- packed f32x2 helpers (Blackwell FFMA2) -------------------------------
__device__ __forceinline__ ull pack2(float lo, float hi) {
    ull r; asm("mov.b64 %0, {%1, %2};" : "=l"(r) : "f"(lo), "f"(hi)); return r;
}
__device__ __forceinline__ void unpack2(ull v, float& lo, float& hi) {
    asm("mov.b64 {%0, %1}, %2;" : "=f"(lo), "=f"(hi) : "l"(v));
}
__device__ __forceinline__ void ffma2(ull& d, ull a, ull b) {
    asm("fma.rn.f32x2 %0, %1, %2, %0;" : "+l"(d) : "l"(a), "l"(b));
}

// dual-edge dot (used by front kernel only)
template <int NU2>
__device__ __forceinline__ void dotp2(const float* __restrict__ w,
                                      const ull* __restrict__ hA,
                                      const ull* __restrict__ hB,
                                      float& rA, float& rB) {
    ull a0 = 0ull, a1 = 0ull, b0 = 0ull, b1 = 0ull;
    const ulonglong2* wp = reinterpret_cast<const ulonglong2*>(w);
#pragma unroll
    for (int t = 0; t < NU2; t++) {
        ulonglong2 ww = wp[t];
        ffma2(a0, ww.x, hA[2 * t]);
        ffma2(a1, ww.y, hA[2 * t + 1]);
        ffma2(b0, ww.x, hB[2 * t]);
        ffma2(b1, ww.y, hB[2 * t + 1]);
    }
    float x0, x1, x2, x3;
    unpack2(a0, x0, x1); unpack2(a1, x2, x3);
    rA = (x0 + x1) + (x2 + x3);
    unpack2(b0, x0, x1); unpack2(b1, x2, x3);
    rB = (x0 + x1) + (x2 + x3);
}

__device__ __forceinline__ void atomicMaxF(float* addr, float v) {
    if (v >= 0.f) atomicMax((int*)addr, __float_as_int(v));
    else          atomicMin((unsigned int*)addr, __float_as_uint(v));
}

// ---------------------------------------------------------------------------
// Kernel A: node prep (x = ir_linear(node_attr); qd = (q @ Wd) precontracted)
// ---------------------------------------------------------------------------
__global__ void node_prep_kernel(const float* __restrict__ na,
                                 const float* __restrict__ Win0,
                                 const float* __restrict__ Win1,
                                 const float* __restrict__ Wq0,
                                 const float* __restrict__ Wq1,
                                 const float* __restrict__ Wd0,
                                 const float* __restrict__ Wd1,
                                 int N) {
    __shared__ float sWin0[512], sWin1[32], sWq0[128], sWq1[8], sWd0[64], sWd1[4];
    int tid = threadIdx.x;
    for (int i = tid; i < 512; i += blockDim.x) sWin0[i] = Win0[i];
    for (int i = tid; i < 32;  i += blockDim.x) sWin1[i] = Win1[i];
    for (int i = tid; i < 128; i += blockDim.x) sWq0[i]  = Wq0[i];
    for (int i = tid; i < 8;   i += blockDim.x) sWq1[i]  = Wq1[i];
    for (int i = tid; i < 64;  i += blockDim.x) sWd0[i]  = Wd0[i];
    for (int i = tid; i < 4;   i += blockDim.x) sWd1[i]  = Wd1[i];
    __syncthreads();

    int n = blockIdx.x * blockDim.x + tid;
    if (n >= N) return;

    const float* p = na + (size_t)n * 56;
    float a0[32], a1[24];
#pragma unroll
    for (int i = 0; i < 32; i++) a0[i] = p[i];
#pragma unroll
    for (int i = 0; i < 24; i++) a1[i] = p[32 + i];

    float x0[16];
#pragma unroll
    for (int o = 0; o < 16; o++) {
        float s = 0.f;
#pragma unroll
        for (int i = 0; i < 32; i++) s = fmaf(a0[i], sWin0[i * 16 + o], s);
        x0[o] = s * 0.17677669529663687f;   // 1/sqrt(32)
    }
    float x1[12];
#pragma unroll
    for (int o = 0; o < 4; o++)
#pragma unroll
        for (int c = 0; c < 3; c++) {
            float s = 0.f;
#pragma unroll
            for (int m = 0; m < 8; m++) s = fmaf(a1[m * 3 + c], sWin1[m * 4 + o], s);
            x1[o * 3 + c] = s * 0.35355339059327373f;  // 1/sqrt(8)
        }

    float q0[8];
#pragma unroll
    for (int b = 0; b < 8; b++) {
        float s = 0.f;
#pragma unroll
        for (int o = 0; o < 16; o++) s = fmaf(x0[o], sWq0[o * 8 + b], s);
        q0[b] = s * 0.25f;                   // 1/sqrt(16)
    }
    float q1[6];
#pragma unroll
    for (int j = 0; j < 2; j++)
#pragma unroll
        for (int c = 0; c < 3; c++) {
            float s = 0.f;
#pragma unroll
            for (int o = 0; o < 4; o++) s = fmaf(x1[o * 3 + c], sWq1[o * 2 + j], s);
            q1[j * 3 + c] = s * 0.5f;        // 1/sqrt(4)
        }

#pragma unroll
    for (int j = 0; j < 8; j++) {
        float s = 0.f;
#pragma unroll
        for (int i = 0; i < 8; i++) s = fmaf(q0[i], sWd0[i * 8 + j], s);
        g_qd0[(size_t)n * 8 + j] = s;
    }
#pragma unroll
    for (int j = 0; j < 2; j++)
#pragma unroll
        for (int c = 0; c < 3; c++) {
            float s = 0.f;
#pragma unroll
            for (int i = 0; i < 2; i++) s = fmaf(q1[i * 3 + c], sWd1[i * 2 + j], s);
            g_qd1[(size_t)n * 6 + j * 3 + c] = s;
        }

#pragma unroll
    for (int o = 0; o < 16; o++) g_x0[(size_t)n * 16 + o] = x0[o];
#pragma unroll
    for (int o = 0; o < 12; o++) g_x1[(size_t)n * 12 + o] = x1[o];
}

// ---------------------------------------------------------------------------
__global__ void init_kernel(int N) {
    int i = blockIdx.x * blockDim.x + threadIdx.x;
    if (i < N * 28) g_agg[i] = 0.f;
    if (i < N) {
        g_m[i] = __int_as_float(0xff800000);  // -inf
        g_z[i] = 0.f;
    }
}

// ---------------------------------------------------------------------------
// FRONT kernel (EPT=2): both MLP fronts (32->64->64), writes h2 TRANSPOSED
// ---------------------------------------------------------------------------
#define F_OW1K 0
#define F_OB1K 2048
#define F_OW2K 2112
#define F_OB2K 6208
#define F_OW1V 6272
#define F_OB1V 8320
#define F_OW2V 8384
#define F_OB2V 12480
#define F_FLOATS 12544

__device__ __forceinline__ void front_one2(const float* __restrict__ sm,
                                           int oW1, int oB1, int oW2, int oB2,
                                           const float* __restrict__ edge_attr,
                                           float* __restrict__ gh2,
                                           size_t e0, size_t e1, bool hb, int E) {
    ull eapA[16], eapB[16];
    {
        const ulonglong2* a2 = reinterpret_cast<const ulonglong2*>(edge_attr + e0 * 32);
        const ulonglong2* b2 = reinterpret_cast<const ulonglong2*>(edge_attr + e1 * 32);
#pragma unroll
        for (int t = 0; t < 8; t++) {
            ulonglong2 va = a2[t]; ulonglong2 vb = b2[t];
            eapA[2 * t] = va.x; eapA[2 * t + 1] = va.y;
            eapB[2 * t] = vb.x; eapB[2 * t + 1] = vb.y;
        }
    }
    ull h1A[32], h1B[32];
#pragma unroll 4
    for (int o = 0; o < 64; o += 2) {
        float loA, loB, hiA, hiB;
        dotp2<8>(sm + oW1 + o * 32,       eapA, eapB, loA, loB);
        dotp2<8>(sm + oW1 + (o + 1) * 32, eapA, eapB, hiA, hiB);
        float b_lo = sm[oB1 + o], b_hi = sm[oB1 + o + 1];
        h1A[o >> 1] = pack2(frelu(b_lo + loA), frelu(b_hi + hiA));
        h1B[o >> 1] = pack2(frelu(b_lo + loB), frelu(b_hi + hiB));
    }
#pragma unroll 2
    for (int o = 0; o < 64; o += 4) {
        float vA[4], vB[4];
#pragma unroll
        for (int k = 0; k < 4; k++) {
            float a, b;
            dotp2<16>(sm + oW2 + (o + k) * 64, h1A, h1B, a, b);
            float bias = sm[oB2 + o + k];
            vA[k] = frelu(bias + a);
            vB[k] = frelu(bias + b);
        }
        // transposed (c-major) stores — coalesced across the warp
#pragma unroll
        for (int k = 0; k < 4; k++) {
            gh2[(size_t)(o + k) * E + e0] = vA[k];
            if (hb) gh2[(size_t)(o + k) * E + e1] = vB[k];
        }
    }
}

__global__ void __launch_bounds__(128, 2)
front_kernel(const float* __restrict__ edge_attr,
             const float* __restrict__ fcW1, const float* __restrict__ fcb1,
             const float* __restrict__ fcW2, const float* __restrict__ fcb2,
             const float* __restrict__ fkW1, const float* __restrict__ fkb1,
             const float* __restrict__ fkW2, const float* __restrict__ fkb2,
             int E) {
    extern __shared__ float sm[];
    int tid = threadIdx.x, bs = blockDim.x;
    for (int i = tid; i < 2048; i += bs) { int o = i >> 5, c = i & 31; sm[F_OW1K + i] = fkW1[c * 64 + o]; }
    for (int i = tid; i < 64;   i += bs) sm[F_OB1K + i] = fkb1[i];
    for (int i = tid; i < 4096; i += bs) { int o = i >> 6, c = i & 63; sm[F_OW2K + i] = fkW2[c * 64 + o]; }
    for (int i = tid; i < 64;   i += bs) sm[F_OB2K + i] = fkb2[i];
    for (int i = tid; i < 2048; i += bs) { int o = i >> 5, c = i & 31; sm[F_OW1V + i] = fcW1[c * 64 + o]; }
    for (int i = tid; i < 64;   i += bs) sm[F_OB1V + i] = fcb1[i];
    for (int i = tid; i < 4096; i += bs) { int o = i >> 6, c = i & 63; sm[F_OW2V + i] = fcW2[c * 64 + o]; }
    for (int i = tid; i < 64;   i += bs) sm[F_OB2V + i] = fcb2[i];
    __syncthreads();

    int stride = gridDim.x * bs;
    for (int e0 = blockIdx.x * bs + tid; e0 < E; e0 += 2 * stride) {
        int e1 = e0 + stride;
        bool hb = e1 < E;
        size_t e1c = hb ? (size_t)e1 : (size_t)e0;
        front_one2(sm, F_OW1K, F_OB1K, F_OW2K, F_OB2K, edge_attr, g_h2k,
                   (size_t)e0, e1c, hb, E);
        front_one2(sm, F_OW1V, F_OB1V, F_OW2V, F_OB2V, edge_attr, g_h2v,
                   (size_t)e0, e1c, hb, E);
    }
}

// ---------------------------------------------------------------------------
// L3 GEMM machinery
//   Tile: 128 edges. C[w=224pad][e=128] = A[c=64][e=128]^T-style GEMM.
//   Thread (re=warp 0..7, cw=lane 0..31): 16 edges (8 f32x2 pairs) x 7 outputs.
// smem floats: B 64*224=14336 | A 64*128=8192 | C 224*132=29568 | bias 224
// ---------------------------------------------------------------------------
#define TE     128
#define NWP    224
#define CPAD   132
#define L3_B_OFF   0
#define L3_A_OFF   14336
#define L3_C_OFF   22528
#define L3_BIAS_OFF 52096
#define L3_FLOATS  52320

__device__ __forceinline__ void l3_load_A(float* __restrict__ As,
                                          const float* __restrict__ gh2T,
                                          int e0, int E, int tid) {
    // As[c][e] = gh2T[c*E + e0 + e]
    for (int i = tid; i < 64 * (TE / 4); i += 256) {
        int c = i / (TE / 4);
        int v = i % (TE / 4);
        int eb = e0 + 4 * v;
        float4 f;
        if (eb + 3 < E) {
            f = *reinterpret_cast<const float4*>(gh2T + (size_t)c * E + eb);
        } else {
            f.x = (eb + 0 < E) ? gh2T[(size_t)c * E + eb + 0] : 0.f;
            f.y = (eb + 1 < E) ? gh2T[(size_t)c * E + eb + 1] : 0.f;
            f.z = (eb + 2 < E) ? gh2T[(size_t)c * E + eb + 2] : 0.f;
            f.w = (eb + 3 < E) ? gh2T[(size_t)c * E + eb + 3] : 0.f;
        }
        *reinterpret_cast<float4*>(As + c * TE + 4 * v) = f;
    }
}

__device__ __forceinline__ void l3_gemm(const float* __restrict__ As,
                                        const float* __restrict__ Bs,
                                        float* __restrict__ Cs, int tid) {
    int re = tid >> 5;   // warp id -> 16-edge group
    int cw = tid & 31;   // lane -> 7-output group
    ull acc[7][8];
#pragma unroll
    for (int n = 0; n < 7; n++)
#pragma unroll
        for (int p = 0; p < 8; p++) acc[n][p] = 0ull;

#pragma unroll 4
    for (int k = 0; k < 64; k++) {
        const ulonglong2* ap =
            reinterpret_cast<const ulonglong2*>(As + k * TE + 16 * re);
        ulonglong2 t0 = ap[0], t1 = ap[1], t2 = ap[2], t3 = ap[3];
        ull av[8] = {t0.x, t0.y, t1.x, t1.y, t2.x, t2.y, t3.x, t3.y};
        const float* bp = Bs + k * NWP + 7 * cw;
        ull bv[7];
#pragma unroll
        for (int n = 0; n < 7; n++) bv[n] = pack2(bp[n], bp[n]);
#pragma unroll
        for (int n = 0; n < 7; n++)
#pragma unroll
            for (int p = 0; p < 8; p++) ffma2(acc[n][p], av[p], bv[n]);
    }
    // store C[w][e]
#pragma unroll
    for (int n = 0; n < 7; n++) {
        ulonglong2* cp =
            reinterpret_cast<ulonglong2*>(Cs + (7 * cw + n) * CPAD + 16 * re);
        ulonglong2 u;
        u.x = acc[n][0]; u.y = acc[n][1]; cp[0] = u;
        u.x = acc[n][2]; u.y = acc[n][3]; cp[1] = u;
        u.x = acc[n][4]; u.y = acc[n][5]; cp[2] = u;
        u.x = acc[n][6]; u.y = acc[n][7]; cp[3] = u;
    }
}

// ---------------------------------------------------------------------------
// L3K: GEMM + K contraction + logit + atomicMax
// ---------------------------------------------------------------------------
__global__ void __launch_bounds__(256, 1)
l3k_kernel(const float* __restrict__ edge_sh,
           const int*   __restrict__ eidx,
           const float* __restrict__ fkW3, const float* __restrict__ fkb3,
           int E) {
    extern __shared__ float smx[];
    float* Bs  = smx + L3_B_OFF;
    float* As  = smx + L3_A_OFF;
    float* Cs  = smx + L3_C_OFF;
    float* sB3 = smx + L3_BIAS_OFF;
    int tid = threadIdx.x;

    for (int i = tid; i < 64 * NWP; i += 256) {
        int c = i / NWP, w = i % NWP;
        Bs[i] = (w < 200) ? fkW3[c * 200 + w] : 0.f;
    }
    for (int i = tid; i < NWP; i += 256)
        sB3[i] = (i < 200) ? fkb3[i] : 0.f;

    int e0 = blockIdx.x * TE;
    l3_load_A(As, g_h2k, e0, E, tid);
    __syncthreads();

    l3_gemm(As, Bs, Cs, tid);
    __syncthreads();

    if (tid < TE) {
        int e = e0 + tid;
        if (e < E) {
            const float NORM = 0.22360679774997896f;  // 1/sqrt(20)
            const float I3   = 0.5773502691896258f;   // 1/sqrt(3)
            int s = eidx[e], d = eidx[E + e];
            float4 sh = reinterpret_cast<const float4*>(edge_sh)[e];

            float xl0[16], xl1[12], ul1[4];
#pragma unroll
            for (int o = 0; o < 16; o++) xl0[o] = g_x0[(size_t)s * 16 + o];
#pragma unroll
            for (int o = 0; o < 12; o++) xl1[o] = g_x1[(size_t)s * 12 + o];
#pragma unroll
            for (int j = 0; j < 4; j++)
                ul1[j] = xl1[j * 3] * sh.y + xl1[j * 3 + 1] * sh.z + xl1[j * 3 + 2] * sh.w;

            float logit = 0.f;
#pragma unroll 1
            for (int b = 0; b < 8; b++) {
                float acc0 = 0.f;
#pragma unroll
                for (int a = 0; a < 16; a++) {
                    int r = a * 8 + b;
                    acc0 = fmaf(xl0[a], Cs[r * CPAD + tid] + sB3[r], acc0);
                }
                float acc1 = 0.f;
#pragma unroll
                for (int a = 0; a < 4; a++) {
                    int r = 168 + a * 8 + b;
                    acc1 = fmaf(ul1[a], Cs[r * CPAD + tid] + sB3[r], acc1);
                }
                float k0b = NORM * fmaf(sh.x, acc0, I3 * acc1);
                logit = fmaf(g_qd0[(size_t)d * 8 + b], k0b, logit);
            }
#pragma unroll 1
            for (int j = 0; j < 2; j++) {
                float c01 = 0.f;
#pragma unroll
                for (int a = 0; a < 16; a++) {
                    int r = 128 + a * 2 + j;
                    c01 = fmaf(xl0[a], Cs[r * CPAD + tid] + sB3[r], c01);
                }
                float dx = 0.f, dy = 0.f, dz = 0.f;
#pragma unroll
                for (int a = 0; a < 4; a++) {
                    int r = 160 + a * 2 + j;
                    float w = Cs[r * CPAD + tid] + sB3[r];
                    dx = fmaf(xl1[a * 3 + 0], w, dx);
                    dy = fmaf(xl1[a * 3 + 1], w, dy);
                    dz = fmaf(xl1[a * 3 + 2], w, dz);
                }
                float k1x = NORM * (sh.y * c01 + sh.x * dx);
                float k1y = NORM * (sh.z * c01 + sh.x * dy);
                float k1z = NORM * (sh.w * c01 + sh.x * dz);
                logit += I3 * (g_qd1[(size_t)d * 6 + j * 3 + 0] * k1x +
                               g_qd1[(size_t)d * 6 + j * 3 + 1] * k1y +
                               g_qd1[(size_t)d * 6 + j * 3 + 2] * k1z);
            }
            logit *= 0.31622776601683794f;  // 1/sqrt(10)
            g_logit[e] = logit;
            atomicMaxF(&g_m[d], logit);
        }
    }
}

// ---------------------------------------------------------------------------
// L3V (HALF = 0/1): GEMM + V contraction for half the outputs
// ---------------------------------------------------------------------------
template <int HALF>
__device__ __forceinline__ int v_wi(int r) {
    if (r < 128) { int a = r >> 3, b = r & 7;        return a * 16 + HALF * 8 + b; }
    if (r < 160) { int t = r - 128; int a = t >> 1;  return 256 + a * 4 + HALF * 2 + (t & 1); }
    if (r < 168) { int t = r - 160; int a = t >> 1;  return 320 + a * 4 + HALF * 2 + (t & 1); }
    { int t = r - 168; int a = t >> 3, b = t & 7;    return 336 + a * 16 + HALF * 8 + b; }
}

template <int HALF>
__global__ void __launch_bounds__(256, 1)
l3v_kernel(const float* __restrict__ edge_sh,
           const int*   __restrict__ eidx,
           const float* __restrict__ fcW3, const float* __restrict__ fcb3,
           int E) {
    extern __shared__ float smx[];
    float* Bs  = smx + L3_B_OFF;
    float* As  = smx + L3_A_OFF;
    float* Cs  = smx + L3_C_OFF;
    float* sB3 = smx + L3_BIAS_OFF;
    int tid = threadIdx.x;

    for (int i = tid; i < 64 * NWP; i += 256) {
        int c = i / NWP, w = i % NWP;
        Bs[i] = (w < 200) ? fcW3[c * 400 + v_wi<HALF>(w)] : 0.f;
    }
    for (int i = tid; i < NWP; i += 256)
        sB3[i] = (i < 200) ? fcb3[v_wi<HALF>(i)] : 0.f;

    int e0 = blockIdx.x * TE;
    l3_load_A(As, g_h2v, e0, E, tid);
    __syncthreads();

    l3_gemm(As, Bs, Cs, tid);
    __syncthreads();

    if (tid < TE) {
        int e = e0 + tid;
        if (e < E) {
            const float NORM = 0.22360679774997896f;  // 1/sqrt(20)
            const float I3   = 0.5773502691896258f;   // 1/sqrt(3)
            int s = eidx[e];
            float4 sh = reinterpret_cast<const float4*>(edge_sh)[e];

            float xl0[16], xl1[12], ul1[4];
#pragma unroll
            for (int o = 0; o < 16; o++) xl0[o] = g_x0[(size_t)s * 16 + o];
#pragma unroll
            for (int o = 0; o < 12; o++) xl1[o] = g_x1[(size_t)s * 12 + o];
#pragma unroll
            for (int j = 0; j < 4; j++)
                ul1[j] = xl1[j * 3] * sh.y + xl1[j * 3 + 1] * sh.z + xl1[j * 3 + 2] * sh.w;

#pragma unroll 1
            for (int b = 0; b < 8; b++) {
                float acc0 = 0.f;
#pragma unroll
                for (int a = 0; a < 16; a++) {
                    int r = a * 8 + b;
                    acc0 = fmaf(xl0[a], Cs[r * CPAD + tid] + sB3[r], acc0);
                }
                float acc1 = 0.f;
#pragma unroll
                for (int a = 0; a < 4; a++) {
                    int r = 168 + a * 8 + b;
                    acc1 = fmaf(ul1[a], Cs[r * CPAD + tid] + sB3[r], acc1);
                }
                int bg = HALF * 8 + b;
                g_v[(size_t)bg * E + e] = NORM * fmaf(sh.x, acc0, I3 * acc1);
            }
#pragma unroll 1
            for (int j = 0; j < 2; j++) {
                float c01 = 0.f;
#pragma unroll
                for (int a = 0; a < 16; a++) {
                    int r = 128 + a * 2 + j;
                    c01 = fmaf(xl0[a], Cs[r * CPAD + tid] + sB3[r], c01);
                }
                float dx = 0.f, dy = 0.f, dz = 0.f;
#pragma unroll
                for (int a = 0; a < 4; a++) {
                    int r = 160 + a * 2 + j;
                    float w = Cs[r * CPAD + tid] + sB3[r];
                    dx = fmaf(xl1[a * 3 + 0], w, dx);
                    dy = fmaf(xl1[a * 3 + 1], w, dy);
                    dz = fmaf(xl1[a * 3 + 2], w, dz);
                }
                int jg = HALF * 2 + j;
                g_v[(size_t)(16 + jg * 3 + 0) * E + e] = NORM * (sh.y * c01 + sh.x * dx);
                g_v[(size_t)(16 + jg * 3 + 1) * E + e] = NORM * (sh.z * c01 + sh.x * dy);
                g_v[(size_t)(16 + jg * 3 + 2) * E + e] = NORM * (sh.w * c01 + sh.x * dz);
            }
        }
    }
}

// ---------------------------------------------------------------------------
__global__ void softmax_agg_kernel(const int* __restrict__ eidx, int E) {
    int e = blockIdx.x * blockDim.x + threadIdx.x;
    if (e >= E) return;
    int d = eidx[E + e];
    float p = __expf(g_logit[e] - g_m[d]);
    atomicAdd(&g_z[d], p);
#pragma unroll
    for (int j = 0; j < 28; j++)
        atomicAdd(&g_agg[(size_t)d * 28 + j], p * g_v[(size_t)j * E + e]);
}

// ---------------------------------------------------------------------------
__global__ void node_out_kernel(const float* __restrict__ na,
                                const float* __restrict__ Wo0,
                                const float* __restrict__ Wo1,
                                float* __restrict__ out, int N) {
    __shared__ float sW0[512], sW1[32];
    int tid = threadIdx.x;
    for (int i = tid; i < 512; i += blockDim.x) sW0[i] = Wo0[i];
    for (int i = tid; i < 32;  i += blockDim.x) sW1[i] = Wo1[i];
    __syncthreads();

    int n = blockIdx.x * blockDim.x + tid;
    if (n >= N) return;
    float z = g_z[n];
    float zi = z > 0.f ? 1.f / z : 0.f;
    float ag[28];
#pragma unroll
    for (int j = 0; j < 28; j++) ag[j] = g_agg[(size_t)n * 28 + j] * zi;

#pragma unroll
    for (int o = 0; o < 32; o++) {
        float s = 0.f;
#pragma unroll
        for (int a = 0; a < 16; a++) s = fmaf(ag[a], sW0[a * 32 + o], s);
        out[(size_t)n * 56 + o] = fmaf(s, 0.25f, na[(size_t)n * 56 + o]);
    }
#pragma unroll
    for (int o = 0; o < 8; o++)
#pragma unroll
        for (int c = 0; c < 3; c++) {
            float s = 0.f;
#pragma unroll
            for (int a = 0; a < 4; a++) s = fmaf(ag[16 + a * 3 + c], sW1[a * 8 + o], s);
            out[(size_t)n * 56 + 32 + o * 3 + c] =
                fmaf(s, 0.5f, na[(size_t)n * 56 + 32 + o * 3 + c]);
        }
}

// ---------------------------------------------------------------------------
extern "C" void kernel_launch(void* const* d_in, const int* in_sizes, int n_in,
                              void* d_out, int out_size) {
    const float* node_attr  = (const float*)d_in[0];
    const float* edge_attr  = (const float*)d_in[1];
    const float* edge_sh    = (const float*)d_in[2];
    const int*   edge_index = (const int*)  d_in[3];
    const float* W_in0  = (const float*)d_in[4];
    const float* W_in1  = (const float*)d_in[5];
    const float* Wq0    = (const float*)d_in[6];
    const float* Wq1    = (const float*)d_in[7];
    const float* Wd0    = (const float*)d_in[8];
    const float* Wd1    = (const float*)d_in[9];
    const float* W_out0 = (const float*)d_in[10];
    const float* W_out1 = (const float*)d_in[11];
    const float* fcW1 = (const float*)d_in[12];
    const float* fcb1 = (const float*)d_in[13];
    const float* fcW2 = (const float*)d_in[14];
    const float* fcb2 = (const float*)d_in[15];
    const float* fcW3 = (const float*)d_in[16];
    const float* fcb3 = (const float*)d_in[17];
    const float* fkW1 = (const float*)d_in[18];
    const float* fkb1 = (const float*)d_in[19];
    const float* fkW2 = (const float*)d_in[20];
    const float* fkb2 = (const float*)d_in[21];
    const float* fkW3 = (const float*)d_in[22];
    const float* fkb3 = (const float*)d_in[23];
    float* out = (float*)d_out;

    int N = in_sizes[0] / 56;
    int E = in_sizes[2] / 4;

    const int FRONT_SMEM = F_FLOATS * (int)sizeof(float);   // 50176 B
    const int L3_SMEM    = L3_FLOATS * (int)sizeof(float);  // 209280 B

    cudaFuncSetAttribute(front_kernel,
                         cudaFuncAttributeMaxDynamicSharedMemorySize, FRONT_SMEM);
    cudaFuncSetAttribute(l3k_kernel,
                         cudaFuncAttributeMaxDynamicSharedMemorySize, L3_SMEM);
    cudaFuncSetAttribute(l3v_kernel<0>,
                         cudaFuncAttributeMaxDynamicSharedMemorySize, L3_SMEM);
    cudaFuncSetAttribute(l3v_kernel<1>,
                         cudaFuncAttributeMaxDynamicSharedMemorySize, L3_SMEM);

    int tiles = (E + TE - 1) / TE;

    node_prep_kernel<<<(N + 127) / 128, 128>>>(node_attr, W_in0, W_in1, Wq0, Wq1,
                                               Wd0, Wd1, N);
    init_kernel<<<(N * 28 + 255) / 256, 256>>>(N);
    front_kernel<<<NSM * 2, 128, FRONT_SMEM>>>(edge_attr,
                                               fcW1, fcb1, fcW2, fcb2,
                                               fkW1, fkb1, fkW2, fkb2, E);
    l3k_kernel<<<tiles, 256, L3_SMEM>>>(edge_sh, edge_index, fkW3, fkb3, E);
    l3v_kernel<0><<<tiles, 256, L3_SMEM>>>(edge_sh, edge_index, fcW3, fcb3, E);
    l3v_kernel<1><<<tiles, 256, L3_SMEM>>>(edge_sh, edge_index, fcW3, fcb3, E);
    softmax_agg_kernel<<<(E + 255) / 256, 256>>>(edge_index, E);
    node_out_kernel<<<(N + 127) / 128, 128>>>(node_attr, W_out0, W_out1, out, N);
}

// round 11
// speedup vs baseline: 1.3115x; 1.3115x over previous
#include <cuda_runtime.h>
#include <cstdint>
#include <cstddef>

#define MAXN 10000
#define MAXE 160000
#define NSM  148

typedef unsigned long long ull;

__device__ float g_x0[MAXN * 16];
__device__ float g_x1[MAXN * 12];
__device__ float g_qd0[MAXN * 8];
__device__ float g_qd1[MAXN * 6];
__device__ float g_logit[MAXE];
__device__ float g_v[MAXE * 28];       // SoA: [j*E + e]
__device__ float g_m[MAXN];
__device__ float g_z[MAXN];
__device__ float g_agg[MAXN * 28];     // AoS
__device__ float g_h2k[(size_t)MAXE * 64];   // TRANSPOSED: [c*E + e]
__device__ float g_h2v[(size_t)MAXE * 64];   // TRANSPOSED: [c*E + e]

__device__ __forceinline__ float frelu(float x) { return x > 0.f ? x : 0.f; }

// ---- packed f32x2 helpers (Blackwell FFMA2) -------------------------------
__device__ __forceinline__ ull pack2(float lo, float hi) {
    ull r; asm("mov.b64 %0, {%1, %2};" : "=l"(r) : "f"(lo), "f"(hi)); return r;
}
__device__ __forceinline__ void unpack2(ull v, float& lo, float& hi) {
    asm("mov.b64 {%0, %1}, %2;" : "=f"(lo), "=f"(hi) : "l"(v));
}
__device__ __forceinline__ void ffma2(ull& d, ull a, ull b) {
    asm("fma.rn.f32x2 %0, %1, %2, %0;" : "+l"(d) : "l"(a), "l"(b));
}

// dual-edge dot (front kernel only)
template <int NU2>
__device__ __forceinline__ void dotp2(const float* __restrict__ w,
                                      const ull* __restrict__ hA,
                                      const ull* __restrict__ hB,
                                      float& rA, float& rB) {
    ull a0 = 0ull, a1 = 0ull, b0 = 0ull, b1 = 0ull;
    const ulonglong2* wp = reinterpret_cast<const ulonglong2*>(w);
#pragma unroll
    for (int t = 0; t < NU2; t++) {
        ulonglong2 ww = wp[t];
        ffma2(a0, ww.x, hA[2 * t]);
        ffma2(a1, ww.y, hA[2 * t + 1]);
        ffma2(b0, ww.x, hB[2 * t]);
        ffma2(b1, ww.y, hB[2 * t + 1]);
    }
    float x0, x1, x2, x3;
    unpack2(a0, x0, x1); unpack2(a1, x2, x3);
    rA = (x0 + x1) + (x2 + x3);
    unpack2(b0, x0, x1); unpack2(b1, x2, x3);
    rB = (x0 + x1) + (x2 + x3);
}

__device__ __forceinline__ void atomicMaxF(float* addr, float v) {
    if (v >= 0.f) atomicMax((int*)addr, __float_as_int(v));
    else          atomicMin((unsigned int*)addr, __float_as_uint(v));
}

// ---------------------------------------------------------------------------
// Kernel A: node prep
// ---------------------------------------------------------------------------
__global__ void node_prep_kernel(const float* __restrict__ na,
                                 const float* __restrict__ Win0,
                                 const float* __restrict__ Win1,
                                 const float* __restrict__ Wq0,
                                 const float* __restrict__ Wq1,
                                 const float* __restrict__ Wd0,
                                 const float* __restrict__ Wd1,
                                 int N) {
    __shared__ float sWin0[512], sWin1[32], sWq0[128], sWq1[8], sWd0[64], sWd1[4];
    int tid = threadIdx.x;
    for (int i = tid; i < 512; i += blockDim.x) sWin0[i] = Win0[i];
    for (int i = tid; i < 32;  i += blockDim.x) sWin1[i] = Win1[i];
    for (int i = tid; i < 128; i += blockDim.x) sWq0[i]  = Wq0[i];
    for (int i = tid; i < 8;   i += blockDim.x) sWq1[i]  = Wq1[i];
    for (int i = tid; i < 64;  i += blockDim.x) sWd0[i]  = Wd0[i];
    for (int i = tid; i < 4;   i += blockDim.x) sWd1[i]  = Wd1[i];
    __syncthreads();

    int n = blockIdx.x * blockDim.x + tid;
    if (n >= N) return;

    const float* p = na + (size_t)n * 56;
    float a0[32], a1[24];
#pragma unroll
    for (int i = 0; i < 32; i++) a0[i] = p[i];
#pragma unroll
    for (int i = 0; i < 24; i++) a1[i] = p[32 + i];

    float x0[16];
#pragma unroll
    for (int o = 0; o < 16; o++) {
        float s = 0.f;
#pragma unroll
        for (int i = 0; i < 32; i++) s = fmaf(a0[i], sWin0[i * 16 + o], s);
        x0[o] = s * 0.17677669529663687f;   // 1/sqrt(32)
    }
    float x1[12];
#pragma unroll
    for (int o = 0; o < 4; o++)
#pragma unroll
        for (int c = 0; c < 3; c++) {
            float s = 0.f;
#pragma unroll
            for (int m = 0; m < 8; m++) s = fmaf(a1[m * 3 + c], sWin1[m * 4 + o], s);
            x1[o * 3 + c] = s * 0.35355339059327373f;  // 1/sqrt(8)
        }

    float q0[8];
#pragma unroll
    for (int b = 0; b < 8; b++) {
        float s = 0.f;
#pragma unroll
        for (int o = 0; o < 16; o++) s = fmaf(x0[o], sWq0[o * 8 + b], s);
        q0[b] = s * 0.25f;                   // 1/sqrt(16)
    }
    float q1[6];
#pragma unroll
    for (int j = 0; j < 2; j++)
#pragma unroll
        for (int c = 0; c < 3; c++) {
            float s = 0.f;
#pragma unroll
            for (int o = 0; o < 4; o++) s = fmaf(x1[o * 3 + c], sWq1[o * 2 + j], s);
            q1[j * 3 + c] = s * 0.5f;        // 1/sqrt(4)
        }

#pragma unroll
    for (int j = 0; j < 8; j++) {
        float s = 0.f;
#pragma unroll
        for (int i = 0; i < 8; i++) s = fmaf(q0[i], sWd0[i * 8 + j], s);
        g_qd0[(size_t)n * 8 + j] = s;
    }
#pragma unroll
    for (int j = 0; j < 2; j++)
#pragma unroll
        for (int c = 0; c < 3; c++) {
            float s = 0.f;
#pragma unroll
            for (int i = 0; i < 2; i++) s = fmaf(q1[i * 3 + c], sWd1[i * 2 + j], s);
            g_qd1[(size_t)n * 6 + j * 3 + c] = s;
        }

#pragma unroll
    for (int o = 0; o < 16; o++) g_x0[(size_t)n * 16 + o] = x0[o];
#pragma unroll
    for (int o = 0; o < 12; o++) g_x1[(size_t)n * 12 + o] = x1[o];
}

// ---------------------------------------------------------------------------
__global__ void init_kernel(int N) {
    int i = blockIdx.x * blockDim.x + threadIdx.x;
    if (i < N * 28) g_agg[i] = 0.f;
    if (i < N) {
        g_m[i] = __int_as_float(0xff800000);  // -inf
        g_z[i] = 0.f;
    }
}

// ---------------------------------------------------------------------------
// FRONT kernel (EPT=2): both MLP fronts, writes h2 TRANSPOSED (c-major)
// ---------------------------------------------------------------------------
#define F_OW1K 0
#define F_OB1K 2048
#define F_OW2K 2112
#define F_OB2K 6208
#define F_OW1V 6272
#define F_OB1V 8320
#define F_OW2V 8384
#define F_OB2V 12480
#define F_FLOATS 12544

__device__ __forceinline__ void front_one2(const float* __restrict__ sm,
                                           int oW1, int oB1, int oW2, int oB2,
                                           const float* __restrict__ edge_attr,
                                           float* __restrict__ gh2,
                                           size_t e0, size_t e1, bool hb, int E) {
    ull eapA[16], eapB[16];
    {
        const ulonglong2* a2 = reinterpret_cast<const ulonglong2*>(edge_attr + e0 * 32);
        const ulonglong2* b2 = reinterpret_cast<const ulonglong2*>(edge_attr + e1 * 32);
#pragma unroll
        for (int t = 0; t < 8; t++) {
            ulonglong2 va = a2[t]; ulonglong2 vb = b2[t];
            eapA[2 * t] = va.x; eapA[2 * t + 1] = va.y;
            eapB[2 * t] = vb.x; eapB[2 * t + 1] = vb.y;
        }
    }
    ull h1A[32], h1B[32];
#pragma unroll 4
    for (int o = 0; o < 64; o += 2) {
        float loA, loB, hiA, hiB;
        dotp2<8>(sm + oW1 + o * 32,       eapA, eapB, loA, loB);
        dotp2<8>(sm + oW1 + (o + 1) * 32, eapA, eapB, hiA, hiB);
        float b_lo = sm[oB1 + o], b_hi = sm[oB1 + o + 1];
        h1A[o >> 1] = pack2(frelu(b_lo + loA), frelu(b_hi + hiA));
        h1B[o >> 1] = pack2(frelu(b_lo + loB), frelu(b_hi + hiB));
    }
#pragma unroll 2
    for (int o = 0; o < 64; o += 4) {
        float vA[4], vB[4];
#pragma unroll
        for (int k = 0; k < 4; k++) {
            float a, b;
            dotp2<16>(sm + oW2 + (o + k) * 64, h1A, h1B, a, b);
            float bias = sm[oB2 + o + k];
            vA[k] = frelu(bias + a);
            vB[k] = frelu(bias + b);
        }
#pragma unroll
        for (int k = 0; k < 4; k++) {
            gh2[(size_t)(o + k) * E + e0] = vA[k];
            if (hb) gh2[(size_t)(o + k) * E + e1] = vB[k];
        }
    }
}

__global__ void __launch_bounds__(128, 2)
front_kernel(const float* __restrict__ edge_attr,
             const float* __restrict__ fcW1, const float* __restrict__ fcb1,
             const float* __restrict__ fcW2, const float* __restrict__ fcb2,
             const float* __restrict__ fkW1, const float* __restrict__ fkb1,
             const float* __restrict__ fkW2, const float* __restrict__ fkb2,
             int E) {
    extern __shared__ float sm[];
    int tid = threadIdx.x, bs = blockDim.x;
    for (int i = tid; i < 2048; i += bs) { int o = i >> 5, c = i & 31; sm[F_OW1K + i] = fkW1[c * 64 + o]; }
    for (int i = tid; i < 64;   i += bs) sm[F_OB1K + i] = fkb1[i];
    for (int i = tid; i < 4096; i += bs) { int o = i >> 6, c = i & 63; sm[F_OW2K + i] = fkW2[c * 64 + o]; }
    for (int i = tid; i < 64;   i += bs) sm[F_OB2K + i] = fkb2[i];
    for (int i = tid; i < 2048; i += bs) { int o = i >> 5, c = i & 31; sm[F_OW1V + i] = fcW1[c * 64 + o]; }
    for (int i = tid; i < 64;   i += bs) sm[F_OB1V + i] = fcb1[i];
    for (int i = tid; i < 4096; i += bs) { int o = i >> 6, c = i & 63; sm[F_OW2V + i] = fcW2[c * 64 + o]; }
    for (int i = tid; i < 64;   i += bs) sm[F_OB2V + i] = fcb2[i];
    __syncthreads();

    int stride = gridDim.x * bs;
    for (int e0 = blockIdx.x * bs + tid; e0 < E; e0 += 2 * stride) {
        int e1 = e0 + stride;
        bool hb = e1 < E;
        size_t e1c = hb ? (size_t)e1 : (size_t)e0;
        front_one2(sm, F_OW1K, F_OB1K, F_OW2K, F_OB2K, edge_attr, g_h2k,
                   (size_t)e0, e1c, hb, E);
        front_one2(sm, F_OW1V, F_OB1V, F_OW2V, F_OB2V, edge_attr, g_h2v,
                   (size_t)e0, e1c, hb, E);
    }
}

// ---------------------------------------------------------------------------
// L3 GEMM machinery (persistent, double-buffered k-loop)
//   Tile: 128 edges. Thread (re=warp, cw=lane): 16 edges x 7 outputs.
// smem floats: B 64*224 | A 64*128 | C 224*132 | bias 224
// ---------------------------------------------------------------------------
#define TE     128
#define NWP    224
#define CPAD   132
#define L3_B_OFF    0
#define L3_A_OFF    14336
#define L3_C_OFF    22528
#define L3_BIAS_OFF 52096
#define L3_FLOATS   52320

__device__ __forceinline__ void l3_load_A(float* __restrict__ As,
                                          const float* __restrict__ gh2T,
                                          int e0, int E, int tid) {
    for (int i = tid; i < 64 * (TE / 4); i += 256) {
        int c = i / (TE / 4);
        int v = i % (TE / 4);
        int eb = e0 + 4 * v;
        float4 f;
        if (eb + 3 < E) {
            f = *reinterpret_cast<const float4*>(gh2T + (size_t)c * E + eb);
        } else {
            f.x = (eb + 0 < E) ? gh2T[(size_t)c * E + eb + 0] : 0.f;
            f.y = (eb + 1 < E) ? gh2T[(size_t)c * E + eb + 1] : 0.f;
            f.z = (eb + 2 < E) ? gh2T[(size_t)c * E + eb + 2] : 0.f;
            f.w = (eb + 3 < E) ? gh2T[(size_t)c * E + eb + 3] : 0.f;
        }
        *reinterpret_cast<float4*>(As + c * TE + 4 * v) = f;
    }
}

__device__ __forceinline__ void l3_loadk(const float* __restrict__ As,
                                         const float* __restrict__ Bs,
                                         int k, int re, int cw,
                                         ull* __restrict__ av,
                                         ull* __restrict__ bv) {
    const ulonglong2* ap = reinterpret_cast<const ulonglong2*>(As + k * TE + 16 * re);
    ulonglong2 t0 = ap[0], t1 = ap[1], t2 = ap[2], t3 = ap[3];
    av[0] = t0.x; av[1] = t0.y; av[2] = t1.x; av[3] = t1.y;
    av[4] = t2.x; av[5] = t2.y; av[6] = t3.x; av[7] = t3.y;
    const float* bp = Bs + k * NWP + 7 * cw;
#pragma unroll
    for (int n = 0; n < 7; n++) bv[n] = pack2(bp[n], bp[n]);
}

__device__ __forceinline__ void l3_gemm(const float* __restrict__ As,
                                        const float* __restrict__ Bs,
                                        float* __restrict__ Cs, int tid) {
    int re = tid >> 5;
    int cw = tid & 31;
    ull acc[7][8];
#pragma unroll
    for (int n = 0; n < 7; n++)
#pragma unroll
        for (int p = 0; p < 8; p++) acc[n][p] = 0ull;

    ull avA[8], bvA[7], avB[8], bvB[7];
    l3_loadk(As, Bs, 0, re, cw, avA, bvA);
#pragma unroll 1
    for (int k = 0; k < 64; k += 2) {
        l3_loadk(As, Bs, k + 1, re, cw, avB, bvB);
#pragma unroll
        for (int n = 0; n < 7; n++)
#pragma unroll
            for (int p = 0; p < 8; p++) ffma2(acc[n][p], avA[p], bvA[n]);
        l3_loadk(As, Bs, (k + 2 < 64) ? (k + 2) : 0, re, cw, avA, bvA);
#pragma unroll
        for (int n = 0; n < 7; n++)
#pragma unroll
            for (int p = 0; p < 8; p++) ffma2(acc[n][p], avB[p], bvB[n]);
    }

#pragma unroll
    for (int n = 0; n < 7; n++) {
        ulonglong2* cp =
            reinterpret_cast<ulonglong2*>(Cs + (7 * cw + n) * CPAD + 16 * re);
        ulonglong2 u;
        u.x = acc[n][0]; u.y = acc[n][1]; cp[0] = u;
        u.x = acc[n][2]; u.y = acc[n][3]; cp[1] = u;
        u.x = acc[n][4]; u.y = acc[n][5]; cp[2] = u;
        u.x = acc[n][6]; u.y = acc[n][7]; cp[3] = u;
    }
}

// ---------------------------------------------------------------------------
// L3K: persistent GEMM + K contraction + logit + atomicMax
// Epilogue: 2 threads per edge (h splits b-range and j), shfl combine.
// ---------------------------------------------------------------------------
__global__ void __launch_bounds__(256, 1)
l3k_kernel(const float* __restrict__ edge_sh,
           const int*   __restrict__ eidx,
           const float* __restrict__ fkW3, const float* __restrict__ fkb3,
           int E, int tiles) {
    extern __shared__ float smx[];
    float* Bs  = smx + L3_B_OFF;
    float* As  = smx + L3_A_OFF;
    float* Cs  = smx + L3_C_OFF;
    float* sB3 = smx + L3_BIAS_OFF;
    int tid = threadIdx.x;

    for (int i = tid; i < 64 * NWP; i += 256) {
        int c = i / NWP, w = i % NWP;
        Bs[i] = (w < 200) ? fkW3[c * 200 + w] : 0.f;
    }
    for (int i = tid; i < NWP; i += 256)
        sB3[i] = (i < 200) ? fkb3[i] : 0.f;

    const float NORM = 0.22360679774997896f;  // 1/sqrt(20)
    const float I3   = 0.5773502691896258f;   // 1/sqrt(3)

    for (int tile = blockIdx.x; tile < tiles; tile += gridDim.x) {
        int e0 = tile * TE;
        l3_load_A(As, g_h2k, e0, E, tid);
        __syncthreads();
        l3_gemm(As, Bs, Cs, tid);
        __syncthreads();

        // epilogue: 2 threads per edge
        {
            int el = tid >> 1;
            int h  = tid & 1;
            int e  = e0 + el;
            int ee = (e < E) ? e : (E - 1);
            int s = eidx[ee], d = eidx[E + ee];
            float4 sh = reinterpret_cast<const float4*>(edge_sh)[ee];

            float xl0[16], xl1[12], ul1[4];
#pragma unroll
            for (int o = 0; o < 16; o++) xl0[o] = g_x0[(size_t)s * 16 + o];
#pragma unroll
            for (int o = 0; o < 12; o++) xl1[o] = g_x1[(size_t)s * 12 + o];
#pragma unroll
            for (int j = 0; j < 4; j++)
                ul1[j] = xl1[j * 3] * sh.y + xl1[j * 3 + 1] * sh.z + xl1[j * 3 + 2] * sh.w;

            float logit = 0.f;
#pragma unroll
            for (int bb = 0; bb < 4; bb++) {
                int b = 4 * h + bb;
                float acc0 = 0.f;
#pragma unroll
                for (int a = 0; a < 16; a++) {
                    int r = a * 8 + b;
                    acc0 = fmaf(xl0[a], Cs[r * CPAD + el] + sB3[r], acc0);
                }
                float acc1 = 0.f;
#pragma unroll
                for (int a = 0; a < 4; a++) {
                    int r = 168 + a * 8 + b;
                    acc1 = fmaf(ul1[a], Cs[r * CPAD + el] + sB3[r], acc1);
                }
                float k0b = NORM * fmaf(sh.x, acc0, I3 * acc1);
                logit = fmaf(g_qd0[(size_t)d * 8 + b], k0b, logit);
            }
            {
                int j = h;
                float c01 = 0.f;
#pragma unroll
                for (int a = 0; a < 16; a++) {
                    int r = 128 + a * 2 + j;
                    c01 = fmaf(xl0[a], Cs[r * CPAD + el] + sB3[r], c01);
                }
                float dx = 0.f, dy = 0.f, dz = 0.f;
#pragma unroll
                for (int a = 0; a < 4; a++) {
                    int r = 160 + a * 2 + j;
                    float w = Cs[r * CPAD + el] + sB3[r];
                    dx = fmaf(xl1[a * 3 + 0], w, dx);
                    dy = fmaf(xl1[a * 3 + 1], w, dy);
                    dz = fmaf(xl1[a * 3 + 2], w, dz);
                }
                float k1x = NORM * (sh.y * c01 + sh.x * dx);
                float k1y = NORM * (sh.z * c01 + sh.x * dy);
                float k1z = NORM * (sh.w * c01 + sh.x * dz);
                logit += I3 * (g_qd1[(size_t)d * 6 + j * 3 + 0] * k1x +
                               g_qd1[(size_t)d * 6 + j * 3 + 1] * k1y +
                               g_qd1[(size_t)d * 6 + j * 3 + 2] * k1z);
            }
            logit += __shfl_xor_sync(0xffffffffu, logit, 1);
            logit *= 0.31622776601683794f;  // 1/sqrt(10)
            if (h == 0 && e < E) {
                g_logit[e] = logit;
                atomicMaxF(&g_m[d], logit);
            }
        }
        __syncthreads();
    }
}

// ---------------------------------------------------------------------------
// L3V (HALF = 0/1): persistent GEMM + V contraction for half the outputs
// ---------------------------------------------------------------------------
template <int HALF>
__device__ __forceinline__ int v_wi(int r) {
    if (r < 128) { int a = r >> 3, b = r & 7;        return a * 16 + HALF * 8 + b; }
    if (r < 160) { int t = r - 128; int a = t >> 1;  return 256 + a * 4 + HALF * 2 + (t & 1); }
    if (r < 168) { int t = r - 160; int a = t >> 1;  return 320 + a * 4 + HALF * 2 + (t & 1); }
    { int t = r - 168; int a = t >> 3, b = t & 7;    return 336 + a * 16 + HALF * 8 + b; }
}

template <int HALF>
__global__ void __launch_bounds__(256, 1)
l3v_kernel(const float* __restrict__ edge_sh,
           const int*   __restrict__ eidx,
           const float* __restrict__ fcW3, const float* __restrict__ fcb3,
           int E, int tiles) {
    extern __shared__ float smx[];
    float* Bs  = smx + L3_B_OFF;
    float* As  = smx + L3_A_OFF;
    float* Cs  = smx + L3_C_OFF;
    float* sB3 = smx + L3_BIAS_OFF;
    int tid = threadIdx.x;

    for (int i = tid; i < 64 * NWP; i += 256) {
        int c = i / NWP, w = i % NWP;
        Bs[i] = (w < 200) ? fcW3[c * 400 + v_wi<HALF>(w)] : 0.f;
    }
    for (int i = tid; i < NWP; i += 256)
        sB3[i] = (i < 200) ? fcb3[v_wi<HALF>(i)] : 0.f;

    const float NORM = 0.22360679774997896f;  // 1/sqrt(20)
    const float I3   = 0.5773502691896258f;   // 1/sqrt(3)

    for (int tile = blockIdx.x; tile < tiles; tile += gridDim.x) {
        int e0 = tile * TE;
        l3_load_A(As, g_h2v, e0, E, tid);
        __syncthreads();
        l3_gemm(As, Bs, Cs, tid);
        __syncthreads();

        {
            int el = tid >> 1;
            int h  = tid & 1;
            int e  = e0 + el;
            bool ok = e < E;
            int ee = ok ? e : (E - 1);
            int s = eidx[ee];
            float4 sh = reinterpret_cast<const float4*>(edge_sh)[ee];

            float xl0[16], xl1[12], ul1[4];
#pragma unroll
            for (int o = 0; o < 16; o++) xl0[o] = g_x0[(size_t)s * 16 + o];
#pragma unroll
            for (int o = 0; o < 12; o++) xl1[o] = g_x1[(size_t)s * 12 + o];
#pragma unroll
            for (int j = 0; j < 4; j++)
                ul1[j] = xl1[j * 3] * sh.y + xl1[j * 3 + 1] * sh.z + xl1[j * 3 + 2] * sh.w;

#pragma unroll
            for (int bb = 0; bb < 4; bb++) {
                int b = 4 * h + bb;
                float acc0 = 0.f;
#pragma unroll
                for (int a = 0; a < 16; a++) {
                    int r = a * 8 + b;
                    acc0 = fmaf(xl0[a], Cs[r * CPAD + el] + sB3[r], acc0);
                }
                float acc1 = 0.f;
#pragma unroll
                for (int a = 0; a < 4; a++) {
                    int r = 168 + a * 8 + b;
                    acc1 = fmaf(ul1[a], Cs[r * CPAD + el] + sB3[r], acc1);
                }
                int bg = HALF * 8 + b;
                if (ok) g_v[(size_t)bg * E + e] = NORM * fmaf(sh.x, acc0, I3 * acc1);
            }
            {
                int j = h;
                float c01 = 0.f;
#pragma unroll
                for (int a = 0; a < 16; a++) {
                    int r = 128 + a * 2 + j;
                    c01 = fmaf(xl0[a], Cs[r * CPAD + el] + sB3[r], c01);
                }
                float dx = 0.f, dy = 0.f, dz = 0.f;
#pragma unroll
                for (int a = 0; a < 4; a++) {
                    int r = 160 + a * 2 + j;
                    float w = Cs[r * CPAD + el] + sB3[r];
                    dx = fmaf(xl1[a * 3 + 0], w, dx);
                    dy = fmaf(xl1[a * 3 + 1], w, dy);
                    dz = fmaf(xl1[a * 3 + 2], w, dz);
                }
                int jg = HALF * 2 + j;
                if (ok) {
                    g_v[(size_t)(16 + jg * 3 + 0) * E + e] = NORM * (sh.y * c01 + sh.x * dx);
                    g_v[(size_t)(16 + jg * 3 + 1) * E + e] = NORM * (sh.z * c01 + sh.x * dy);
                    g_v[(size_t)(16 + jg * 3 + 2) * E + e] = NORM * (sh.w * c01 + sh.x * dz);
                }
            }
        }
        __syncthreads();
    }
}

// ---------------------------------------------------------------------------
__global__ void softmax_agg_kernel(const int* __restrict__ eidx, int E) {
    int e = blockIdx.x * blockDim.x + threadIdx.x;
    if (e >= E) return;
    int d = eidx[E + e];
    float p = __expf(g_logit[e] - g_m[d]);
    atomicAdd(&g_z[d], p);
#pragma unroll
    for (int j = 0; j < 28; j++)
        atomicAdd(&g_agg[(size_t)d * 28 + j], p * g_v[(size_t)j * E + e]);
}

// ---------------------------------------------------------------------------
__global__ void node_out_kernel(const float* __restrict__ na,
                                const float* __restrict__ Wo0,
                                const float* __restrict__ Wo1,
                                float* __restrict__ out, int N) {
    __shared__ float sW0[512], sW1[32];
    int tid = threadIdx.x;
    for (int i = tid; i < 512; i += blockDim.x) sW0[i] = Wo0[i];
    for (int i = tid; i < 32;  i += blockDim.x) sW1[i] = Wo1[i];
    __syncthreads();

    int n = blockIdx.x * blockDim.x + tid;
    if (n >= N) return;
    float z = g_z[n];
    float zi = z > 0.f ? 1.f / z : 0.f;
    float ag[28];
#pragma unroll
    for (int j = 0; j < 28; j++) ag[j] = g_agg[(size_t)n * 28 + j] * zi;

#pragma unroll
    for (int o = 0; o < 32; o++) {
        float s = 0.f;
#pragma unroll
        for (int a = 0; a < 16; a++) s = fmaf(ag[a], sW0[a * 32 + o], s);
        out[(size_t)n * 56 + o] = fmaf(s, 0.25f, na[(size_t)n * 56 + o]);
    }
#pragma unroll
    for (int o = 0; o < 8; o++)
#pragma unroll
        for (int c = 0; c < 3; c++) {
            float s = 0.f;
#pragma unroll
            for (int a = 0; a < 4; a++) s = fmaf(ag[16 + a * 3 + c], sW1[a * 8 + o], s);
            out[(size_t)n * 56 + 32 + o * 3 + c] =
                fmaf(s, 0.5f, na[(size_t)n * 56 + 32 + o * 3 + c]);
        }
}

// ---------------------------------------------------------------------------
extern "C" void kernel_launch(void* const* d_in, const int* in_sizes, int n_in,
                              void* d_out, int out_size) {
    const float* node_attr  = (const float*)d_in[0];
    const float* edge_attr  = (const float*)d_in[1];
    const float* edge_sh    = (const float*)d_in[2];
    const int*   edge_index = (const int*)  d_in[3];
    const float* W_in0  = (const float*)d_in[4];
    const float* W_in1  = (const float*)d_in[5];
    const float* Wq0    = (const float*)d_in[6];
    const float* Wq1    = (const float*)d_in[7];
    const float* Wd0    = (const float*)d_in[8];
    const float* Wd1    = (const float*)d_in[9];
    const float* W_out0 = (const float*)d_in[10];
    const float* W_out1 = (const float*)d_in[11];
    const float* fcW1 = (const float*)d_in[12];
    const float* fcb1 = (const float*)d_in[13];
    const float* fcW2 = (const float*)d_in[14];
    const float* fcb2 = (const float*)d_in[15];
    const float* fcW3 = (const float*)d_in[16];
    const float* fcb3 = (const float*)d_in[17];
    const float* fkW1 = (const float*)d_in[18];
    const float* fkb1 = (const float*)d_in[19];
    const float* fkW2 = (const float*)d_in[20];
    const float* fkb2 = (const float*)d_in[21];
    const float* fkW3 = (const float*)d_in[22];
    const float* fkb3 = (const float*)d_in[23];
    float* out = (float*)d_out;

    int N = in_sizes[0] / 56;
    int E = in_sizes[2] / 4;

    const int FRONT_SMEM = F_FLOATS * (int)sizeof(float);   // 50176 B
    const int L3_SMEM    = L3_FLOATS * (int)sizeof(float);  // 209280 B

    cudaFuncSetAttribute(front_kernel,
                         cudaFuncAttributeMaxDynamicSharedMemorySize, FRONT_SMEM);
    cudaFuncSetAttribute(l3k_kernel,
                         cudaFuncAttributeMaxDynamicSharedMemorySize, L3_SMEM);
    cudaFuncSetAttribute(l3v_kernel<0>,
                         cudaFuncAttributeMaxDynamicSharedMemorySize, L3_SMEM);
    cudaFuncSetAttribute(l3v_kernel<1>,
                         cudaFuncAttributeMaxDynamicSharedMemorySize, L3_SMEM);

    int tiles = (E + TE - 1) / TE;

    node_prep_kernel<<<(N + 127) / 128, 128>>>(node_attr, W_in0, W_in1, Wq0, Wq1,
                                               Wd0, Wd1, N);
    init_kernel<<<(N * 28 + 255) / 256, 256>>>(N);
    front_kernel<<<NSM * 2, 128, FRONT_SMEM>>>(edge_attr,
                                               fcW1, fcb1, fcW2, fcb2,
                                               fkW1, fkb1, fkW2, fkb2, E);
    l3k_kernel<<<NSM, 256, L3_SMEM>>>(edge_sh, edge_index, fkW3, fkb3, E, tiles);
    l3v_kernel<0><<<NSM, 256, L3_SMEM>>>(edge_sh, edge_index, fcW3, fcb3, E, tiles);
    l3v_kernel<1><<<NSM, 256, L3_SMEM>>>(edge_sh, edge_index, fcW3, fcb3, E, tiles);
    softmax_agg_kernel<<<(E + 255) / 256, 256>>>(edge_index, E);
    node_out_kernel<<<(N + 127) / 128, 128>>>(node_attr, W_out0, W_out1, out, N);
}

// round 12
// speedup vs baseline: 1.5515x; 1.1830x over previous
#include <cuda_runtime.h>
#include <cstdint>
#include <cstddef>

#define MAXN 10000
#define MAXE 160000
#define NSM  148

typedef unsigned long long ull;

__device__ float g_x0[MAXN * 16];
__device__ float g_x1[MAXN * 12];
__device__ float g_qd0[MAXN * 8];
__device__ float g_qd1[MAXN * 6];
__device__ float g_logit[MAXE];
__device__ float g_v[MAXE * 28];       // SoA: [j*E + e]
__device__ float g_m[MAXN];
__device__ float g_z[MAXN];
__device__ float g_agg[MAXN * 28];     // AoS
__device__ float g_h2k[(size_t)MAXE * 64];   // AoS rows [e*64 + c]
__device__ float g_h2v[(size_t)MAXE * 64];   // AoS rows [e*64 + c]

__device__ __forceinline__ float frelu(float x) { return x > 0.f ? x : 0.f; }

// ---- packed f32x2 helpers (Blackwell FFMA2) -------------------------------
__device__ __forceinline__ ull pack2(float lo, float hi) {
    ull r; asm("mov.b64 %0, {%1, %2};" : "=l"(r) : "f"(lo), "f"(hi)); return r;
}
__device__ __forceinline__ void unpack2(ull v, float& lo, float& hi) {
    asm("mov.b64 {%0, %1}, %2;" : "=f"(lo), "=f"(hi) : "l"(v));
}
__device__ __forceinline__ void ffma2(ull& d, ull a, ull b) {
    asm("fma.rn.f32x2 %0, %1, %2, %0;" : "+l"(d) : "l"(a), "l"(b));
}

// dual-edge dot of (4*NU2) floats: ONE weight fetch feeds BOTH edges
template <int NU2>
__device__ __forceinline__ void dotp2(const float* __restrict__ w,
                                      const ull* __restrict__ hA,
                                      const ull* __restrict__ hB,
                                      float& rA, float& rB) {
    ull a0 = 0ull, a1 = 0ull, b0 = 0ull, b1 = 0ull;
    const ulonglong2* wp = reinterpret_cast<const ulonglong2*>(w);
#pragma unroll
    for (int t = 0; t < NU2; t++) {
        ulonglong2 ww = wp[t];
        ffma2(a0, ww.x, hA[2 * t]);
        ffma2(a1, ww.y, hA[2 * t + 1]);
        ffma2(b0, ww.x, hB[2 * t]);
        ffma2(b1, ww.y, hB[2 * t + 1]);
    }
    float x0, x1, x2, x3;
    unpack2(a0, x0, x1); unpack2(a1, x2, x3);
    rA = (x0 + x1) + (x2 + x3);
    unpack2(b0, x0, x1); unpack2(b1, x2, x3);
    rB = (x0 + x1) + (x2 + x3);
}

__device__ __forceinline__ void atomicMaxF(float* addr, float v) {
    if (v >= 0.f) atomicMax((int*)addr, __float_as_int(v));
    else          atomicMin((unsigned int*)addr, __float_as_uint(v));
}

// ---------------------------------------------------------------------------
// Kernel A: node prep (x = ir_linear(node_attr); qd = (q @ Wd) precontracted)
// ---------------------------------------------------------------------------
__global__ void node_prep_kernel(const float* __restrict__ na,
                                 const float* __restrict__ Win0,
                                 const float* __restrict__ Win1,
                                 const float* __restrict__ Wq0,
                                 const float* __restrict__ Wq1,
                                 const float* __restrict__ Wd0,
                                 const float* __restrict__ Wd1,
                                 int N) {
    __shared__ float sWin0[512], sWin1[32], sWq0[128], sWq1[8], sWd0[64], sWd1[4];
    int tid = threadIdx.x;
    for (int i = tid; i < 512; i += blockDim.x) sWin0[i] = Win0[i];
    for (int i = tid; i < 32;  i += blockDim.x) sWin1[i] = Win1[i];
    for (int i = tid; i < 128; i += blockDim.x) sWq0[i]  = Wq0[i];
    for (int i = tid; i < 8;   i += blockDim.x) sWq1[i]  = Wq1[i];
    for (int i = tid; i < 64;  i += blockDim.x) sWd0[i]  = Wd0[i];
    for (int i = tid; i < 4;   i += blockDim.x) sWd1[i]  = Wd1[i];
    __syncthreads();

    int n = blockIdx.x * blockDim.x + tid;
    if (n >= N) return;

    const float* p = na + (size_t)n * 56;
    float a0[32], a1[24];
#pragma unroll
    for (int i = 0; i < 32; i++) a0[i] = p[i];
#pragma unroll
    for (int i = 0; i < 24; i++) a1[i] = p[32 + i];

    float x0[16];
#pragma unroll
    for (int o = 0; o < 16; o++) {
        float s = 0.f;
#pragma unroll
        for (int i = 0; i < 32; i++) s = fmaf(a0[i], sWin0[i * 16 + o], s);
        x0[o] = s * 0.17677669529663687f;   // 1/sqrt(32)
    }
    float x1[12];
#pragma unroll
    for (int o = 0; o < 4; o++)
#pragma unroll
        for (int c = 0; c < 3; c++) {
            float s = 0.f;
#pragma unroll
            for (int m = 0; m < 8; m++) s = fmaf(a1[m * 3 + c], sWin1[m * 4 + o], s);
            x1[o * 3 + c] = s * 0.35355339059327373f;  // 1/sqrt(8)
        }

    float q0[8];
#pragma unroll
    for (int b = 0; b < 8; b++) {
        float s = 0.f;
#pragma unroll
        for (int o = 0; o < 16; o++) s = fmaf(x0[o], sWq0[o * 8 + b], s);
        q0[b] = s * 0.25f;                   // 1/sqrt(16)
    }
    float q1[6];
#pragma unroll
    for (int j = 0; j < 2; j++)
#pragma unroll
        for (int c = 0; c < 3; c++) {
            float s = 0.f;
#pragma unroll
            for (int o = 0; o < 4; o++) s = fmaf(x1[o * 3 + c], sWq1[o * 2 + j], s);
            q1[j * 3 + c] = s * 0.5f;        // 1/sqrt(4)
        }

#pragma unroll
    for (int j = 0; j < 8; j++) {
        float s = 0.f;
#pragma unroll
        for (int i = 0; i < 8; i++) s = fmaf(q0[i], sWd0[i * 8 + j], s);
        g_qd0[(size_t)n * 8 + j] = s;
    }
#pragma unroll
    for (int j = 0; j < 2; j++)
#pragma unroll
        for (int c = 0; c < 3; c++) {
            float s = 0.f;
#pragma unroll
            for (int i = 0; i < 2; i++) s = fmaf(q1[i * 3 + c], sWd1[i * 2 + j], s);
            g_qd1[(size_t)n * 6 + j * 3 + c] = s;
        }

#pragma unroll
    for (int o = 0; o < 16; o++) g_x0[(size_t)n * 16 + o] = x0[o];
#pragma unroll
    for (int o = 0; o < 12; o++) g_x1[(size_t)n * 12 + o] = x1[o];
}

// ---------------------------------------------------------------------------
__global__ void init_kernel(int N) {
    int i = blockIdx.x * blockDim.x + threadIdx.x;
    if (i < N * 28) g_agg[i] = 0.f;
    if (i < N) {
        g_m[i] = __int_as_float(0xff800000);  // -inf
        g_z[i] = 0.f;
    }
}

// ---------------------------------------------------------------------------
// FRONT kernel (EPT=2): both MLP fronts (32->64->64), writes h2K / h2V
// ---------------------------------------------------------------------------
#define F_OW1K 0
#define F_OB1K 2048
#define F_OW2K 2112
#define F_OB2K 6208
#define F_OW1V 6272
#define F_OB1V 8320
#define F_OW2V 8384
#define F_OB2V 12480
#define F_FLOATS 12544

__device__ __forceinline__ void front_one2(const float* __restrict__ sm,
                                           int oW1, int oB1, int oW2, int oB2,
                                           const float* __restrict__ edge_attr,
                                           float* __restrict__ gh2,
                                           size_t e0, size_t e1, bool hb) {
    ull eapA[16], eapB[16];
    {
        const ulonglong2* a2 = reinterpret_cast<const ulonglong2*>(edge_attr + e0 * 32);
        const ulonglong2* b2 = reinterpret_cast<const ulonglong2*>(edge_attr + e1 * 32);
#pragma unroll
        for (int t = 0; t < 8; t++) {
            ulonglong2 va = a2[t]; ulonglong2 vb = b2[t];
            eapA[2 * t] = va.x; eapA[2 * t + 1] = va.y;
            eapB[2 * t] = vb.x; eapB[2 * t + 1] = vb.y;
        }
    }
    ull h1A[32], h1B[32];
#pragma unroll 4
    for (int o = 0; o < 64; o += 2) {
        float loA, loB, hiA, hiB;
        dotp2<8>(sm + oW1 + o * 32,       eapA, eapB, loA, loB);
        dotp2<8>(sm + oW1 + (o + 1) * 32, eapA, eapB, hiA, hiB);
        float b_lo = sm[oB1 + o], b_hi = sm[oB1 + o + 1];
        h1A[o >> 1] = pack2(frelu(b_lo + loA), frelu(b_hi + hiA));
        h1B[o >> 1] = pack2(frelu(b_lo + loB), frelu(b_hi + hiB));
    }
#pragma unroll 2
    for (int o = 0; o < 64; o += 4) {
        float vA[4], vB[4];
#pragma unroll
        for (int k = 0; k < 4; k++) {
            float a, b;
            dotp2<16>(sm + oW2 + (o + k) * 64, h1A, h1B, a, b);
            float bias = sm[oB2 + o + k];
            vA[k] = frelu(bias + a);
            vB[k] = frelu(bias + b);
        }
        ulonglong2 sA; sA.x = pack2(vA[0], vA[1]); sA.y = pack2(vA[2], vA[3]);
        reinterpret_cast<ulonglong2*>(gh2 + e0 * 64)[o >> 2] = sA;
        if (hb) {
            ulonglong2 sB; sB.x = pack2(vB[0], vB[1]); sB.y = pack2(vB[2], vB[3]);
            reinterpret_cast<ulonglong2*>(gh2 + e1 * 64)[o >> 2] = sB;
        }
    }
}

__global__ void __launch_bounds__(128, 2)
front_kernel(const float* __restrict__ edge_attr,
             const float* __restrict__ fcW1, const float* __restrict__ fcb1,
             const float* __restrict__ fcW2, const float* __restrict__ fcb2,
             const float* __restrict__ fkW1, const float* __restrict__ fkb1,
             const float* __restrict__ fkW2, const float* __restrict__ fkb2,
             int E) {
    extern __shared__ float sm[];
    int tid = threadIdx.x, bs = blockDim.x;
    for (int i = tid; i < 2048; i += bs) { int o = i >> 5, c = i & 31; sm[F_OW1K + i] = fkW1[c * 64 + o]; }
    for (int i = tid; i < 64;   i += bs) sm[F_OB1K + i] = fkb1[i];
    for (int i = tid; i < 4096; i += bs) { int o = i >> 6, c = i & 63; sm[F_OW2K + i] = fkW2[c * 64 + o]; }
    for (int i = tid; i < 64;   i += bs) sm[F_OB2K + i] = fkb2[i];
    for (int i = tid; i < 2048; i += bs) { int o = i >> 5, c = i & 31; sm[F_OW1V + i] = fcW1[c * 64 + o]; }
    for (int i = tid; i < 64;   i += bs) sm[F_OB1V + i] = fcb1[i];
    for (int i = tid; i < 4096; i += bs) { int o = i >> 6, c = i & 63; sm[F_OW2V + i] = fcW2[c * 64 + o]; }
    for (int i = tid; i < 64;   i += bs) sm[F_OB2V + i] = fcb2[i];
    __syncthreads();

    int stride = gridDim.x * bs;
    for (int e0 = blockIdx.x * bs + tid; e0 < E; e0 += 2 * stride) {
        int e1 = e0 + stride;
        bool hb = e1 < E;
        size_t e1c = hb ? (size_t)e1 : (size_t)e0;
        front_one2(sm, F_OW1K, F_OB1K, F_OW2K, F_OB2K, edge_attr, g_h2k,
                   (size_t)e0, e1c, hb);
        front_one2(sm, F_OW1V, F_OB1V, F_OW2V, F_OB2V, edge_attr, g_h2v,
                   (size_t)e0, e1c, hb);
    }
}

// ---------------------------------------------------------------------------
// L3K kernel (EPT=2): K layer-3 + TP contraction + logit + atomicMax
// smem: W3K^T (200 x 64) + bias 200 = 13000 floats
// ---------------------------------------------------------------------------
__global__ void __launch_bounds__(128, 2)
l3k_kernel(const float* __restrict__ edge_sh,
           const int*   __restrict__ eidx,
           const float* __restrict__ fkW3, const float* __restrict__ fkb3,
           int E) {
    extern __shared__ float sm[];
    int tid = threadIdx.x, bs = blockDim.x;
    for (int i = tid; i < 12800; i += bs) { int w = i >> 6, c = i & 63; sm[i] = fkW3[c * 200 + w]; }
    for (int i = tid; i < 200;   i += bs) sm[12800 + i] = fkb3[i];
    __syncthreads();
    const float* B3 = sm + 12800;

    const float NORM = 0.22360679774997896f;  // 1/sqrt(20)
    const float I3   = 0.5773502691896258f;   // 1/sqrt(3)

    int stride = gridDim.x * bs;
    for (int e0 = blockIdx.x * bs + tid; e0 < E; e0 += 2 * stride) {
        int e1 = e0 + stride;
        bool hb = e1 < E;
        size_t e1c = hb ? (size_t)e1 : (size_t)e0;

        int sA = eidx[e0],  dA = eidx[E + e0];
        int sB = eidx[e1c], dB = eidx[E + e1c];
        float4 shA = reinterpret_cast<const float4*>(edge_sh)[e0];
        float4 shB = reinterpret_cast<const float4*>(edge_sh)[e1c];

        ull h2A[32], h2B[32];
        {
            const ulonglong2* ra = reinterpret_cast<const ulonglong2*>(g_h2k + (size_t)e0 * 64);
            const ulonglong2* rb = reinterpret_cast<const ulonglong2*>(g_h2k + e1c * 64);
#pragma unroll
            for (int t = 0; t < 16; t++) {
                ulonglong2 va = ra[t]; ulonglong2 vb = rb[t];
                h2A[2 * t] = va.x; h2A[2 * t + 1] = va.y;
                h2B[2 * t] = vb.x; h2B[2 * t + 1] = vb.y;
            }
        }

        float xl0A[16], xl0B[16], xl1A[12], xl1B[12], ul1A[4], ul1B[4];
#pragma unroll
        for (int o = 0; o < 16; o++) {
            xl0A[o] = g_x0[(size_t)sA * 16 + o];
            xl0B[o] = g_x0[(size_t)sB * 16 + o];
        }
#pragma unroll
        for (int o = 0; o < 12; o++) {
            xl1A[o] = g_x1[(size_t)sA * 12 + o];
            xl1B[o] = g_x1[(size_t)sB * 12 + o];
        }
#pragma unroll
        for (int j = 0; j < 4; j++) {
            ul1A[j] = xl1A[j * 3] * shA.y + xl1A[j * 3 + 1] * shA.z + xl1A[j * 3 + 2] * shA.w;
            ul1B[j] = xl1B[j * 3] * shB.y + xl1B[j * 3 + 1] * shB.z + xl1B[j * 3 + 2] * shB.w;
        }

        float logitA = 0.f, logitB = 0.f;
#pragma unroll 1
        for (int b = 0; b < 8; b++) {
            float a0A = 0.f, a0B = 0.f;
#pragma unroll 2
            for (int a = 0; a < 16; a++) {
                int wi = a * 8 + b;
                float wA, wB;
                dotp2<16>(sm + wi * 64, h2A, h2B, wA, wB);
                float bb = B3[wi];
                a0A = fmaf(xl0A[a], wA + bb, a0A);
                a0B = fmaf(xl0B[a], wB + bb, a0B);
            }
            float a1A = 0.f, a1B = 0.f;
#pragma unroll 2
            for (int a = 0; a < 4; a++) {
                int wi = 168 + a * 8 + b;
                float wA, wB;
                dotp2<16>(sm + wi * 64, h2A, h2B, wA, wB);
                float bb = B3[wi];
                a1A = fmaf(ul1A[a], wA + bb, a1A);
                a1B = fmaf(ul1B[a], wB + bb, a1B);
            }
            float k0A = NORM * fmaf(shA.x, a0A, I3 * a1A);
            float k0B = NORM * fmaf(shB.x, a0B, I3 * a1B);
            logitA = fmaf(g_qd0[(size_t)dA * 8 + b], k0A, logitA);
            logitB = fmaf(g_qd0[(size_t)dB * 8 + b], k0B, logitB);
        }
#pragma unroll 1
        for (int j = 0; j < 2; j++) {
            float cA = 0.f, cB = 0.f;
#pragma unroll 2
            for (int a = 0; a < 16; a++) {
                int wi = 128 + a * 2 + j;
                float wA, wB;
                dotp2<16>(sm + wi * 64, h2A, h2B, wA, wB);
                float bb = B3[wi];
                cA = fmaf(xl0A[a], wA + bb, cA);
                cB = fmaf(xl0B[a], wB + bb, cB);
            }
            float dxA = 0.f, dyA = 0.f, dzA = 0.f;
            float dxB = 0.f, dyB = 0.f, dzB = 0.f;
#pragma unroll 2
            for (int a = 0; a < 4; a++) {
                int wi = 160 + a * 2 + j;
                float wA, wB;
                dotp2<16>(sm + wi * 64, h2A, h2B, wA, wB);
                float bb = B3[wi];
                wA += bb; wB += bb;
                dxA = fmaf(xl1A[a * 3 + 0], wA, dxA);
                dyA = fmaf(xl1A[a * 3 + 1], wA, dyA);
                dzA = fmaf(xl1A[a * 3 + 2], wA, dzA);
                dxB = fmaf(xl1B[a * 3 + 0], wB, dxB);
                dyB = fmaf(xl1B[a * 3 + 1], wB, dyB);
                dzB = fmaf(xl1B[a * 3 + 2], wB, dzB);
            }
            float k1xA = NORM * (shA.y * cA + shA.x * dxA);
            float k1yA = NORM * (shA.z * cA + shA.x * dyA);
            float k1zA = NORM * (shA.w * cA + shA.x * dzA);
            float k1xB = NORM * (shB.y * cB + shB.x * dxB);
            float k1yB = NORM * (shB.z * cB + shB.x * dyB);
            float k1zB = NORM * (shB.w * cB + shB.x * dzB);
            logitA += I3 * (g_qd1[(size_t)dA * 6 + j * 3 + 0] * k1xA +
                            g_qd1[(size_t)dA * 6 + j * 3 + 1] * k1yA +
                            g_qd1[(size_t)dA * 6 + j * 3 + 2] * k1zA);
            logitB += I3 * (g_qd1[(size_t)dB * 6 + j * 3 + 0] * k1xB +
                            g_qd1[(size_t)dB * 6 + j * 3 + 1] * k1yB +
                            g_qd1[(size_t)dB * 6 + j * 3 + 2] * k1zB);
        }
        logitA *= 0.31622776601683794f;  // 1/sqrt(10)
        logitB *= 0.31622776601683794f;
        g_logit[e0] = logitA;
        atomicMaxF(&g_m[dA], logitA);
        if (hb) {
            g_logit[e1] = logitB;
            atomicMaxF(&g_m[dB], logitB);
        }
    }
}

// ---------------------------------------------------------------------------
// L3V kernel (MERGED, EPT=2): V layer-3 + TP contraction, ALL 28 outputs
// smem: W3V^T (400 x 64) + bias 400 = 26000 floats (104000 B) -> 2 CTAs/SM
// ---------------------------------------------------------------------------
__global__ void __launch_bounds__(128, 2)
l3v_kernel(const float* __restrict__ edge_sh,
           const int*   __restrict__ eidx,
           const float* __restrict__ fcW3, const float* __restrict__ fcb3,
           int E) {
    extern __shared__ float sm[];
    int tid = threadIdx.x, bs = blockDim.x;
    for (int i = tid; i < 25600; i += bs) { int w = i >> 6, c = i & 63; sm[i] = fcW3[c * 400 + w]; }
    for (int i = tid; i < 400;   i += bs) sm[25600 + i] = fcb3[i];
    __syncthreads();
    const float* B3 = sm + 25600;

    const float NORM = 0.22360679774997896f;  // 1/sqrt(20)
    const float I3   = 0.5773502691896258f;   // 1/sqrt(3)

    int stride = gridDim.x * bs;
    for (int e0 = blockIdx.x * bs + tid; e0 < E; e0 += 2 * stride) {
        int e1 = e0 + stride;
        bool hb = e1 < E;
        size_t e1c = hb ? (size_t)e1 : (size_t)e0;

        int sA = eidx[e0], sB = eidx[e1c];
        float4 shA = reinterpret_cast<const float4*>(edge_sh)[e0];
        float4 shB = reinterpret_cast<const float4*>(edge_sh)[e1c];

        ull h2A[32], h2B[32];
        {
            const ulonglong2* ra = reinterpret_cast<const ulonglong2*>(g_h2v + (size_t)e0 * 64);
            const ulonglong2* rb = reinterpret_cast<const ulonglong2*>(g_h2v + e1c * 64);
#pragma unroll
            for (int t = 0; t < 16; t++) {
                ulonglong2 va = ra[t]; ulonglong2 vb = rb[t];
                h2A[2 * t] = va.x; h2A[2 * t + 1] = va.y;
                h2B[2 * t] = vb.x; h2B[2 * t + 1] = vb.y;
            }
        }

        float xl0A[16], xl0B[16], xl1A[12], xl1B[12], ul1A[4], ul1B[4];
#pragma unroll
        for (int o = 0; o < 16; o++) {
            xl0A[o] = g_x0[(size_t)sA * 16 + o];
            xl0B[o] = g_x0[(size_t)sB * 16 + o];
        }
#pragma unroll
        for (int o = 0; o < 12; o++) {
            xl1A[o] = g_x1[(size_t)sA * 12 + o];
            xl1B[o] = g_x1[(size_t)sB * 12 + o];
        }
#pragma unroll
        for (int j = 0; j < 4; j++) {
            ul1A[j] = xl1A[j * 3] * shA.y + xl1A[j * 3 + 1] * shA.z + xl1A[j * 3 + 2] * shA.w;
            ul1B[j] = xl1B[j * 3] * shB.y + xl1B[j * 3 + 1] * shB.z + xl1B[j * 3 + 2] * shB.w;
        }

#pragma unroll 1
        for (int b = 0; b < 16; b++) {
            float a0A = 0.f, a0B = 0.f;
#pragma unroll 2
            for (int a = 0; a < 16; a++) {
                int wi = a * 16 + b;
                float wA, wB;
                dotp2<16>(sm + wi * 64, h2A, h2B, wA, wB);
                float bb = B3[wi];
                a0A = fmaf(xl0A[a], wA + bb, a0A);
                a0B = fmaf(xl0B[a], wB + bb, a0B);
            }
            float a1A = 0.f, a1B = 0.f;
#pragma unroll 2
            for (int a = 0; a < 4; a++) {
                int wi = 336 + a * 16 + b;
                float wA, wB;
                dotp2<16>(sm + wi * 64, h2A, h2B, wA, wB);
                float bb = B3[wi];
                a1A = fmaf(ul1A[a], wA + bb, a1A);
                a1B = fmaf(ul1B[a], wB + bb, a1B);
            }
            g_v[(size_t)b * E + e0] = NORM * fmaf(shA.x, a0A, I3 * a1A);
            if (hb) g_v[(size_t)b * E + e1] = NORM * fmaf(shB.x, a0B, I3 * a1B);
        }
#pragma unroll 1
        for (int j = 0; j < 4; j++) {
            float cA = 0.f, cB = 0.f;
#pragma unroll 2
            for (int a = 0; a < 16; a++) {
                int wi = 256 + a * 4 + j;
                float wA, wB;
                dotp2<16>(sm + wi * 64, h2A, h2B, wA, wB);
                float bb = B3[wi];
                cA = fmaf(xl0A[a], wA + bb, cA);
                cB = fmaf(xl0B[a], wB + bb, cB);
            }
            float dxA = 0.f, dyA = 0.f, dzA = 0.f;
            float dxB = 0.f, dyB = 0.f, dzB = 0.f;
#pragma unroll 2
            for (int a = 0; a < 4; a++) {
                int wi = 320 + a * 4 + j;
                float wA, wB;
                dotp2<16>(sm + wi * 64, h2A, h2B, wA, wB);
                float bb = B3[wi];
                wA += bb; wB += bb;
                dxA = fmaf(xl1A[a * 3 + 0], wA, dxA);
                dyA = fmaf(xl1A[a * 3 + 1], wA, dyA);
                dzA = fmaf(xl1A[a * 3 + 2], wA, dzA);
                dxB = fmaf(xl1B[a * 3 + 0], wB, dxB);
                dyB = fmaf(xl1B[a * 3 + 1], wB, dyB);
                dzB = fmaf(xl1B[a * 3 + 2], wB, dzB);
            }
            g_v[(size_t)(16 + j * 3 + 0) * E + e0] = NORM * (shA.y * cA + shA.x * dxA);
            g_v[(size_t)(16 + j * 3 + 1) * E + e0] = NORM * (shA.z * cA + shA.x * dyA);
            g_v[(size_t)(16 + j * 3 + 2) * E + e0] = NORM * (shA.w * cA + shA.x * dzA);
            if (hb) {
                g_v[(size_t)(16 + j * 3 + 0) * E + e1] = NORM * (shB.y * cB + shB.x * dxB);
                g_v[(size_t)(16 + j * 3 + 1) * E + e1] = NORM * (shB.z * cB + shB.x * dyB);
                g_v[(size_t)(16 + j * 3 + 2) * E + e1] = NORM * (shB.w * cB + shB.x * dzB);
            }
        }
    }
}

// ---------------------------------------------------------------------------
// softmax+aggregate: 4 threads per edge (7 channels each) — atomics are
// latency-bound, so 4x parallelism cuts the exposed latency.
// ---------------------------------------------------------------------------
__global__ void softmax_agg_kernel(const int* __restrict__ eidx, int E) {
    int t = blockIdx.x * blockDim.x + threadIdx.x;
    int e = t >> 2;
    int q = t & 3;
    if (e >= E) return;
    int d = eidx[E + e];
    float p = __expf(g_logit[e] - g_m[d]);
    if (q == 0) atomicAdd(&g_z[d], p);
#pragma unroll
    for (int jj = 0; jj < 7; jj++) {
        int j = q * 7 + jj;
        atomicAdd(&g_agg[(size_t)d * 28 + j], p * g_v[(size_t)j * E + e]);
    }
}

// ---------------------------------------------------------------------------
__global__ void node_out_kernel(const float* __restrict__ na,
                                const float* __restrict__ Wo0,
                                const float* __restrict__ Wo1,
                                float* __restrict__ out, int N) {
    __shared__ float sW0[512], sW1[32];
    int tid = threadIdx.x;
    for (int i = tid; i < 512; i += blockDim.x) sW0[i] = Wo0[i];
    for (int i = tid; i < 32;  i += blockDim.x) sW1[i] = Wo1[i];
    __syncthreads();

    int n = blockIdx.x * blockDim.x + tid;
    if (n >= N) return;
    float z = g_z[n];
    float zi = z > 0.f ? 1.f / z : 0.f;
    float ag[28];
#pragma unroll
    for (int j = 0; j < 28; j++) ag[j] = g_agg[(size_t)n * 28 + j] * zi;

#pragma unroll
    for (int o = 0; o < 32; o++) {
        float s = 0.f;
#pragma unroll
        for (int a = 0; a < 16; a++) s = fmaf(ag[a], sW0[a * 32 + o], s);
        out[(size_t)n * 56 + o] = fmaf(s, 0.25f, na[(size_t)n * 56 + o]);
    }
#pragma unroll
    for (int o = 0; o < 8; o++)
#pragma unroll
        for (int c = 0; c < 3; c++) {
            float s = 0.f;
#pragma unroll
            for (int a = 0; a < 4; a++) s = fmaf(ag[16 + a * 3 + c], sW1[a * 8 + o], s);
            out[(size_t)n * 56 + 32 + o * 3 + c] =
                fmaf(s, 0.5f, na[(size_t)n * 56 + 32 + o * 3 + c]);
        }
}

// ---------------------------------------------------------------------------
extern "C" void kernel_launch(void* const* d_in, const int* in_sizes, int n_in,
                              void* d_out, int out_size) {
    const float* node_attr  = (const float*)d_in[0];
    const float* edge_attr  = (const float*)d_in[1];
    const float* edge_sh    = (const float*)d_in[2];
    const int*   edge_index = (const int*)  d_in[3];
    const float* W_in0  = (const float*)d_in[4];
    const float* W_in1  = (const float*)d_in[5];
    const float* Wq0    = (const float*)d_in[6];
    const float* Wq1    = (const float*)d_in[7];
    const float* Wd0    = (const float*)d_in[8];
    const float* Wd1    = (const float*)d_in[9];
    const float* W_out0 = (const float*)d_in[10];
    const float* W_out1 = (const float*)d_in[11];
    const float* fcW1 = (const float*)d_in[12];
    const float* fcb1 = (const float*)d_in[13];
    const float* fcW2 = (const float*)d_in[14];
    const float* fcb2 = (const float*)d_in[15];
    const float* fcW3 = (const float*)d_in[16];
    const float* fcb3 = (const float*)d_in[17];
    const float* fkW1 = (const float*)d_in[18];
    const float* fkb1 = (const float*)d_in[19];
    const float* fkW2 = (const float*)d_in[20];
    const float* fkb2 = (const float*)d_in[21];
    const float* fkW3 = (const float*)d_in[22];
    const float* fkb3 = (const float*)d_in[23];
    float* out = (float*)d_out;

    int N = in_sizes[0] / 56;
    int E = in_sizes[2] / 4;

    const int FRONT_SMEM = F_FLOATS * (int)sizeof(float);   // 50176 B
    const int L3K_SMEM   = 13000 * (int)sizeof(float);      // 52000 B
    const int L3V_SMEM   = 26000 * (int)sizeof(float);      // 104000 B

    cudaFuncSetAttribute(front_kernel,
                         cudaFuncAttributeMaxDynamicSharedMemorySize, FRONT_SMEM);
    cudaFuncSetAttribute(l3k_kernel,
                         cudaFuncAttributeMaxDynamicSharedMemorySize, L3K_SMEM);
    cudaFuncSetAttribute(l3v_kernel,
                         cudaFuncAttributeMaxDynamicSharedMemorySize, L3V_SMEM);

    node_prep_kernel<<<(N + 127) / 128, 128>>>(node_attr, W_in0, W_in1, Wq0, Wq1,
                                               Wd0, Wd1, N);
    init_kernel<<<(N * 28 + 255) / 256, 256>>>(N);
    front_kernel<<<NSM * 2, 128, FRONT_SMEM>>>(edge_attr,
                                               fcW1, fcb1, fcW2, fcb2,
                                               fkW1, fkb1, fkW2, fkb2, E);
    l3k_kernel<<<NSM * 2, 128, L3K_SMEM>>>(edge_sh, edge_index, fkW3, fkb3, E);
    l3v_kernel<<<NSM * 2, 128, L3V_SMEM>>>(edge_sh, edge_index, fcW3, fcb3, E);
    softmax_agg_kernel<<<(E * 4 + 255) / 256, 256>>>(edge_index, E);
    node_out_kernel<<<(N + 127) / 128, 128>>>(node_attr, W_out0, W_out1, out, N);
}

// round 13
// speedup vs baseline: 1.7689x; 1.1401x over previous
#include <cuda_runtime.h>
#include <cstdint>
#include <cstddef>

#define MAXN 10000
#define MAXE 160000
#define NSM  148

typedef unsigned long long ull;

__device__ float g_x0[MAXN * 16];
__device__ float g_x1[MAXN * 12];
__device__ float g_qd0[MAXN * 8];
__device__ float g_qd1[MAXN * 6];
__device__ float g_logit[MAXE];
__device__ float g_v[MAXE * 28];       // SoA: [j*E + e]
__device__ float g_m[MAXN];
__device__ float g_z[MAXN];
__device__ float g_agg[MAXN * 28];     // AoS
__device__ float g_h2k[(size_t)MAXE * 64];   // TRANSPOSED: [c*E + e]
__device__ float g_h2v[(size_t)MAXE * 64];   // TRANSPOSED: [c*E + e]

__device__ __forceinline__ float frelu(float x) { return x > 0.f ? x : 0.f; }

// ---- packed f32x2 helpers (front kernel) ----------------------------------
__device__ __forceinline__ ull pack2(float lo, float hi) {
    ull r; asm("mov.b64 %0, {%1, %2};" : "=l"(r) : "f"(lo), "f"(hi)); return r;
}
__device__ __forceinline__ void unpack2(ull v, float& lo, float& hi) {
    asm("mov.b64 {%0, %1}, %2;" : "=f"(lo), "=f"(hi) : "l"(v));
}
__device__ __forceinline__ void ffma2(ull& d, ull a, ull b) {
    asm("fma.rn.f32x2 %0, %1, %2, %0;" : "+l"(d) : "l"(a), "l"(b));
}

template <int NU2>
__device__ __forceinline__ void dotp2(const float* __restrict__ w,
                                      const ull* __restrict__ hA,
                                      const ull* __restrict__ hB,
                                      float& rA, float& rB) {
    ull a0 = 0ull, a1 = 0ull, b0 = 0ull, b1 = 0ull;
    const ulonglong2* wp = reinterpret_cast<const ulonglong2*>(w);
#pragma unroll
    for (int t = 0; t < NU2; t++) {
        ulonglong2 ww = wp[t];
        ffma2(a0, ww.x, hA[2 * t]);
        ffma2(a1, ww.y, hA[2 * t + 1]);
        ffma2(b0, ww.x, hB[2 * t]);
        ffma2(b1, ww.y, hB[2 * t + 1]);
    }
    float x0, x1, x2, x3;
    unpack2(a0, x0, x1); unpack2(a1, x2, x3);
    rA = (x0 + x1) + (x2 + x3);
    unpack2(b0, x0, x1); unpack2(b1, x2, x3);
    rB = (x0 + x1) + (x2 + x3);
}

__device__ __forceinline__ void atomicMaxF(float* addr, float v) {
    if (v >= 0.f) atomicMax((int*)addr, __float_as_int(v));
    else          atomicMin((unsigned int*)addr, __float_as_uint(v));
}

// ---- tf32 helpers ----------------------------------------------------------
__device__ __forceinline__ float to_tf32(float x) {
    uint32_t u; asm("cvt.rna.tf32.f32 %0, %1;" : "=r"(u) : "f"(x));
    return __uint_as_float(u);
}
__device__ __forceinline__ void mma_tf32(float* d, const uint32_t* a,
                                         const uint32_t* b) {
    asm volatile(
        "mma.sync.aligned.m16n8k8.row.col.f32.tf32.tf32.f32 "
        "{%0,%1,%2,%3}, {%4,%5,%6,%7}, {%8,%9}, {%0,%1,%2,%3};\n"
        : "+f"(d[0]), "+f"(d[1]), "+f"(d[2]), "+f"(d[3])
        : "r"(a[0]), "r"(a[1]), "r"(a[2]), "r"(a[3]), "r"(b[0]), "r"(b[1]));
}

// ---------------------------------------------------------------------------
// Kernel A: node prep
// ---------------------------------------------------------------------------
__global__ void node_prep_kernel(const float* __restrict__ na,
                                 const float* __restrict__ Win0,
                                 const float* __restrict__ Win1,
                                 const float* __restrict__ Wq0,
                                 const float* __restrict__ Wq1,
                                 const float* __restrict__ Wd0,
                                 const float* __restrict__ Wd1,
                                 int N) {
    __shared__ float sWin0[512], sWin1[32], sWq0[128], sWq1[8], sWd0[64], sWd1[4];
    int tid = threadIdx.x;
    for (int i = tid; i < 512; i += blockDim.x) sWin0[i] = Win0[i];
    for (int i = tid; i < 32;  i += blockDim.x) sWin1[i] = Win1[i];
    for (int i = tid; i < 128; i += blockDim.x) sWq0[i]  = Wq0[i];
    for (int i = tid; i < 8;   i += blockDim.x) sWq1[i]  = Wq1[i];
    for (int i = tid; i < 64;  i += blockDim.x) sWd0[i]  = Wd0[i];
    for (int i = tid; i < 4;   i += blockDim.x) sWd1[i]  = Wd1[i];
    __syncthreads();

    int n = blockIdx.x * blockDim.x + tid;
    if (n >= N) return;

    const float* p = na + (size_t)n * 56;
    float a0[32], a1[24];
#pragma unroll
    for (int i = 0; i < 32; i++) a0[i] = p[i];
#pragma unroll
    for (int i = 0; i < 24; i++) a1[i] = p[32 + i];

    float x0[16];
#pragma unroll
    for (int o = 0; o < 16; o++) {
        float s = 0.f;
#pragma unroll
        for (int i = 0; i < 32; i++) s = fmaf(a0[i], sWin0[i * 16 + o], s);
        x0[o] = s * 0.17677669529663687f;   // 1/sqrt(32)
    }
    float x1[12];
#pragma unroll
    for (int o = 0; o < 4; o++)
#pragma unroll
        for (int c = 0; c < 3; c++) {
            float s = 0.f;
#pragma unroll
            for (int m = 0; m < 8; m++) s = fmaf(a1[m * 3 + c], sWin1[m * 4 + o], s);
            x1[o * 3 + c] = s * 0.35355339059327373f;  // 1/sqrt(8)
        }

    float q0[8];
#pragma unroll
    for (int b = 0; b < 8; b++) {
        float s = 0.f;
#pragma unroll
        for (int o = 0; o < 16; o++) s = fmaf(x0[o], sWq0[o * 8 + b], s);
        q0[b] = s * 0.25f;                   // 1/sqrt(16)
    }
    float q1[6];
#pragma unroll
    for (int j = 0; j < 2; j++)
#pragma unroll
        for (int c = 0; c < 3; c++) {
            float s = 0.f;
#pragma unroll
            for (int o = 0; o < 4; o++) s = fmaf(x1[o * 3 + c], sWq1[o * 2 + j], s);
            q1[j * 3 + c] = s * 0.5f;        // 1/sqrt(4)
        }

#pragma unroll
    for (int j = 0; j < 8; j++) {
        float s = 0.f;
#pragma unroll
        for (int i = 0; i < 8; i++) s = fmaf(q0[i], sWd0[i * 8 + j], s);
        g_qd0[(size_t)n * 8 + j] = s;
    }
#pragma unroll
    for (int j = 0; j < 2; j++)
#pragma unroll
        for (int c = 0; c < 3; c++) {
            float s = 0.f;
#pragma unroll
            for (int i = 0; i < 2; i++) s = fmaf(q1[i * 3 + c], sWd1[i * 2 + j], s);
            g_qd1[(size_t)n * 6 + j * 3 + c] = s;
        }

#pragma unroll
    for (int o = 0; o < 16; o++) g_x0[(size_t)n * 16 + o] = x0[o];
#pragma unroll
    for (int o = 0; o < 12; o++) g_x1[(size_t)n * 12 + o] = x1[o];
}

// ---------------------------------------------------------------------------
__global__ void init_kernel(int N) {
    int i = blockIdx.x * blockDim.x + threadIdx.x;
    if (i < N * 28) g_agg[i] = 0.f;
    if (i < N) {
        g_m[i] = __int_as_float(0xff800000);  // -inf
        g_z[i] = 0.f;
    }
}

// ---------------------------------------------------------------------------
// FRONT kernel (EPT=2): both MLP fronts, writes h2 TRANSPOSED (c-major)
// ---------------------------------------------------------------------------
#define F_OW1K 0
#define F_OB1K 2048
#define F_OW2K 2112
#define F_OB2K 6208
#define F_OW1V 6272
#define F_OB1V 8320
#define F_OW2V 8384
#define F_OB2V 12480
#define F_FLOATS 12544

__device__ __forceinline__ void front_one2(const float* __restrict__ sm,
                                           int oW1, int oB1, int oW2, int oB2,
                                           const float* __restrict__ edge_attr,
                                           float* __restrict__ gh2,
                                           size_t e0, size_t e1, bool hb, int E) {
    ull eapA[16], eapB[16];
    {
        const ulonglong2* a2 = reinterpret_cast<const ulonglong2*>(edge_attr + e0 * 32);
        const ulonglong2* b2 = reinterpret_cast<const ulonglong2*>(edge_attr + e1 * 32);
#pragma unroll
        for (int t = 0; t < 8; t++) {
            ulonglong2 va = a2[t]; ulonglong2 vb = b2[t];
            eapA[2 * t] = va.x; eapA[2 * t + 1] = va.y;
            eapB[2 * t] = vb.x; eapB[2 * t + 1] = vb.y;
        }
    }
    ull h1A[32], h1B[32];
#pragma unroll 4
    for (int o = 0; o < 64; o += 2) {
        float loA, loB, hiA, hiB;
        dotp2<8>(sm + oW1 + o * 32,       eapA, eapB, loA, loB);
        dotp2<8>(sm + oW1 + (o + 1) * 32, eapA, eapB, hiA, hiB);
        float b_lo = sm[oB1 + o], b_hi = sm[oB1 + o + 1];
        h1A[o >> 1] = pack2(frelu(b_lo + loA), frelu(b_hi + hiA));
        h1B[o >> 1] = pack2(frelu(b_lo + loB), frelu(b_hi + hiB));
    }
#pragma unroll 2
    for (int o = 0; o < 64; o += 4) {
        float vA[4], vB[4];
#pragma unroll
        for (int k = 0; k < 4; k++) {
            float a, b;
            dotp2<16>(sm + oW2 + (o + k) * 64, h1A, h1B, a, b);
            float bias = sm[oB2 + o + k];
            vA[k] = frelu(bias + a);
            vB[k] = frelu(bias + b);
        }
        // transposed (c-major) stores — coalesced across the warp
#pragma unroll
        for (int k = 0; k < 4; k++) {
            gh2[(size_t)(o + k) * E + e0] = vA[k];
            if (hb) gh2[(size_t)(o + k) * E + e1] = vB[k];
        }
    }
}

__global__ void __launch_bounds__(128, 2)
front_kernel(const float* __restrict__ edge_attr,
             const float* __restrict__ fcW1, const float* __restrict__ fcb1,
             const float* __restrict__ fcW2, const float* __restrict__ fcb2,
             const float* __restrict__ fkW1, const float* __restrict__ fkb1,
             const float* __restrict__ fkW2, const float* __restrict__ fkb2,
             int E) {
    extern __shared__ float sm[];
    int tid = threadIdx.x, bs = blockDim.x;
    for (int i = tid; i < 2048; i += bs) { int o = i >> 5, c = i & 31; sm[F_OW1K + i] = fkW1[c * 64 + o]; }
    for (int i = tid; i < 64;   i += bs) sm[F_OB1K + i] = fkb1[i];
    for (int i = tid; i < 4096; i += bs) { int o = i >> 6, c = i & 63; sm[F_OW2K + i] = fkW2[c * 64 + o]; }
    for (int i = tid; i < 64;   i += bs) sm[F_OB2K + i] = fkb2[i];
    for (int i = tid; i < 2048; i += bs) { int o = i >> 5, c = i & 31; sm[F_OW1V + i] = fcW1[c * 64 + o]; }
    for (int i = tid; i < 64;   i += bs) sm[F_OB1V + i] = fcb1[i];
    for (int i = tid; i < 4096; i += bs) { int o = i >> 6, c = i & 63; sm[F_OW2V + i] = fcW2[c * 64 + o]; }
    for (int i = tid; i < 64;   i += bs) sm[F_OB2V + i] = fcb2[i];
    __syncthreads();

    int stride = gridDim.x * bs;
    for (int e0 = blockIdx.x * bs + tid; e0 < E; e0 += 2 * stride) {
        int e1 = e0 + stride;
        bool hb = e1 < E;
        size_t e1c = hb ? (size_t)e1 : (size_t)e0;
        front_one2(sm, F_OW1K, F_OB1K, F_OW2K, F_OB2K, edge_attr, g_h2k,
                   (size_t)e0, e1c, hb, E);
        front_one2(sm, F_OW1V, F_OB1V, F_OW2V, F_OB2V, edge_attr, g_h2v,
                   (size_t)e0, e1c, hb, E);
    }
}

// ---------------------------------------------------------------------------
// L3 tensor-core GEMM machinery (persistent tiles of 128 edges)
//   C[w<224][e<128] = A[e][c<64] x B[c][w], tf32 mma m16n8k8, fp32 accum.
//   Warp w: edges [16w,16w+16). 28 n-tiles x 8 k-steps = 224 mma/warp/tile.
// smem floats: B 64*228 | A 64*132 | C 224*132 | bias 224
// ---------------------------------------------------------------------------
#define TE     128
#define NWP    224
#define APAD   132
#define BPAD   228
#define CPAD   132
#define L3_B_OFF    0
#define L3_A_OFF    14592
#define L3_C_OFF    23040
#define L3_BIAS_OFF 52608
#define L3_FLOATS   52832

__device__ __forceinline__ void l3_load_A(float* __restrict__ As,
                                          const float* __restrict__ gh2T,
                                          int e0, int E, int tid) {
    // As[c][e] = tf32(gh2T[c*E + e0 + e]), APAD stride
    for (int i = tid; i < 64 * (TE / 4); i += 256) {
        int c = i >> 5;            // i / 32
        int v = i & 31;            // i % 32
        int eb = e0 + 4 * v;
        float4 f;
        if (eb + 3 < E) {
            f = *reinterpret_cast<const float4*>(gh2T + (size_t)c * E + eb);
        } else {
            f.x = (eb + 0 < E) ? gh2T[(size_t)c * E + eb + 0] : 0.f;
            f.y = (eb + 1 < E) ? gh2T[(size_t)c * E + eb + 1] : 0.f;
            f.z = (eb + 2 < E) ? gh2T[(size_t)c * E + eb + 2] : 0.f;
            f.w = (eb + 3 < E) ? gh2T[(size_t)c * E + eb + 3] : 0.f;
        }
        f.x = to_tf32(f.x); f.y = to_tf32(f.y);
        f.z = to_tf32(f.z); f.w = to_tf32(f.w);
        *reinterpret_cast<float4*>(As + c * APAD + 4 * v) = f;
    }
}

__device__ __forceinline__ void l3_gemm_mma(const float* __restrict__ As,
                                            const float* __restrict__ Bs,
                                            float* __restrict__ Cs, int tid) {
    int warp = tid >> 5, lane = tid & 31;
    int g = lane >> 2, tc = lane & 3;
    int e0 = warp * 16;

    float acc[28][4];
#pragma unroll
    for (int n = 0; n < 28; n++)
#pragma unroll
        for (int i = 0; i < 4; i++) acc[n][i] = 0.f;

#pragma unroll
    for (int k0 = 0; k0 < 64; k0 += 8) {
        uint32_t a[4];
        a[0] = __float_as_uint(As[(k0 + tc)     * APAD + e0 + g]);
        a[1] = __float_as_uint(As[(k0 + tc)     * APAD + e0 + g + 8]);
        a[2] = __float_as_uint(As[(k0 + tc + 4) * APAD + e0 + g]);
        a[3] = __float_as_uint(As[(k0 + tc + 4) * APAD + e0 + g + 8]);
#pragma unroll
        for (int n = 0; n < 28; n++) {
            uint32_t b[2];
            b[0] = __float_as_uint(Bs[(k0 + tc)     * BPAD + n * 8 + g]);
            b[1] = __float_as_uint(Bs[(k0 + tc + 4) * BPAD + n * 8 + g]);
            mma_tf32(acc[n], a, b);
        }
    }
    // store C[w][e]: c0:(n*8+2tc, e0+g) c1:(+1 col) c2:(row+8 edges) ...
#pragma unroll
    for (int n = 0; n < 28; n++) {
        int w0 = n * 8 + 2 * tc;
        Cs[w0 * CPAD + e0 + g]           = acc[n][0];
        Cs[(w0 + 1) * CPAD + e0 + g]     = acc[n][1];
        Cs[w0 * CPAD + e0 + g + 8]       = acc[n][2];
        Cs[(w0 + 1) * CPAD + e0 + g + 8] = acc[n][3];
    }
}

// ---------------------------------------------------------------------------
// L3K: persistent tensor GEMM + K contraction + logit + atomicMax
// Epilogue: 2 threads per edge (h splits b-range and j), shfl combine.
// ---------------------------------------------------------------------------
__global__ void __launch_bounds__(256, 1)
l3k_kernel(const float* __restrict__ edge_sh,
           const int*   __restrict__ eidx,
           const float* __restrict__ fkW3, const float* __restrict__ fkb3,
           int E, int tiles) {
    extern __shared__ float smx[];
    float* Bs  = smx + L3_B_OFF;
    float* As  = smx + L3_A_OFF;
    float* Cs  = smx + L3_C_OFF;
    float* sB3 = smx + L3_BIAS_OFF;
    int tid = threadIdx.x;

    for (int i = tid; i < 64 * BPAD; i += 256) {
        int c = i / BPAD, w = i % BPAD;
        Bs[i] = (w < 200) ? to_tf32(fkW3[c * 200 + w]) : 0.f;
    }
    for (int i = tid; i < NWP; i += 256)
        sB3[i] = (i < 200) ? fkb3[i] : 0.f;

    const float NORM = 0.22360679774997896f;  // 1/sqrt(20)
    const float I3   = 0.5773502691896258f;   // 1/sqrt(3)

    for (int tile = blockIdx.x; tile < tiles; tile += gridDim.x) {
        int e0 = tile * TE;
        l3_load_A(As, g_h2k, e0, E, tid);
        __syncthreads();
        l3_gemm_mma(As, Bs, Cs, tid);
        __syncthreads();

        {
            int el = tid >> 1;
            int h  = tid & 1;
            int e  = e0 + el;
            int ee = (e < E) ? e : (E - 1);
            int s = eidx[ee], d = eidx[E + ee];
            float4 sh = reinterpret_cast<const float4*>(edge_sh)[ee];

            float xl0[16], xl1[12], ul1[4];
#pragma unroll
            for (int o = 0; o < 16; o++) xl0[o] = g_x0[(size_t)s * 16 + o];
#pragma unroll
            for (int o = 0; o < 12; o++) xl1[o] = g_x1[(size_t)s * 12 + o];
#pragma unroll
            for (int j = 0; j < 4; j++)
                ul1[j] = xl1[j * 3] * sh.y + xl1[j * 3 + 1] * sh.z + xl1[j * 3 + 2] * sh.w;

            float logit = 0.f;
#pragma unroll
            for (int bb = 0; bb < 4; bb++) {
                int b = 4 * h + bb;
                float acc0 = 0.f;
#pragma unroll
                for (int a = 0; a < 16; a++) {
                    int r = a * 8 + b;
                    acc0 = fmaf(xl0[a], Cs[r * CPAD + el] + sB3[r], acc0);
                }
                float acc1 = 0.f;
#pragma unroll
                for (int a = 0; a < 4; a++) {
                    int r = 168 + a * 8 + b;
                    acc1 = fmaf(ul1[a], Cs[r * CPAD + el] + sB3[r], acc1);
                }
                float k0b = NORM * fmaf(sh.x, acc0, I3 * acc1);
                logit = fmaf(g_qd0[(size_t)d * 8 + b], k0b, logit);
            }
            {
                int j = h;
                float c01 = 0.f;
#pragma unroll
                for (int a = 0; a < 16; a++) {
                    int r = 128 + a * 2 + j;
                    c01 = fmaf(xl0[a], Cs[r * CPAD + el] + sB3[r], c01);
                }
                float dx = 0.f, dy = 0.f, dz = 0.f;
#pragma unroll
                for (int a = 0; a < 4; a++) {
                    int r = 160 + a * 2 + j;
                    float w = Cs[r * CPAD + el] + sB3[r];
                    dx = fmaf(xl1[a * 3 + 0], w, dx);
                    dy = fmaf(xl1[a * 3 + 1], w, dy);
                    dz = fmaf(xl1[a * 3 + 2], w, dz);
                }
                float k1x = NORM * (sh.y * c01 + sh.x * dx);
                float k1y = NORM * (sh.z * c01 + sh.x * dy);
                float k1z = NORM * (sh.w * c01 + sh.x * dz);
                logit += I3 * (g_qd1[(size_t)d * 6 + j * 3 + 0] * k1x +
                               g_qd1[(size_t)d * 6 + j * 3 + 1] * k1y +
                               g_qd1[(size_t)d * 6 + j * 3 + 2] * k1z);
            }
            logit += __shfl_xor_sync(0xffffffffu, logit, 1);
            logit *= 0.31622776601683794f;  // 1/sqrt(10)
            if (h == 0 && e < E) {
                g_logit[e] = logit;
                atomicMaxF(&g_m[d], logit);
            }
        }
        __syncthreads();
    }
}

// ---------------------------------------------------------------------------
// L3V (HALF = 0/1): persistent tensor GEMM + V contraction, half outputs
// ---------------------------------------------------------------------------
template <int HALF>
__device__ __forceinline__ int v_wi(int r) {
    if (r < 128) { int a = r >> 3, b = r & 7;        return a * 16 + HALF * 8 + b; }
    if (r < 160) { int t = r - 128; int a = t >> 1;  return 256 + a * 4 + HALF * 2 + (t & 1); }
    if (r < 168) { int t = r - 160; int a = t >> 1;  return 320 + a * 4 + HALF * 2 + (t & 1); }
    { int t = r - 168; int a = t >> 3, b = t & 7;    return 336 + a * 16 + HALF * 8 + b; }
}

template <int HALF>
__global__ void __launch_bounds__(256, 1)
l3v_kernel(const float* __restrict__ edge_sh,
           const int*   __restrict__ eidx,
           const float* __restrict__ fcW3, const float* __restrict__ fcb3,
           int E, int tiles) {
    extern __shared__ float smx[];
    float* Bs  = smx + L3_B_OFF;
    float* As  = smx + L3_A_OFF;
    float* Cs  = smx + L3_C_OFF;
    float* sB3 = smx + L3_BIAS_OFF;
    int tid = threadIdx.x;

    for (int i = tid; i < 64 * BPAD; i += 256) {
        int c = i / BPAD, w = i % BPAD;
        Bs[i] = (w < 200) ? to_tf32(fcW3[c * 400 + v_wi<HALF>(w)]) : 0.f;
    }
    for (int i = tid; i < NWP; i += 256)
        sB3[i] = (i < 200) ? fcb3[v_wi<HALF>(i)] : 0.f;

    const float NORM = 0.22360679774997896f;  // 1/sqrt(20)
    const float I3   = 0.5773502691896258f;   // 1/sqrt(3)

    for (int tile = blockIdx.x; tile < tiles; tile += gridDim.x) {
        int e0 = tile * TE;
        l3_load_A(As, g_h2v, e0, E, tid);
        __syncthreads();
        l3_gemm_mma(As, Bs, Cs, tid);
        __syncthreads();

        {
            int el = tid >> 1;
            int h  = tid & 1;
            int e  = e0 + el;
            bool ok = e < E;
            int ee = ok ? e : (E - 1);
            int s = eidx[ee];
            float4 sh = reinterpret_cast<const float4*>(edge_sh)[ee];

            float xl0[16], xl1[12], ul1[4];
#pragma unroll
            for (int o = 0; o < 16; o++) xl0[o] = g_x0[(size_t)s * 16 + o];
#pragma unroll
            for (int o = 0; o < 12; o++) xl1[o] = g_x1[(size_t)s * 12 + o];
#pragma unroll
            for (int j = 0; j < 4; j++)
                ul1[j] = xl1[j * 3] * sh.y + xl1[j * 3 + 1] * sh.z + xl1[j * 3 + 2] * sh.w;

#pragma unroll
            for (int bb = 0; bb < 4; bb++) {
                int b = 4 * h + bb;
                float acc0 = 0.f;
#pragma unroll
                for (int a = 0; a < 16; a++) {
                    int r = a * 8 + b;
                    acc0 = fmaf(xl0[a], Cs[r * CPAD + el] + sB3[r], acc0);
                }
                float acc1 = 0.f;
#pragma unroll
                for (int a = 0; a < 4; a++) {
                    int r = 168 + a * 8 + b;
                    acc1 = fmaf(ul1[a], Cs[r * CPAD + el] + sB3[r], acc1);
                }
                int bg = HALF * 8 + b;
                if (ok) g_v[(size_t)bg * E + e] = NORM * fmaf(sh.x, acc0, I3 * acc1);
            }
            {
                int j = h;
                float c01 = 0.f;
#pragma unroll
                for (int a = 0; a < 16; a++) {
                    int r = 128 + a * 2 + j;
                    c01 = fmaf(xl0[a], Cs[r * CPAD + el] + sB3[r], c01);
                }
                float dx = 0.f, dy = 0.f, dz = 0.f;
#pragma unroll
                for (int a = 0; a < 4; a++) {
                    int r = 160 + a * 2 + j;
                    float w = Cs[r * CPAD + el] + sB3[r];
                    dx = fmaf(xl1[a * 3 + 0], w, dx);
                    dy = fmaf(xl1[a * 3 + 1], w, dy);
                    dz = fmaf(xl1[a * 3 + 2], w, dz);
                }
                int jg = HALF * 2 + j;
                if (ok) {
                    g_v[(size_t)(16 + jg * 3 + 0) * E + e] = NORM * (sh.y * c01 + sh.x * dx);
                    g_v[(size_t)(16 + jg * 3 + 1) * E + e] = NORM * (sh.z * c01 + sh.x * dy);
                    g_v[(size_t)(16 + jg * 3 + 2) * E + e] = NORM * (sh.w * c01 + sh.x * dz);
                }
            }
        }
        __syncthreads();
    }
}

// ---------------------------------------------------------------------------
// softmax+aggregate: 4 threads per edge (7 channels each)
// ---------------------------------------------------------------------------
__global__ void softmax_agg_kernel(const int* __restrict__ eidx, int E) {
    int t = blockIdx.x * blockDim.x + threadIdx.x;
    int e = t >> 2;
    int q = t & 3;
    if (e >= E) return;
    int d = eidx[E + e];
    float p = __expf(g_logit[e] - g_m[d]);
    if (q == 0) atomicAdd(&g_z[d], p);
#pragma unroll
    for (int jj = 0; jj < 7; jj++) {
        int j = q * 7 + jj;
        atomicAdd(&g_agg[(size_t)d * 28 + j], p * g_v[(size_t)j * E + e]);
    }
}

// ---------------------------------------------------------------------------
__global__ void node_out_kernel(const float* __restrict__ na,
                                const float* __restrict__ Wo0,
                                const float* __restrict__ Wo1,
                                float* __restrict__ out, int N) {
    __shared__ float sW0[512], sW1[32];
    int tid = threadIdx.x;
    for (int i = tid; i < 512; i += blockDim.x) sW0[i] = Wo0[i];
    for (int i = tid; i < 32;  i += blockDim.x) sW1[i] = Wo1[i];
    __syncthreads();

    int n = blockIdx.x * blockDim.x + tid;
    if (n >= N) return;
    float z = g_z[n];
    float zi = z > 0.f ? 1.f / z : 0.f;
    float ag[28];
#pragma unroll
    for (int j = 0; j < 28; j++) ag[j] = g_agg[(size_t)n * 28 + j] * zi;

#pragma unroll
    for (int o = 0; o < 32; o++) {
        float s = 0.f;
#pragma unroll
        for (int a = 0; a < 16; a++) s = fmaf(ag[a], sW0[a * 32 + o], s);
        out[(size_t)n * 56 + o] = fmaf(s, 0.25f, na[(size_t)n * 56 + o]);
    }
#pragma unroll
    for (int o = 0; o < 8; o++)
#pragma unroll
        for (int c = 0; c < 3; c++) {
            float s = 0.f;
#pragma unroll
            for (int a = 0; a < 4; a++) s = fmaf(ag[16 + a * 3 + c], sW1[a * 8 + o], s);
            out[(size_t)n * 56 + 32 + o * 3 + c] =
                fmaf(s, 0.5f, na[(size_t)n * 56 + 32 + o * 3 + c]);
        }
}

// ---------------------------------------------------------------------------
extern "C" void kernel_launch(void* const* d_in, const int* in_sizes, int n_in,
                              void* d_out, int out_size) {
    const float* node_attr  = (const float*)d_in[0];
    const float* edge_attr  = (const float*)d_in[1];
    const float* edge_sh    = (const float*)d_in[2];
    const int*   edge_index = (const int*)  d_in[3];
    const float* W_in0  = (const float*)d_in[4];
    const float* W_in1  = (const float*)d_in[5];
    const float* Wq0    = (const float*)d_in[6];
    const float* Wq1    = (const float*)d_in[7];
    const float* Wd0    = (const float*)d_in[8];
    const float* Wd1    = (const float*)d_in[9];
    const float* W_out0 = (const float*)d_in[10];
    const float* W_out1 = (const float*)d_in[11];
    const float* fcW1 = (const float*)d_in[12];
    const float* fcb1 = (const float*)d_in[13];
    const float* fcW2 = (const float*)d_in[14];
    const float* fcb2 = (const float*)d_in[15];
    const float* fcW3 = (const float*)d_in[16];
    const float* fcb3 = (const float*)d_in[17];
    const float* fkW1 = (const float*)d_in[18];
    const float* fkb1 = (const float*)d_in[19];
    const float* fkW2 = (const float*)d_in[20];
    const float* fkb2 = (const float*)d_in[21];
    const float* fkW3 = (const float*)d_in[22];
    const float* fkb3 = (const float*)d_in[23];
    float* out = (float*)d_out;

    int N = in_sizes[0] / 56;
    int E = in_sizes[2] / 4;

    const int FRONT_SMEM = F_FLOATS * (int)sizeof(float);   // 50176 B
    const int L3_SMEM    = L3_FLOATS * (int)sizeof(float);  // 211328 B

    cudaFuncSetAttribute(front_kernel,
                         cudaFuncAttributeMaxDynamicSharedMemorySize, FRONT_SMEM);
    cudaFuncSetAttribute(l3k_kernel,
                         cudaFuncAttributeMaxDynamicSharedMemorySize, L3_SMEM);
    cudaFuncSetAttribute(l3v_kernel<0>,
                         cudaFuncAttributeMaxDynamicSharedMemorySize, L3_SMEM);
    cudaFuncSetAttribute(l3v_kernel<1>,
                         cudaFuncAttributeMaxDynamicSharedMemorySize, L3_SMEM);

    int tiles = (E + TE - 1) / TE;

    node_prep_kernel<<<(N + 127) / 128, 128>>>(node_attr, W_in0, W_in1, Wq0, Wq1,
                                               Wd0, Wd1, N);
    init_kernel<<<(N * 28 + 255) / 256, 256>>>(N);
    front_kernel<<<NSM * 2, 128, FRONT_SMEM>>>(edge_attr,
                                               fcW1, fcb1, fcW2, fcb2,
                                               fkW1, fkb1, fkW2, fkb2, E);
    l3k_kernel<<<NSM, 256, L3_SMEM>>>(edge_sh, edge_index, fkW3, fkb3, E, tiles);
    l3v_kernel<0><<<NSM, 256, L3_SMEM>>>(edge_sh, edge_index, fcW3, fcb3, E, tiles);
    l3v_kernel<1><<<NSM, 256, L3_SMEM>>>(edge_sh, edge_index, fcW3, fcb3, E, tiles);
    softmax_agg_kernel<<<(E * 4 + 255) / 256, 256>>>(edge_index, E);
    node_out_kernel<<<(N + 127) / 128, 128>>>(node_attr, W_out0, W_out1, out, N);
}

// round 14
// speedup vs baseline: 1.9297x; 1.0909x over previous
#include <cuda_runtime.h>
#include <cstdint>
#include <cstddef>

#define MAXN 10000
#define MAXE 160000
#define NSM  148

__device__ float g_x0[MAXN * 16];
__device__ float g_x1[MAXN * 12];
__device__ float g_qd0[MAXN * 8];
__device__ float g_qd1[MAXN * 6];
__device__ float g_logit[MAXE];
__device__ float g_v[MAXE * 28];       // SoA: [j*E + e]
__device__ float g_m[MAXN];
__device__ float g_z[MAXN];
__device__ float g_agg[MAXN * 28];     // AoS
__device__ float g_h2k[(size_t)MAXE * 64];   // TRANSPOSED: [c*E + e]
__device__ float g_h2v[(size_t)MAXE * 64];   // TRANSPOSED: [c*E + e]
__device__ float g_eg[(size_t)MAXE * 32];    // SoA [j*E+e]: 0-15 xl0, 16-19 ul1, 20-31 xl1
__device__ float g_qg[(size_t)MAXE * 14];    // SoA [j*E+e]: 0-7 qd0[dst], 8-13 qd1[dst]

__device__ __forceinline__ float frelu(float x) { return x > 0.f ? x : 0.f; }

__device__ __forceinline__ void atomicMaxF(float* addr, float v) {
    if (v >= 0.f) atomicMax((int*)addr, __float_as_int(v));
    else          atomicMin((unsigned int*)addr, __float_as_uint(v));
}

// ---- tf32 helpers ----------------------------------------------------------
__device__ __forceinline__ float to_tf32(float x) {
    uint32_t u; asm("cvt.rna.tf32.f32 %0, %1;" : "=r"(u) : "f"(x));
    return __uint_as_float(u);
}
__device__ __forceinline__ void mma_tf32(float* d, const uint32_t* a,
                                         const uint32_t* b) {
    asm volatile(
        "mma.sync.aligned.m16n8k8.row.col.f32.tf32.tf32.f32 "
        "{%0,%1,%2,%3}, {%4,%5,%6,%7}, {%8,%9}, {%0,%1,%2,%3};\n"
        : "+f"(d[0]), "+f"(d[1]), "+f"(d[2]), "+f"(d[3])
        : "r"(a[0]), "r"(a[1]), "r"(a[2]), "r"(a[3]), "r"(b[0]), "r"(b[1]));
}

// ---------------------------------------------------------------------------
// Kernel A: node prep
// ---------------------------------------------------------------------------
__global__ void node_prep_kernel(const float* __restrict__ na,
                                 const float* __restrict__ Win0,
                                 const float* __restrict__ Win1,
                                 const float* __restrict__ Wq0,
                                 const float* __restrict__ Wq1,
                                 const float* __restrict__ Wd0,
                                 const float* __restrict__ Wd1,
                                 int N) {
    __shared__ float sWin0[512], sWin1[32], sWq0[128], sWq1[8], sWd0[64], sWd1[4];
    int tid = threadIdx.x;
    for (int i = tid; i < 512; i += blockDim.x) sWin0[i] = Win0[i];
    for (int i = tid; i < 32;  i += blockDim.x) sWin1[i] = Win1[i];
    for (int i = tid; i < 128; i += blockDim.x) sWq0[i]  = Wq0[i];
    for (int i = tid; i < 8;   i += blockDim.x) sWq1[i]  = Wq1[i];
    for (int i = tid; i < 64;  i += blockDim.x) sWd0[i]  = Wd0[i];
    for (int i = tid; i < 4;   i += blockDim.x) sWd1[i]  = Wd1[i];
    __syncthreads();

    int n = blockIdx.x * blockDim.x + tid;
    if (n >= N) return;

    const float* p = na + (size_t)n * 56;
    float a0[32], a1[24];
#pragma unroll
    for (int i = 0; i < 32; i++) a0[i] = p[i];
#pragma unroll
    for (int i = 0; i < 24; i++) a1[i] = p[32 + i];

    float x0[16];
#pragma unroll
    for (int o = 0; o < 16; o++) {
        float s = 0.f;
#pragma unroll
        for (int i = 0; i < 32; i++) s = fmaf(a0[i], sWin0[i * 16 + o], s);
        x0[o] = s * 0.17677669529663687f;   // 1/sqrt(32)
    }
    float x1[12];
#pragma unroll
    for (int o = 0; o < 4; o++)
#pragma unroll
        for (int c = 0; c < 3; c++) {
            float s = 0.f;
#pragma unroll
            for (int m = 0; m < 8; m++) s = fmaf(a1[m * 3 + c], sWin1[m * 4 + o], s);
            x1[o * 3 + c] = s * 0.35355339059327373f;  // 1/sqrt(8)
        }

    float q0[8];
#pragma unroll
    for (int b = 0; b < 8; b++) {
        float s = 0.f;
#pragma unroll
        for (int o = 0; o < 16; o++) s = fmaf(x0[o], sWq0[o * 8 + b], s);
        q0[b] = s * 0.25f;                   // 1/sqrt(16)
    }
    float q1[6];
#pragma unroll
    for (int j = 0; j < 2; j++)
#pragma unroll
        for (int c = 0; c < 3; c++) {
            float s = 0.f;
#pragma unroll
            for (int o = 0; o < 4; o++) s = fmaf(x1[o * 3 + c], sWq1[o * 2 + j], s);
            q1[j * 3 + c] = s * 0.5f;        // 1/sqrt(4)
        }

#pragma unroll
    for (int j = 0; j < 8; j++) {
        float s = 0.f;
#pragma unroll
        for (int i = 0; i < 8; i++) s = fmaf(q0[i], sWd0[i * 8 + j], s);
        g_qd0[(size_t)n * 8 + j] = s;
    }
#pragma unroll
    for (int j = 0; j < 2; j++)
#pragma unroll
        for (int c = 0; c < 3; c++) {
            float s = 0.f;
#pragma unroll
            for (int i = 0; i < 2; i++) s = fmaf(q1[i * 3 + c], sWd1[i * 2 + j], s);
            g_qd1[(size_t)n * 6 + j * 3 + c] = s;
        }

#pragma unroll
    for (int o = 0; o < 16; o++) g_x0[(size_t)n * 16 + o] = x0[o];
#pragma unroll
    for (int o = 0; o < 12; o++) g_x1[(size_t)n * 12 + o] = x1[o];
}

// ---------------------------------------------------------------------------
__global__ void init_kernel(int N) {
    int i = blockIdx.x * blockDim.x + threadIdx.x;
    if (i < N * 28) g_agg[i] = 0.f;
    if (i < N) {
        g_m[i] = __int_as_float(0xff800000);  // -inf
        g_z[i] = 0.f;
    }
}

// ---------------------------------------------------------------------------
// EDGE GATHER: scatter-gather per-edge operands ONCE into SoA staging.
// ---------------------------------------------------------------------------
__global__ void edge_gather_kernel(const float* __restrict__ edge_sh,
                                   const int* __restrict__ eidx, int E) {
    int e = blockIdx.x * blockDim.x + threadIdx.x;
    if (e >= E) return;
    int s = eidx[e], d = eidx[E + e];
    float4 sh = reinterpret_cast<const float4*>(edge_sh)[e];

#pragma unroll
    for (int o = 0; o < 16; o++)
        g_eg[(size_t)o * E + e] = g_x0[(size_t)s * 16 + o];
    float x1[12];
#pragma unroll
    for (int o = 0; o < 12; o++) {
        x1[o] = g_x1[(size_t)s * 12 + o];
        g_eg[(size_t)(20 + o) * E + e] = x1[o];
    }
#pragma unroll
    for (int j = 0; j < 4; j++)
        g_eg[(size_t)(16 + j) * E + e] =
            x1[j * 3] * sh.y + x1[j * 3 + 1] * sh.z + x1[j * 3 + 2] * sh.w;
#pragma unroll
    for (int j = 0; j < 8; j++)
        g_qg[(size_t)j * E + e] = g_qd0[(size_t)d * 8 + j];
#pragma unroll
    for (int j = 0; j < 6; j++)
        g_qg[(size_t)(8 + j) * E + e] = g_qd1[(size_t)d * 6 + j];
}

// ---------------------------------------------------------------------------
// FRONT kernel (tensor-core): both MLPs 32->64->64, tiles of 128 edges.
// smem layout (floats):
//   B1K[32][68]@0  B2K[64][68]@2176  B1V@6528  B2V@8704
//   b1K@13056 b2K@13120 b1V@13184 b2V@13248
//   A0[32][132]@13312  A1[64][132]@17536  C[64][132]@25984
// ---------------------------------------------------------------------------
#define FT_BP 68
#define FT_AP 132
#define FT_B1K 0
#define FT_B2K 2176
#define FT_B1V 6528
#define FT_B2V 8704
#define FT_b1K 13056
#define FT_b2K 13120
#define FT_b1V 13184
#define FT_b2V 13248
#define FT_A0  13312
#define FT_A1  17536
#define FT_C   25984
#define FT_FLOATS 34432

// GEMM 128e x 64n, K = 8*KSTEPS. Fragments validated in R13.
// TO_A1: write tf32(relu(bias+acc)) into A1 (stride FT_AP); else raw to C.
template <int KSTEPS, bool TO_A1>
__device__ __forceinline__ void ft_gemm(const float* __restrict__ As,
                                        const float* __restrict__ Bs,
                                        const float* __restrict__ bias,
                                        float* __restrict__ dst, int tid) {
    int warp = tid >> 5, lane = tid & 31;
    int g = lane >> 2, tc = lane & 3;
    int e0 = warp * 16;

    float acc[8][4];
#pragma unroll
    for (int n = 0; n < 8; n++)
#pragma unroll
        for (int i = 0; i < 4; i++) acc[n][i] = 0.f;

#pragma unroll
    for (int ks = 0; ks < KSTEPS; ks++) {
        int k0 = ks * 8;
        uint32_t a[4];
        a[0] = __float_as_uint(As[(k0 + tc)     * FT_AP + e0 + g]);
        a[1] = __float_as_uint(As[(k0 + tc)     * FT_AP + e0 + g + 8]);
        a[2] = __float_as_uint(As[(k0 + tc + 4) * FT_AP + e0 + g]);
        a[3] = __float_as_uint(As[(k0 + tc + 4) * FT_AP + e0 + g + 8]);
#pragma unroll
        for (int n = 0; n < 8; n++) {
            uint32_t b[2];
            b[0] = __float_as_uint(Bs[(k0 + tc)     * FT_BP + n * 8 + g]);
            b[1] = __float_as_uint(Bs[(k0 + tc + 4) * FT_BP + n * 8 + g]);
            mma_tf32(acc[n], a, b);
        }
    }
#pragma unroll
    for (int n = 0; n < 8; n++) {
        int w0 = n * 8 + 2 * tc;
        if (TO_A1) {
            float b0 = bias[w0], b1 = bias[w0 + 1];
            dst[w0 * FT_AP + e0 + g]           = to_tf32(frelu(b0 + acc[n][0]));
            dst[(w0 + 1) * FT_AP + e0 + g]     = to_tf32(frelu(b1 + acc[n][1]));
            dst[w0 * FT_AP + e0 + g + 8]       = to_tf32(frelu(b0 + acc[n][2]));
            dst[(w0 + 1) * FT_AP + e0 + g + 8] = to_tf32(frelu(b1 + acc[n][3]));
        } else {
            dst[w0 * FT_AP + e0 + g]           = acc[n][0];
            dst[(w0 + 1) * FT_AP + e0 + g]     = acc[n][1];
            dst[w0 * FT_AP + e0 + g + 8]       = acc[n][2];
            dst[(w0 + 1) * FT_AP + e0 + g + 8] = acc[n][3];
        }
    }
}

__device__ __forceinline__ void ft_store_h2(const float* __restrict__ Cs,
                                            const float* __restrict__ bias,
                                            float* __restrict__ gh2,
                                            int e0t, int E, int tid) {
    for (int i = tid; i < 64 * 32; i += 256) {
        int c = i >> 5, v = i & 31;
        int e = e0t + 4 * v;
        float bb = bias[c];
        const float* src = Cs + c * FT_AP + 4 * v;
        if (e + 3 < E) {
            float4 f = *reinterpret_cast<const float4*>(src);
            f.x = frelu(bb + f.x); f.y = frelu(bb + f.y);
            f.z = frelu(bb + f.z); f.w = frelu(bb + f.w);
            *reinterpret_cast<float4*>(gh2 + (size_t)c * E + e) = f;
        } else {
            for (int t = 0; t < 4; t++)
                if (e + t < E) gh2[(size_t)c * E + e + t] = frelu(bb + src[t]);
        }
    }
}

__global__ void __launch_bounds__(256, 1)
front_kernel(const float* __restrict__ edge_attr,
             const float* __restrict__ fcW1, const float* __restrict__ fcb1,
             const float* __restrict__ fcW2, const float* __restrict__ fcb2,
             const float* __restrict__ fkW1, const float* __restrict__ fkb1,
             const float* __restrict__ fkW2, const float* __restrict__ fkb2,
             int E, int tiles) {
    extern __shared__ float sm[];
    int tid = threadIdx.x;

    for (int i = tid; i < 32 * FT_BP; i += 256) {
        int c = i / FT_BP, o = i % FT_BP;
        sm[FT_B1K + i] = (o < 64) ? to_tf32(fkW1[c * 64 + o]) : 0.f;
        sm[FT_B1V + i] = (o < 64) ? to_tf32(fcW1[c * 64 + o]) : 0.f;
    }
    for (int i = tid; i < 64 * FT_BP; i += 256) {
        int c = i / FT_BP, o = i % FT_BP;
        sm[FT_B2K + i] = (o < 64) ? to_tf32(fkW2[c * 64 + o]) : 0.f;
        sm[FT_B2V + i] = (o < 64) ? to_tf32(fcW2[c * 64 + o]) : 0.f;
    }
    for (int i = tid; i < 64; i += 256) {
        sm[FT_b1K + i] = fkb1[i];
        sm[FT_b2K + i] = fkb2[i];
        sm[FT_b1V + i] = fcb1[i];
        sm[FT_b2V + i] = fcb2[i];
    }
    __syncthreads();

    for (int tile = blockIdx.x; tile < tiles; tile += gridDim.x) {
        int e0t = tile * 128;
        // load A0: transpose edge_attr[e][c] -> A0[c][e], tf32
        for (int i = tid; i < 128 * 8; i += 256) {
            int e = i >> 3, q = i & 3;
            // two float4 per 8-chunk: re-derive: i covers (e, q8) with q8<8
            int q8 = i & 7; e = i >> 3;
            float4 v;
            if (e0t + e < E)
                v = *reinterpret_cast<const float4*>(
                        edge_attr + (size_t)(e0t + e) * 32 + 4 * q8);
            else { v.x = v.y = v.z = v.w = 0.f; }
            sm[FT_A0 + (4 * q8 + 0) * FT_AP + e] = to_tf32(v.x);
            sm[FT_A0 + (4 * q8 + 1) * FT_AP + e] = to_tf32(v.y);
            sm[FT_A0 + (4 * q8 + 2) * FT_AP + e] = to_tf32(v.z);
            sm[FT_A0 + (4 * q8 + 3) * FT_AP + e] = to_tf32(v.w);
            (void)q;
        }
        __syncthreads();
        // K MLP
        ft_gemm<4, true>(sm + FT_A0, sm + FT_B1K, sm + FT_b1K, sm + FT_A1, tid);
        __syncthreads();
        ft_gemm<8, false>(sm + FT_A1, sm + FT_B2K, nullptr, sm + FT_C, tid);
        __syncthreads();
        ft_store_h2(sm + FT_C, sm + FT_b2K, g_h2k, e0t, E, tid);
        // V MLP layer1 (A1 free after K layer2 read; C being read by store,
        // not touched by this GEMM)
        ft_gemm<4, true>(sm + FT_A0, sm + FT_B1V, sm + FT_b1V, sm + FT_A1, tid);
        __syncthreads();   // store-C reads done; A1 writes visible
        ft_gemm<8, false>(sm + FT_A1, sm + FT_B2V, nullptr, sm + FT_C, tid);
        __syncthreads();
        ft_store_h2(sm + FT_C, sm + FT_b2V, g_h2v, e0t, E, tid);
        __syncthreads();   // protect A0/C before next tile
    }
}

// ---------------------------------------------------------------------------
// L3 tensor-core GEMM machinery (persistent tiles of 128 edges)
// smem floats: B 64*228 | A 64*132 | C 224*132 | bias 224
// ---------------------------------------------------------------------------
#define TE     128
#define NWP    224
#define APAD   132
#define BPAD   228
#define CPAD   132
#define L3_B_OFF    0
#define L3_A_OFF    14592
#define L3_C_OFF    23040
#define L3_BIAS_OFF 52608
#define L3_FLOATS   52832

__device__ __forceinline__ void l3_load_A(float* __restrict__ As,
                                          const float* __restrict__ gh2T,
                                          int e0, int E, int tid) {
    for (int i = tid; i < 64 * (TE / 4); i += 256) {
        int c = i >> 5;
        int v = i & 31;
        int eb = e0 + 4 * v;
        float4 f;
        if (eb + 3 < E) {
            f = *reinterpret_cast<const float4*>(gh2T + (size_t)c * E + eb);
        } else {
            f.x = (eb + 0 < E) ? gh2T[(size_t)c * E + eb + 0] : 0.f;
            f.y = (eb + 1 < E) ? gh2T[(size_t)c * E + eb + 1] : 0.f;
            f.z = (eb + 2 < E) ? gh2T[(size_t)c * E + eb + 2] : 0.f;
            f.w = (eb + 3 < E) ? gh2T[(size_t)c * E + eb + 3] : 0.f;
        }
        f.x = to_tf32(f.x); f.y = to_tf32(f.y);
        f.z = to_tf32(f.z); f.w = to_tf32(f.w);
        *reinterpret_cast<float4*>(As + c * APAD + 4 * v) = f;
    }
}

__device__ __forceinline__ void l3_gemm_mma(const float* __restrict__ As,
                                            const float* __restrict__ Bs,
                                            float* __restrict__ Cs, int tid) {
    int warp = tid >> 5, lane = tid & 31;
    int g = lane >> 2, tc = lane & 3;
    int e0 = warp * 16;

    float acc[28][4];
#pragma unroll
    for (int n = 0; n < 28; n++)
#pragma unroll
        for (int i = 0; i < 4; i++) acc[n][i] = 0.f;

#pragma unroll
    for (int k0 = 0; k0 < 64; k0 += 8) {
        uint32_t a[4];
        a[0] = __float_as_uint(As[(k0 + tc)     * APAD + e0 + g]);
        a[1] = __float_as_uint(As[(k0 + tc)     * APAD + e0 + g + 8]);
        a[2] = __float_as_uint(As[(k0 + tc + 4) * APAD + e0 + g]);
        a[3] = __float_as_uint(As[(k0 + tc + 4) * APAD + e0 + g + 8]);
#pragma unroll
        for (int n = 0; n < 28; n++) {
            uint32_t b[2];
            b[0] = __float_as_uint(Bs[(k0 + tc)     * BPAD + n * 8 + g]);
            b[1] = __float_as_uint(Bs[(k0 + tc + 4) * BPAD + n * 8 + g]);
            mma_tf32(acc[n], a, b);
        }
    }
#pragma unroll
    for (int n = 0; n < 28; n++) {
        int w0 = n * 8 + 2 * tc;
        Cs[w0 * CPAD + e0 + g]           = acc[n][0];
        Cs[(w0 + 1) * CPAD + e0 + g]     = acc[n][1];
        Cs[w0 * CPAD + e0 + g + 8]       = acc[n][2];
        Cs[(w0 + 1) * CPAD + e0 + g + 8] = acc[n][3];
    }
}

// ---------------------------------------------------------------------------
// L3K: persistent tensor GEMM + K contraction (staged operands) + logit
// ---------------------------------------------------------------------------
__global__ void __launch_bounds__(256, 1)
l3k_kernel(const int* __restrict__ eidx,
           const float* __restrict__ edge_sh,
           const float* __restrict__ fkW3, const float* __restrict__ fkb3,
           int E, int tiles) {
    extern __shared__ float smx[];
    float* Bs  = smx + L3_B_OFF;
    float* As  = smx + L3_A_OFF;
    float* Cs  = smx + L3_C_OFF;
    float* sB3 = smx + L3_BIAS_OFF;
    int tid = threadIdx.x;

    for (int i = tid; i < 64 * BPAD; i += 256) {
        int c = i / BPAD, w = i % BPAD;
        Bs[i] = (w < 200) ? to_tf32(fkW3[c * 200 + w]) : 0.f;
    }
    for (int i = tid; i < NWP; i += 256)
        sB3[i] = (i < 200) ? fkb3[i] : 0.f;

    const float NORM = 0.22360679774997896f;  // 1/sqrt(20)
    const float I3   = 0.5773502691896258f;   // 1/sqrt(3)

    for (int tile = blockIdx.x; tile < tiles; tile += gridDim.x) {
        int e0 = tile * TE;
        l3_load_A(As, g_h2k, e0, E, tid);
        __syncthreads();
        l3_gemm_mma(As, Bs, Cs, tid);
        __syncthreads();

        {
            int el = tid >> 1;
            int h  = tid & 1;
            int e  = e0 + el;
            int ee = (e < E) ? e : (E - 1);
            int d = eidx[E + ee];
            float4 sh = reinterpret_cast<const float4*>(edge_sh)[ee];

            float xl0[16], ul1[4];
#pragma unroll
            for (int o = 0; o < 16; o++) xl0[o] = g_eg[(size_t)o * E + ee];
#pragma unroll
            for (int j = 0; j < 4; j++) ul1[j] = g_eg[(size_t)(16 + j) * E + ee];

            float logit = 0.f;
#pragma unroll
            for (int bb = 0; bb < 4; bb++) {
                int b = 4 * h + bb;
                float acc0 = 0.f;
#pragma unroll
                for (int a = 0; a < 16; a++) {
                    int r = a * 8 + b;
                    acc0 = fmaf(xl0[a], Cs[r * CPAD + el] + sB3[r], acc0);
                }
                float acc1 = 0.f;
#pragma unroll
                for (int a = 0; a < 4; a++) {
                    int r = 168 + a * 8 + b;
                    acc1 = fmaf(ul1[a], Cs[r * CPAD + el] + sB3[r], acc1);
                }
                float k0b = NORM * fmaf(sh.x, acc0, I3 * acc1);
                logit = fmaf(g_qg[(size_t)b * E + ee], k0b, logit);
            }
            {
                int j = h;
                float c01 = 0.f;
#pragma unroll
                for (int a = 0; a < 16; a++) {
                    int r = 128 + a * 2 + j;
                    c01 = fmaf(xl0[a], Cs[r * CPAD + el] + sB3[r], c01);
                }
                float dx = 0.f, dy = 0.f, dz = 0.f;
#pragma unroll
                for (int a = 0; a < 4; a++) {
                    int r = 160 + a * 2 + j;
                    float w = Cs[r * CPAD + el] + sB3[r];
                    dx = fmaf(g_eg[(size_t)(20 + a * 3 + 0) * E + ee], w, dx);
                    dy = fmaf(g_eg[(size_t)(20 + a * 3 + 1) * E + ee], w, dy);
                    dz = fmaf(g_eg[(size_t)(20 + a * 3 + 2) * E + ee], w, dz);
                }
                float k1x = NORM * (sh.y * c01 + sh.x * dx);
                float k1y = NORM * (sh.z * c01 + sh.x * dy);
                float k1z = NORM * (sh.w * c01 + sh.x * dz);
                logit += I3 * (g_qg[(size_t)(8 + j * 3 + 0) * E + ee] * k1x +
                               g_qg[(size_t)(8 + j * 3 + 1) * E + ee] * k1y +
                               g_qg[(size_t)(8 + j * 3 + 2) * E + ee] * k1z);
            }
            logit += __shfl_xor_sync(0xffffffffu, logit, 1);
            logit *= 0.31622776601683794f;  // 1/sqrt(10)
            if (h == 0 && e < E) {
                g_logit[e] = logit;
                atomicMaxF(&g_m[d], logit);
            }
        }
        __syncthreads();
    }
}

// ---------------------------------------------------------------------------
// L3V (HALF = 0/1): persistent tensor GEMM + V contraction, half outputs
// ---------------------------------------------------------------------------
template <int HALF>
__device__ __forceinline__ int v_wi(int r) {
    if (r < 128) { int a = r >> 3, b = r & 7;        return a * 16 + HALF * 8 + b; }
    if (r < 160) { int t = r - 128; int a = t >> 1;  return 256 + a * 4 + HALF * 2 + (t & 1); }
    if (r < 168) { int t = r - 160; int a = t >> 1;  return 320 + a * 4 + HALF * 2 + (t & 1); }
    { int t = r - 168; int a = t >> 3, b = t & 7;    return 336 + a * 16 + HALF * 8 + b; }
}

template <int HALF>
__global__ void __launch_bounds__(256, 1)
l3v_kernel(const float* __restrict__ edge_sh,
           const float* __restrict__ fcW3, const float* __restrict__ fcb3,
           int E, int tiles) {
    extern __shared__ float smx[];
    float* Bs  = smx + L3_B_OFF;
    float* As  = smx + L3_A_OFF;
    float* Cs  = smx + L3_C_OFF;
    float* sB3 = smx + L3_BIAS_OFF;
    int tid = threadIdx.x;

    for (int i = tid; i < 64 * BPAD; i += 256) {
        int c = i / BPAD, w = i % BPAD;
        Bs[i] = (w < 200) ? to_tf32(fcW3[c * 400 + v_wi<HALF>(w)]) : 0.f;
    }
    for (int i = tid; i < NWP; i += 256)
        sB3[i] = (i < 200) ? fcb3[v_wi<HALF>(i)] : 0.f;

    const float NORM = 0.22360679774997896f;  // 1/sqrt(20)
    const float I3   = 0.5773502691896258f;   // 1/sqrt(3)

    for (int tile = blockIdx.x; tile < tiles; tile += gridDim.x) {
        int e0 = tile * TE;
        l3_load_A(As, g_h2v, e0, E, tid);
        __syncthreads();
        l3_gemm_mma(As, Bs, Cs, tid);
        __syncthreads();

        {
            int el = tid >> 1;
            int h  = tid & 1;
            int e  = e0 + el;
            bool ok = e < E;
            int ee = ok ? e : (E - 1);
            float4 sh = reinterpret_cast<const float4*>(edge_sh)[ee];

            float xl0[16], ul1[4];
#pragma unroll
            for (int o = 0; o < 16; o++) xl0[o] = g_eg[(size_t)o * E + ee];
#pragma unroll
            for (int j = 0; j < 4; j++) ul1[j] = g_eg[(size_t)(16 + j) * E + ee];

#pragma unroll
            for (int bb = 0; bb < 4; bb++) {
                int b = 4 * h + bb;
                float acc0 = 0.f;
#pragma unroll
                for (int a = 0; a < 16; a++) {
                    int r = a * 8 + b;
                    acc0 = fmaf(xl0[a], Cs[r * CPAD + el] + sB3[r], acc0);
                }
                float acc1 = 0.f;
#pragma unroll
                for (int a = 0; a < 4; a++) {
                    int r = 168 + a * 8 + b;
                    acc1 = fmaf(ul1[a], Cs[r * CPAD + el] + sB3[r], acc1);
                }
                int bg = HALF * 8 + b;
                if (ok) g_v[(size_t)bg * E + e] = NORM * fmaf(sh.x, acc0, I3 * acc1);
            }
            {
                int j = h;
                float c01 = 0.f;
#pragma unroll
                for (int a = 0; a < 16; a++) {
                    int r = 128 + a * 2 + j;
                    c01 = fmaf(xl0[a], Cs[r * CPAD + el] + sB3[r], c01);
                }
                float dx = 0.f, dy = 0.f, dz = 0.f;
#pragma unroll
                for (int a = 0; a < 4; a++) {
                    int r = 160 + a * 2 + j;
                    float w = Cs[r * CPAD + el] + sB3[r];
                    dx = fmaf(g_eg[(size_t)(20 + a * 3 + 0) * E + ee], w, dx);
                    dy = fmaf(g_eg[(size_t)(20 + a * 3 + 1) * E + ee], w, dy);
                    dz = fmaf(g_eg[(size_t)(20 + a * 3 + 2) * E + ee], w, dz);
                }
                int jg = HALF * 2 + j;
                if (ok) {
                    g_v[(size_t)(16 + jg * 3 + 0) * E + e] = NORM * (sh.y * c01 + sh.x * dx);
                    g_v[(size_t)(16 + jg * 3 + 1) * E + e] = NORM * (sh.z * c01 + sh.x * dy);
                    g_v[(size_t)(16 + jg * 3 + 2) * E + e] = NORM * (sh.w * c01 + sh.x * dz);
                }
            }
        }
        __syncthreads();
    }
}

// ---------------------------------------------------------------------------
// softmax+aggregate: 4 threads per edge (7 channels each)
// ---------------------------------------------------------------------------
__global__ void softmax_agg_kernel(const int* __restrict__ eidx, int E) {
    int t = blockIdx.x * blockDim.x + threadIdx.x;
    int e = t >> 2;
    int q = t & 3;
    if (e >= E) return;
    int d = eidx[E + e];
    float p = __expf(g_logit[e] - g_m[d]);
    if (q == 0) atomicAdd(&g_z[d], p);
#pragma unroll
    for (int jj = 0; jj < 7; jj++) {
        int j = q * 7 + jj;
        atomicAdd(&g_agg[(size_t)d * 28 + j], p * g_v[(size_t)j * E + e]);
    }
}

// ---------------------------------------------------------------------------
__global__ void node_out_kernel(const float* __restrict__ na,
                                const float* __restrict__ Wo0,
                                const float* __restrict__ Wo1,
                                float* __restrict__ out, int N) {
    __shared__ float sW0[512], sW1[32];
    int tid = threadIdx.x;
    for (int i = tid; i < 512; i += blockDim.x) sW0[i] = Wo0[i];
    for (int i = tid; i < 32;  i += blockDim.x) sW1[i] = Wo1[i];
    __syncthreads();

    int n = blockIdx.x * blockDim.x + tid;
    if (n >= N) return;
    float z = g_z[n];
    float zi = z > 0.f ? 1.f / z : 0.f;
    float ag[28];
#pragma unroll
    for (int j = 0; j < 28; j++) ag[j] = g_agg[(size_t)n * 28 + j] * zi;

#pragma unroll
    for (int o = 0; o < 32; o++) {
        float s = 0.f;
#pragma unroll
        for (int a = 0; a < 16; a++) s = fmaf(ag[a], sW0[a * 32 + o], s);
        out[(size_t)n * 56 + o] = fmaf(s, 0.25f, na[(size_t)n * 56 + o]);
    }
#pragma unroll
    for (int o = 0; o < 8; o++)
#pragma unroll
        for (int c = 0; c < 3; c++) {
            float s = 0.f;
#pragma unroll
            for (int a = 0; a < 4; a++) s = fmaf(ag[16 + a * 3 + c], sW1[a * 8 + o], s);
            out[(size_t)n * 56 + 32 + o * 3 + c] =
                fmaf(s, 0.5f, na[(size_t)n * 56 + 32 + o * 3 + c]);
        }
}

// ---------------------------------------------------------------------------
extern "C" void kernel_launch(void* const* d_in, const int* in_sizes, int n_in,
                              void* d_out, int out_size) {
    const float* node_attr  = (const float*)d_in[0];
    const float* edge_attr  = (const float*)d_in[1];
    const float* edge_sh    = (const float*)d_in[2];
    const int*   edge_index = (const int*)  d_in[3];
    const float* W_in0  = (const float*)d_in[4];
    const float* W_in1  = (const float*)d_in[5];
    const float* Wq0    = (const float*)d_in[6];
    const float* Wq1    = (const float*)d_in[7];
    const float* Wd0    = (const float*)d_in[8];
    const float* Wd1    = (const float*)d_in[9];
    const float* W_out0 = (const float*)d_in[10];
    const float* W_out1 = (const float*)d_in[11];
    const float* fcW1 = (const float*)d_in[12];
    const float* fcb1 = (const float*)d_in[13];
    const float* fcW2 = (const float*)d_in[14];
    const float* fcb2 = (const float*)d_in[15];
    const float* fcW3 = (const float*)d_in[16];
    const float* fcb3 = (const float*)d_in[17];
    const float* fkW1 = (const float*)d_in[18];
    const float* fkb1 = (const float*)d_in[19];
    const float* fkW2 = (const float*)d_in[20];
    const float* fkb2 = (const float*)d_in[21];
    const float* fkW3 = (const float*)d_in[22];
    const float* fkb3 = (const float*)d_in[23];
    float* out = (float*)d_out;

    int N = in_sizes[0] / 56;
    int E = in_sizes[2] / 4;

    const int FRONT_SMEM = FT_FLOATS * (int)sizeof(float);  // 137728 B
    const int L3_SMEM    = L3_FLOATS * (int)sizeof(float);  // 211328 B

    cudaFuncSetAttribute(front_kernel,
                         cudaFuncAttributeMaxDynamicSharedMemorySize, FRONT_SMEM);
    cudaFuncSetAttribute(l3k_kernel,
                         cudaFuncAttributeMaxDynamicSharedMemorySize, L3_SMEM);
    cudaFuncSetAttribute(l3v_kernel<0>,
                         cudaFuncAttributeMaxDynamicSharedMemorySize, L3_SMEM);
    cudaFuncSetAttribute(l3v_kernel<1>,
                         cudaFuncAttributeMaxDynamicSharedMemorySize, L3_SMEM);

    int tiles = (E + TE - 1) / TE;

    node_prep_kernel<<<(N + 127) / 128, 128>>>(node_attr, W_in0, W_in1, Wq0, Wq1,
                                               Wd0, Wd1, N);
    init_kernel<<<(N * 28 + 255) / 256, 256>>>(N);
    edge_gather_kernel<<<(E + 255) / 256, 256>>>(edge_sh, edge_index, E);
    front_kernel<<<NSM, 256, FRONT_SMEM>>>(edge_attr,
                                           fcW1, fcb1, fcW2, fcb2,
                                           fkW1, fkb1, fkW2, fkb2, E, tiles);
    l3k_kernel<<<NSM, 256, L3_SMEM>>>(edge_index, edge_sh, fkW3, fkb3, E, tiles);
    l3v_kernel<0><<<NSM, 256, L3_SMEM>>>(edge_sh, fcW3, fcb3, E, tiles);
    l3v_kernel<1><<<NSM, 256, L3_SMEM>>>(edge_sh, fcW3, fcb3, E, tiles);
    softmax_agg_kernel<<<(E * 4 + 255) / 256, 256>>>(edge_index, E);
    node_out_kernel<<<(N + 127) / 128, 128>>>(node_attr, W_out0, W_out1, out, N);
}

// round 15
// speedup vs baseline: 2.2016x; 1.1409x over previous
#include <cuda_runtime.h>
#include <cstdint>
#include <cstddef>

#define MAXN 10000
#define MAXE 160000
#define NSM  148

__device__ float g_x0[MAXN * 16];
__device__ float g_x1[MAXN * 12];
__device__ float g_qd0[MAXN * 8];
__device__ float g_qd1[MAXN * 6];
__device__ float g_logit[MAXE];
__device__ float g_v[MAXE * 28];       // SoA: [j*E + e]
__device__ float g_m[MAXN];
__device__ float g_z[MAXN];
__device__ float g_agg[MAXN * 28];     // AoS
__device__ float g_h2k[(size_t)MAXE * 64];   // TRANSPOSED [c*E+e], pre-tf32
__device__ float g_h2v[(size_t)MAXE * 64];   // TRANSPOSED [c*E+e], pre-tf32
__device__ float g_eg[(size_t)MAXE * 32];    // SoA: 0-15 xl0, 16-19 ul1, 20-31 xl1
__device__ float g_qg[(size_t)MAXE * 14];    // SoA: 0-7 qd0[dst], 8-13 qd1[dst]

__device__ __forceinline__ float frelu(float x) { return x > 0.f ? x : 0.f; }

__device__ __forceinline__ void atomicMaxF(float* addr, float v) {
    if (v >= 0.f) atomicMax((int*)addr, __float_as_int(v));
    else          atomicMin((unsigned int*)addr, __float_as_uint(v));
}

// ---- tf32 helpers ----------------------------------------------------------
__device__ __forceinline__ float to_tf32(float x) {
    uint32_t u; asm("cvt.rna.tf32.f32 %0, %1;" : "=r"(u) : "f"(x));
    return __uint_as_float(u);
}
__device__ __forceinline__ void mma_tf32(float* d, const uint32_t* a,
                                         const uint32_t* b) {
    asm volatile(
        "mma.sync.aligned.m16n8k8.row.col.f32.tf32.tf32.f32 "
        "{%0,%1,%2,%3}, {%4,%5,%6,%7}, {%8,%9}, {%0,%1,%2,%3};\n"
        : "+f"(d[0]), "+f"(d[1]), "+f"(d[2]), "+f"(d[3])
        : "r"(a[0]), "r"(a[1]), "r"(a[2]), "r"(a[3]), "r"(b[0]), "r"(b[1]));
}

// ---------------------------------------------------------------------------
// Kernel A: node prep
// ---------------------------------------------------------------------------
__global__ void node_prep_kernel(const float* __restrict__ na,
                                 const float* __restrict__ Win0,
                                 const float* __restrict__ Win1,
                                 const float* __restrict__ Wq0,
                                 const float* __restrict__ Wq1,
                                 const float* __restrict__ Wd0,
                                 const float* __restrict__ Wd1,
                                 int N) {
    __shared__ float sWin0[512], sWin1[32], sWq0[128], sWq1[8], sWd0[64], sWd1[4];
    int tid = threadIdx.x;
    for (int i = tid; i < 512; i += blockDim.x) sWin0[i] = Win0[i];
    for (int i = tid; i < 32;  i += blockDim.x) sWin1[i] = Win1[i];
    for (int i = tid; i < 128; i += blockDim.x) sWq0[i]  = Wq0[i];
    for (int i = tid; i < 8;   i += blockDim.x) sWq1[i]  = Wq1[i];
    for (int i = tid; i < 64;  i += blockDim.x) sWd0[i]  = Wd0[i];
    for (int i = tid; i < 4;   i += blockDim.x) sWd1[i]  = Wd1[i];
    __syncthreads();

    int n = blockIdx.x * blockDim.x + tid;
    if (n >= N) return;

    const float* p = na + (size_t)n * 56;
    float a0[32], a1[24];
#pragma unroll
    for (int i = 0; i < 32; i++) a0[i] = p[i];
#pragma unroll
    for (int i = 0; i < 24; i++) a1[i] = p[32 + i];

    float x0[16];
#pragma unroll
    for (int o = 0; o < 16; o++) {
        float s = 0.f;
#pragma unroll
        for (int i = 0; i < 32; i++) s = fmaf(a0[i], sWin0[i * 16 + o], s);
        x0[o] = s * 0.17677669529663687f;   // 1/sqrt(32)
    }
    float x1[12];
#pragma unroll
    for (int o = 0; o < 4; o++)
#pragma unroll
        for (int c = 0; c < 3; c++) {
            float s = 0.f;
#pragma unroll
            for (int m = 0; m < 8; m++) s = fmaf(a1[m * 3 + c], sWin1[m * 4 + o], s);
            x1[o * 3 + c] = s * 0.35355339059327373f;  // 1/sqrt(8)
        }

    float q0[8];
#pragma unroll
    for (int b = 0; b < 8; b++) {
        float s = 0.f;
#pragma unroll
        for (int o = 0; o < 16; o++) s = fmaf(x0[o], sWq0[o * 8 + b], s);
        q0[b] = s * 0.25f;                   // 1/sqrt(16)
    }
    float q1[6];
#pragma unroll
    for (int j = 0; j < 2; j++)
#pragma unroll
        for (int c = 0; c < 3; c++) {
            float s = 0.f;
#pragma unroll
            for (int o = 0; o < 4; o++) s = fmaf(x1[o * 3 + c], sWq1[o * 2 + j], s);
            q1[j * 3 + c] = s * 0.5f;        // 1/sqrt(4)
        }

#pragma unroll
    for (int j = 0; j < 8; j++) {
        float s = 0.f;
#pragma unroll
        for (int i = 0; i < 8; i++) s = fmaf(q0[i], sWd0[i * 8 + j], s);
        g_qd0[(size_t)n * 8 + j] = s;
    }
#pragma unroll
    for (int j = 0; j < 2; j++)
#pragma unroll
        for (int c = 0; c < 3; c++) {
            float s = 0.f;
#pragma unroll
            for (int i = 0; i < 2; i++) s = fmaf(q1[i * 3 + c], sWd1[i * 2 + j], s);
            g_qd1[(size_t)n * 6 + j * 3 + c] = s;
        }

#pragma unroll
    for (int o = 0; o < 16; o++) g_x0[(size_t)n * 16 + o] = x0[o];
#pragma unroll
    for (int o = 0; o < 12; o++) g_x1[(size_t)n * 12 + o] = x1[o];
}

// ---------------------------------------------------------------------------
__global__ void init_kernel(int N) {
    int i = blockIdx.x * blockDim.x + threadIdx.x;
    if (i < N * 28) g_agg[i] = 0.f;
    if (i < N) {
        g_m[i] = __int_as_float(0xff800000);  // -inf
        g_z[i] = 0.f;
    }
}

// ---------------------------------------------------------------------------
// EDGE GATHER: scatter-gather per-edge operands ONCE into SoA staging.
// ---------------------------------------------------------------------------
__global__ void edge_gather_kernel(const float* __restrict__ edge_sh,
                                   const int* __restrict__ eidx, int E) {
    int e = blockIdx.x * blockDim.x + threadIdx.x;
    if (e >= E) return;
    int s = eidx[e], d = eidx[E + e];
    float4 sh = reinterpret_cast<const float4*>(edge_sh)[e];

#pragma unroll
    for (int o = 0; o < 16; o++)
        g_eg[(size_t)o * E + e] = g_x0[(size_t)s * 16 + o];
    float x1[12];
#pragma unroll
    for (int o = 0; o < 12; o++) {
        x1[o] = g_x1[(size_t)s * 12 + o];
        g_eg[(size_t)(20 + o) * E + e] = x1[o];
    }
#pragma unroll
    for (int j = 0; j < 4; j++)
        g_eg[(size_t)(16 + j) * E + e] =
            x1[j * 3] * sh.y + x1[j * 3 + 1] * sh.z + x1[j * 3 + 2] * sh.w;
#pragma unroll
    for (int j = 0; j < 8; j++)
        g_qg[(size_t)j * E + e] = g_qd0[(size_t)d * 8 + j];
#pragma unroll
    for (int j = 0; j < 6; j++)
        g_qg[(size_t)(8 + j) * E + e] = g_qd1[(size_t)d * 6 + j];
}

// ---------------------------------------------------------------------------
// FRONT kernel (tensor-core): both MLPs 32->64->64, tiles of 128 edges.
// Layer-2 fragments stored DIRECTLY to global h2 (tf32(relu(bias+acc))).
// smem floats: B1K[32][68] B2K[64][68] B1V B2V | biases | A0[32][132] A1[64][132]
// ---------------------------------------------------------------------------
#define FT_BP 68
#define FT_AP 132
#define FT_B1K 0
#define FT_B2K 2176
#define FT_B1V 6528
#define FT_B2V 8704
#define FT_b1K 13056
#define FT_b2K 13120
#define FT_b1V 13184
#define FT_b2V 13248
#define FT_A0  13312
#define FT_A1  17536
#define FT_FLOATS 25984

// MODE 0: dst = A1 smem, write tf32(relu(bias+acc)).
// MODE 1: dst = global h2 [w*E + e], write tf32(relu(bias+acc)), bounds-check.
template <int KSTEPS, int MODE>
__device__ __forceinline__ void ft_gemm(const float* __restrict__ As,
                                        const float* __restrict__ Bs,
                                        const float* __restrict__ bias,
                                        float* __restrict__ dst,
                                        int tid, int e0t, int E) {
    int warp = tid >> 5, lane = tid & 31;
    int g = lane >> 2, tc = lane & 3;
    int e0 = warp * 16;

    float acc[8][4];
#pragma unroll
    for (int n = 0; n < 8; n++)
#pragma unroll
        for (int i = 0; i < 4; i++) acc[n][i] = 0.f;

#pragma unroll
    for (int ks = 0; ks < KSTEPS; ks++) {
        int k0 = ks * 8;
        uint32_t a[4];
        a[0] = __float_as_uint(As[(k0 + tc)     * FT_AP + e0 + g]);
        a[1] = __float_as_uint(As[(k0 + tc)     * FT_AP + e0 + g + 8]);
        a[2] = __float_as_uint(As[(k0 + tc + 4) * FT_AP + e0 + g]);
        a[3] = __float_as_uint(As[(k0 + tc + 4) * FT_AP + e0 + g + 8]);
#pragma unroll
        for (int n = 0; n < 8; n++) {
            uint32_t b[2];
            b[0] = __float_as_uint(Bs[(k0 + tc)     * FT_BP + n * 8 + g]);
            b[1] = __float_as_uint(Bs[(k0 + tc + 4) * FT_BP + n * 8 + g]);
            mma_tf32(acc[n], a, b);
        }
    }
#pragma unroll
    for (int n = 0; n < 8; n++) {
        int w0 = n * 8 + 2 * tc;
        float b0 = bias[w0], b1 = bias[w0 + 1];
        float v00 = to_tf32(frelu(b0 + acc[n][0]));
        float v10 = to_tf32(frelu(b1 + acc[n][1]));
        float v01 = to_tf32(frelu(b0 + acc[n][2]));
        float v11 = to_tf32(frelu(b1 + acc[n][3]));
        if (MODE == 0) {
            dst[w0 * FT_AP + e0 + g]           = v00;
            dst[(w0 + 1) * FT_AP + e0 + g]     = v10;
            dst[w0 * FT_AP + e0 + g + 8]       = v01;
            dst[(w0 + 1) * FT_AP + e0 + g + 8] = v11;
        } else {
            int ea = e0t + e0 + g;
            int eb = ea + 8;
            if (ea < E) {
                dst[(size_t)w0 * E + ea]       = v00;
                dst[(size_t)(w0 + 1) * E + ea] = v10;
            }
            if (eb < E) {
                dst[(size_t)w0 * E + eb]       = v01;
                dst[(size_t)(w0 + 1) * E + eb] = v11;
            }
        }
    }
}

__global__ void __launch_bounds__(256, 2)
front_kernel(const float* __restrict__ edge_attr,
             const float* __restrict__ fcW1, const float* __restrict__ fcb1,
             const float* __restrict__ fcW2, const float* __restrict__ fcb2,
             const float* __restrict__ fkW1, const float* __restrict__ fkb1,
             const float* __restrict__ fkW2, const float* __restrict__ fkb2,
             int E, int tiles) {
    extern __shared__ float sm[];
    int tid = threadIdx.x;

    for (int i = tid; i < 32 * FT_BP; i += 256) {
        int c = i / FT_BP, o = i % FT_BP;
        sm[FT_B1K + i] = (o < 64) ? to_tf32(fkW1[c * 64 + o]) : 0.f;
        sm[FT_B1V + i] = (o < 64) ? to_tf32(fcW1[c * 64 + o]) : 0.f;
    }
    for (int i = tid; i < 64 * FT_BP; i += 256) {
        int c = i / FT_BP, o = i % FT_BP;
        sm[FT_B2K + i] = (o < 64) ? to_tf32(fkW2[c * 64 + o]) : 0.f;
        sm[FT_B2V + i] = (o < 64) ? to_tf32(fcW2[c * 64 + o]) : 0.f;
    }
    for (int i = tid; i < 64; i += 256) {
        sm[FT_b1K + i] = fkb1[i];
        sm[FT_b2K + i] = fkb2[i];
        sm[FT_b1V + i] = fcb1[i];
        sm[FT_b2V + i] = fcb2[i];
    }
    __syncthreads();

    for (int tile = blockIdx.x; tile < tiles; tile += gridDim.x) {
        int e0t = tile * 128;
        // load A0: transpose edge_attr[e][c] -> A0[c][e], tf32
        for (int i = tid; i < 128 * 8; i += 256) {
            int e = i >> 3, q8 = i & 7;
            float4 v;
            if (e0t + e < E)
                v = *reinterpret_cast<const float4*>(
                        edge_attr + (size_t)(e0t + e) * 32 + 4 * q8);
            else { v.x = v.y = v.z = v.w = 0.f; }
            sm[FT_A0 + (4 * q8 + 0) * FT_AP + e] = to_tf32(v.x);
            sm[FT_A0 + (4 * q8 + 1) * FT_AP + e] = to_tf32(v.y);
            sm[FT_A0 + (4 * q8 + 2) * FT_AP + e] = to_tf32(v.z);
            sm[FT_A0 + (4 * q8 + 3) * FT_AP + e] = to_tf32(v.w);
        }
        __syncthreads();
        // K MLP
        ft_gemm<4, 0>(sm + FT_A0, sm + FT_B1K, sm + FT_b1K, sm + FT_A1, tid, 0, 0);
        __syncthreads();
        ft_gemm<8, 1>(sm + FT_A1, sm + FT_B2K, sm + FT_b2K, g_h2k, tid, e0t, E);
        __syncthreads();   // A1 reuse
        // V MLP
        ft_gemm<4, 0>(sm + FT_A0, sm + FT_B1V, sm + FT_b1V, sm + FT_A1, tid, 0, 0);
        __syncthreads();
        ft_gemm<8, 1>(sm + FT_A1, sm + FT_B2V, sm + FT_b2V, g_h2v, tid, e0t, E);
        // next-tile A0 load is safe (gemm1V reads completed before prior bar);
        // bar after A0 load protects A1 against next gemm1K.
    }
}

// ---------------------------------------------------------------------------
// L3 tensor-core GEMM machinery (persistent tiles of 128 edges, 512 threads)
//   16 warps: warp-group 0 computes n 0-13, group 1 n 14-27; warp&7 -> edges.
// smem floats: B 64*228 | A 64*132 | C 224*132 | bias 224
// ---------------------------------------------------------------------------
#define TE     128
#define NWP    224
#define APAD   132
#define BPAD   228
#define CPAD   132
#define L3_B_OFF    0
#define L3_A_OFF    14592
#define L3_C_OFF    23040
#define L3_BIAS_OFF 52608
#define L3_FLOATS   52832
#define L3_NT  512

__device__ __forceinline__ void l3_load_A(float* __restrict__ As,
                                          const float* __restrict__ gh2T,
                                          int e0, int E, int tid) {
    // h2 already tf32-rounded by the front kernel
    for (int i = tid; i < 64 * (TE / 4); i += L3_NT) {
        int c = i >> 5;
        int v = i & 31;
        int eb = e0 + 4 * v;
        float4 f;
        if (eb + 3 < E) {
            f = *reinterpret_cast<const float4*>(gh2T + (size_t)c * E + eb);
        } else {
            f.x = (eb + 0 < E) ? gh2T[(size_t)c * E + eb + 0] : 0.f;
            f.y = (eb + 1 < E) ? gh2T[(size_t)c * E + eb + 1] : 0.f;
            f.z = (eb + 2 < E) ? gh2T[(size_t)c * E + eb + 2] : 0.f;
            f.w = (eb + 3 < E) ? gh2T[(size_t)c * E + eb + 3] : 0.f;
        }
        *reinterpret_cast<float4*>(As + c * APAD + 4 * v) = f;
    }
}

__device__ __forceinline__ void l3_gemm_mma(const float* __restrict__ As,
                                            const float* __restrict__ Bs,
                                            float* __restrict__ Cs, int tid) {
    int warp = tid >> 5, lane = tid & 31;
    int g = lane >> 2, tc = lane & 3;
    int wg = warp >> 3;          // 0: n 0-13, 1: n 14-27
    int e0 = (warp & 7) * 16;
    int n0 = wg * 14;

    float acc[14][4];
#pragma unroll
    for (int n = 0; n < 14; n++)
#pragma unroll
        for (int i = 0; i < 4; i++) acc[n][i] = 0.f;

#pragma unroll
    for (int k0 = 0; k0 < 64; k0 += 8) {
        uint32_t a[4];
        a[0] = __float_as_uint(As[(k0 + tc)     * APAD + e0 + g]);
        a[1] = __float_as_uint(As[(k0 + tc)     * APAD + e0 + g + 8]);
        a[2] = __float_as_uint(As[(k0 + tc + 4) * APAD + e0 + g]);
        a[3] = __float_as_uint(As[(k0 + tc + 4) * APAD + e0 + g + 8]);
#pragma unroll
        for (int n = 0; n < 14; n++) {
            uint32_t b[2];
            b[0] = __float_as_uint(Bs[(k0 + tc)     * BPAD + (n0 + n) * 8 + g]);
            b[1] = __float_as_uint(Bs[(k0 + tc + 4) * BPAD + (n0 + n) * 8 + g]);
            mma_tf32(acc[n], a, b);
        }
    }
#pragma unroll
    for (int n = 0; n < 14; n++) {
        int w0 = (n0 + n) * 8 + 2 * tc;
        Cs[w0 * CPAD + e0 + g]           = acc[n][0];
        Cs[(w0 + 1) * CPAD + e0 + g]     = acc[n][1];
        Cs[w0 * CPAD + e0 + g + 8]       = acc[n][2];
        Cs[(w0 + 1) * CPAD + e0 + g + 8] = acc[n][3];
    }
}

// ---------------------------------------------------------------------------
// L3K: persistent tensor GEMM + K contraction + logit (4 threads/edge)
// ---------------------------------------------------------------------------
__global__ void __launch_bounds__(L3_NT, 1)
l3k_kernel(const int* __restrict__ eidx,
           const float* __restrict__ edge_sh,
           const float* __restrict__ fkW3, const float* __restrict__ fkb3,
           int E, int tiles) {
    extern __shared__ float smx[];
    float* Bs  = smx + L3_B_OFF;
    float* As  = smx + L3_A_OFF;
    float* Cs  = smx + L3_C_OFF;
    float* sB3 = smx + L3_BIAS_OFF;
    int tid = threadIdx.x;

    for (int i = tid; i < 64 * BPAD; i += L3_NT) {
        int c = i / BPAD, w = i % BPAD;
        Bs[i] = (w < 200) ? to_tf32(fkW3[c * 200 + w]) : 0.f;
    }
    for (int i = tid; i < NWP; i += L3_NT)
        sB3[i] = (i < 200) ? fkb3[i] : 0.f;

    const float NORM = 0.22360679774997896f;  // 1/sqrt(20)
    const float I3   = 0.5773502691896258f;   // 1/sqrt(3)

    for (int tile = blockIdx.x; tile < tiles; tile += gridDim.x) {
        int e0 = tile * TE;
        l3_load_A(As, g_h2k, e0, E, tid);
        __syncthreads();
        l3_gemm_mma(As, Bs, Cs, tid);
        __syncthreads();

        {
            int el = tid >> 2;     // 0..127
            int h  = tid & 3;      // 0..3
            int e  = e0 + el;
            int ee = (e < E) ? e : (E - 1);
            int d = eidx[E + ee];
            float4 sh = reinterpret_cast<const float4*>(edge_sh)[ee];

            float xl0[16], ul1[4];
#pragma unroll
            for (int o = 0; o < 16; o++) xl0[o] = g_eg[(size_t)o * E + ee];
#pragma unroll
            for (int j = 0; j < 4; j++) ul1[j] = g_eg[(size_t)(16 + j) * E + ee];

            float logit = 0.f;
#pragma unroll
            for (int bb = 0; bb < 2; bb++) {
                int b = 2 * h + bb;
                float acc0 = 0.f;
#pragma unroll
                for (int a = 0; a < 16; a++) {
                    int r = a * 8 + b;
                    acc0 = fmaf(xl0[a], Cs[r * CPAD + el] + sB3[r], acc0);
                }
                float acc1 = 0.f;
#pragma unroll
                for (int a = 0; a < 4; a++) {
                    int r = 168 + a * 8 + b;
                    acc1 = fmaf(ul1[a], Cs[r * CPAD + el] + sB3[r], acc1);
                }
                float k0b = NORM * fmaf(sh.x, acc0, I3 * acc1);
                logit = fmaf(g_qg[(size_t)b * E + ee], k0b, logit);
            }
            if (h < 2) {
                int j = h;
                float c01 = 0.f;
#pragma unroll
                for (int a = 0; a < 16; a++) {
                    int r = 128 + a * 2 + j;
                    c01 = fmaf(xl0[a], Cs[r * CPAD + el] + sB3[r], c01);
                }
                float dx = 0.f, dy = 0.f, dz = 0.f;
#pragma unroll
                for (int a = 0; a < 4; a++) {
                    int r = 160 + a * 2 + j;
                    float w = Cs[r * CPAD + el] + sB3[r];
                    dx = fmaf(g_eg[(size_t)(20 + a * 3 + 0) * E + ee], w, dx);
                    dy = fmaf(g_eg[(size_t)(20 + a * 3 + 1) * E + ee], w, dy);
                    dz = fmaf(g_eg[(size_t)(20 + a * 3 + 2) * E + ee], w, dz);
                }
                float k1x = NORM * (sh.y * c01 + sh.x * dx);
                float k1y = NORM * (sh.z * c01 + sh.x * dy);
                float k1z = NORM * (sh.w * c01 + sh.x * dz);
                logit += I3 * (g_qg[(size_t)(8 + j * 3 + 0) * E + ee] * k1x +
                               g_qg[(size_t)(8 + j * 3 + 1) * E + ee] * k1y +
                               g_qg[(size_t)(8 + j * 3 + 2) * E + ee] * k1z);
            }
            logit += __shfl_xor_sync(0xffffffffu, logit, 1);
            logit += __shfl_xor_sync(0xffffffffu, logit, 2);
            logit *= 0.31622776601683794f;  // 1/sqrt(10)
            if (h == 0 && e < E) {
                g_logit[e] = logit;
                atomicMaxF(&g_m[d], logit);
            }
        }
        __syncthreads();
    }
}

// ---------------------------------------------------------------------------
// L3V (HALF = 0/1): persistent tensor GEMM + V contraction (4 threads/edge)
// ---------------------------------------------------------------------------
template <int HALF>
__device__ __forceinline__ int v_wi(int r) {
    if (r < 128) { int a = r >> 3, b = r & 7;        return a * 16 + HALF * 8 + b; }
    if (r < 160) { int t = r - 128; int a = t >> 1;  return 256 + a * 4 + HALF * 2 + (t & 1); }
    if (r < 168) { int t = r - 160; int a = t >> 1;  return 320 + a * 4 + HALF * 2 + (t & 1); }
    { int t = r - 168; int a = t >> 3, b = t & 7;    return 336 + a * 16 + HALF * 8 + b; }
}

template <int HALF>
__global__ void __launch_bounds__(L3_NT, 1)
l3v_kernel(const float* __restrict__ edge_sh,
           const float* __restrict__ fcW3, const float* __restrict__ fcb3,
           int E, int tiles) {
    extern __shared__ float smx[];
    float* Bs  = smx + L3_B_OFF;
    float* As  = smx + L3_A_OFF;
    float* Cs  = smx + L3_C_OFF;
    float* sB3 = smx + L3_BIAS_OFF;
    int tid = threadIdx.x;

    for (int i = tid; i < 64 * BPAD; i += L3_NT) {
        int c = i / BPAD, w = i % BPAD;
        Bs[i] = (w < 200) ? to_tf32(fcW3[c * 400 + v_wi<HALF>(w)]) : 0.f;
    }
    for (int i = tid; i < NWP; i += L3_NT)
        sB3[i] = (i < 200) ? fcb3[v_wi<HALF>(i)] : 0.f;

    const float NORM = 0.22360679774997896f;  // 1/sqrt(20)
    const float I3   = 0.5773502691896258f;   // 1/sqrt(3)

    for (int tile = blockIdx.x; tile < tiles; tile += gridDim.x) {
        int e0 = tile * TE;
        l3_load_A(As, g_h2v, e0, E, tid);
        __syncthreads();
        l3_gemm_mma(As, Bs, Cs, tid);
        __syncthreads();

        {
            int el = tid >> 2;
            int h  = tid & 3;
            int e  = e0 + el;
            bool ok = e < E;
            int ee = ok ? e : (E - 1);
            float4 sh = reinterpret_cast<const float4*>(edge_sh)[ee];

            float xl0[16], ul1[4];
#pragma unroll
            for (int o = 0; o < 16; o++) xl0[o] = g_eg[(size_t)o * E + ee];
#pragma unroll
            for (int j = 0; j < 4; j++) ul1[j] = g_eg[(size_t)(16 + j) * E + ee];

#pragma unroll
            for (int bb = 0; bb < 2; bb++) {
                int b = 2 * h + bb;
                float acc0 = 0.f;
#pragma unroll
                for (int a = 0; a < 16; a++) {
                    int r = a * 8 + b;
                    acc0 = fmaf(xl0[a], Cs[r * CPAD + el] + sB3[r], acc0);
                }
                float acc1 = 0.f;
#pragma unroll
                for (int a = 0; a < 4; a++) {
                    int r = 168 + a * 8 + b;
                    acc1 = fmaf(ul1[a], Cs[r * CPAD + el] + sB3[r], acc1);
                }
                int bg = HALF * 8 + b;
                if (ok) g_v[(size_t)bg * E + e] = NORM * fmaf(sh.x, acc0, I3 * acc1);
            }
            if (h < 2) {
                int j = h;
                float c01 = 0.f;
#pragma unroll
                for (int a = 0; a < 16; a++) {
                    int r = 128 + a * 2 + j;
                    c01 = fmaf(xl0[a], Cs[r * CPAD + el] + sB3[r], c01);
                }
                float dx = 0.f, dy = 0.f, dz = 0.f;
#pragma unroll
                for (int a = 0; a < 4; a++) {
                    int r = 160 + a * 2 + j;
                    float w = Cs[r * CPAD + el] + sB3[r];
                    dx = fmaf(g_eg[(size_t)(20 + a * 3 + 0) * E + ee], w, dx);
                    dy = fmaf(g_eg[(size_t)(20 + a * 3 + 1) * E + ee], w, dy);
                    dz = fmaf(g_eg[(size_t)(20 + a * 3 + 2) * E + ee], w, dz);
                }
                int jg = HALF * 2 + j;
                if (ok) {
                    g_v[(size_t)(16 + jg * 3 + 0) * E + e] = NORM * (sh.y * c01 + sh.x * dx);
                    g_v[(size_t)(16 + jg * 3 + 1) * E + e] = NORM * (sh.z * c01 + sh.x * dy);
                    g_v[(size_t)(16 + jg * 3 + 2) * E + e] = NORM * (sh.w * c01 + sh.x * dz);
                }
            }
        }
        __syncthreads();
    }
}

// ---------------------------------------------------------------------------
// softmax+aggregate: 4 threads per edge (7 channels each)
// ---------------------------------------------------------------------------
__global__ void softmax_agg_kernel(const int* __restrict__ eidx, int E) {
    int t = blockIdx.x * blockDim.x + threadIdx.x;
    int e = t >> 2;
    int q = t & 3;
    if (e >= E) return;
    int d = eidx[E + e];
    float p = __expf(g_logit[e] - g_m[d]);
    if (q == 0) atomicAdd(&g_z[d], p);
#pragma unroll
    for (int jj = 0; jj < 7; jj++) {
        int j = q * 7 + jj;
        atomicAdd(&g_agg[(size_t)d * 28 + j], p * g_v[(size_t)j * E + e]);
    }
}

// ---------------------------------------------------------------------------
__global__ void node_out_kernel(const float* __restrict__ na,
                                const float* __restrict__ Wo0,
                                const float* __restrict__ Wo1,
                                float* __restrict__ out, int N) {
    __shared__ float sW0[512], sW1[32];
    int tid = threadIdx.x;
    for (int i = tid; i < 512; i += blockDim.x) sW0[i] = Wo0[i];
    for (int i = tid; i < 32;  i += blockDim.x) sW1[i] = Wo1[i];
    __syncthreads();

    int n = blockIdx.x * blockDim.x + tid;
    if (n >= N) return;
    float z = g_z[n];
    float zi = z > 0.f ? 1.f / z : 0.f;
    float ag[28];
#pragma unroll
    for (int j = 0; j < 28; j++) ag[j] = g_agg[(size_t)n * 28 + j] * zi;

#pragma unroll
    for (int o = 0; o < 32; o++) {
        float s = 0.f;
#pragma unroll
        for (int a = 0; a < 16; a++) s = fmaf(ag[a], sW0[a * 32 + o], s);
        out[(size_t)n * 56 + o] = fmaf(s, 0.25f, na[(size_t)n * 56 + o]);
    }
#pragma unroll
    for (int o = 0; o < 8; o++)
#pragma unroll
        for (int c = 0; c < 3; c++) {
            float s = 0.f;
#pragma unroll
            for (int a = 0; a < 4; a++) s = fmaf(ag[16 + a * 3 + c], sW1[a * 8 + o], s);
            out[(size_t)n * 56 + 32 + o * 3 + c] =
                fmaf(s, 0.5f, na[(size_t)n * 56 + 32 + o * 3 + c]);
        }
}

// ---------------------------------------------------------------------------
extern "C" void kernel_launch(void* const* d_in, const int* in_sizes, int n_in,
                              void* d_out, int out_size) {
    const float* node_attr  = (const float*)d_in[0];
    const float* edge_attr  = (const float*)d_in[1];
    const float* edge_sh    = (const float*)d_in[2];
    const int*   edge_index = (const int*)  d_in[3];
    const float* W_in0  = (const float*)d_in[4];
    const float* W_in1  = (const float*)d_in[5];
    const float* Wq0    = (const float*)d_in[6];
    const float* Wq1    = (const float*)d_in[7];
    const float* Wd0    = (const float*)d_in[8];
    const float* Wd1    = (const float*)d_in[9];
    const float* W_out0 = (const float*)d_in[10];
    const float* W_out1 = (const float*)d_in[11];
    const float* fcW1 = (const float*)d_in[12];
    const float* fcb1 = (const float*)d_in[13];
    const float* fcW2 = (const float*)d_in[14];
    const float* fcb2 = (const float*)d_in[15];
    const float* fcW3 = (const float*)d_in[16];
    const float* fcb3 = (const float*)d_in[17];
    const float* fkW1 = (const float*)d_in[18];
    const float* fkb1 = (const float*)d_in[19];
    const float* fkW2 = (const float*)d_in[20];
    const float* fkb2 = (const float*)d_in[21];
    const float* fkW3 = (const float*)d_in[22];
    const float* fkb3 = (const float*)d_in[23];
    float* out = (float*)d_out;

    int N = in_sizes[0] / 56;
    int E = in_sizes[2] / 4;

    const int FRONT_SMEM = FT_FLOATS * (int)sizeof(float);  // 103936 B
    const int L3_SMEM    = L3_FLOATS * (int)sizeof(float);  // 211328 B

    cudaFuncSetAttribute(front_kernel,
                         cudaFuncAttributeMaxDynamicSharedMemorySize, FRONT_SMEM);
    cudaFuncSetAttribute(l3k_kernel,
                         cudaFuncAttributeMaxDynamicSharedMemorySize, L3_SMEM);
    cudaFuncSetAttribute(l3v_kernel<0>,
                         cudaFuncAttributeMaxDynamicSharedMemorySize, L3_SMEM);
    cudaFuncSetAttribute(l3v_kernel<1>,
                         cudaFuncAttributeMaxDynamicSharedMemorySize, L3_SMEM);

    int tiles = (E + TE - 1) / TE;

    node_prep_kernel<<<(N + 127) / 128, 128>>>(node_attr, W_in0, W_in1, Wq0, Wq1,
                                               Wd0, Wd1, N);
    init_kernel<<<(N * 28 + 255) / 256, 256>>>(N);
    edge_gather_kernel<<<(E + 255) / 256, 256>>>(edge_sh, edge_index, E);
    front_kernel<<<NSM * 2, 256, FRONT_SMEM>>>(edge_attr,
                                               fcW1, fcb1, fcW2, fcb2,
                                               fkW1, fkb1, fkW2, fkb2, E, tiles);
    l3k_kernel<<<NSM, L3_NT, L3_SMEM>>>(edge_index, edge_sh, fkW3, fkb3, E, tiles);
    l3v_kernel<0><<<NSM, L3_NT, L3_SMEM>>>(edge_sh, fcW3, fcb3, E, tiles);
    l3v_kernel<1><<<NSM, L3_NT, L3_SMEM>>>(edge_sh, fcW3, fcb3, E, tiles);
    softmax_agg_kernel<<<(E * 4 + 255) / 256, 256>>>(edge_index, E);
    node_out_kernel<<<(N + 127) / 128, 128>>>(node_attr, W_out0, W_out1, out, N);
}

// round 16
// speedup vs baseline: 2.3946x; 1.0877x over previous
#include <cuda_runtime.h>
#include <cstdint>
#include <cstddef>

#define MAXN 10000
#define MAXE 160000
#define NSM  148

__device__ float g_x0[MAXN * 16];
__device__ float g_x1[MAXN * 12];
__device__ float g_qd0[MAXN * 8];
__device__ float g_qd1[MAXN * 6];
__device__ float g_logit[MAXE];
__device__ float g_m[MAXN];
__device__ float g_z[MAXN];
__device__ float g_agg[MAXN * 28];     // AoS
__device__ float g_h2k[(size_t)MAXE * 64];   // TRANSPOSED [c*E+e], pre-tf32
__device__ float g_h2v[(size_t)MAXE * 64];   // TRANSPOSED [c*E+e], pre-tf32
__device__ float g_eg[(size_t)MAXE * 32];    // SoA: 0-15 xl0, 16-19 ul1, 20-31 xl1
__device__ float g_qg[(size_t)MAXE * 14];    // SoA: 0-7 qd0[dst], 8-13 qd1[dst]

__device__ __forceinline__ float frelu(float x) { return x > 0.f ? x : 0.f; }

__device__ __forceinline__ void atomicMaxF(float* addr, float v) {
    if (v >= 0.f) atomicMax((int*)addr, __float_as_int(v));
    else          atomicMin((unsigned int*)addr, __float_as_uint(v));
}

// ---- tf32 helpers ----------------------------------------------------------
__device__ __forceinline__ float to_tf32(float x) {
    uint32_t u; asm("cvt.rna.tf32.f32 %0, %1;" : "=r"(u) : "f"(x));
    return __uint_as_float(u);
}
__device__ __forceinline__ void mma_tf32(float* d, const uint32_t* a,
                                         const uint32_t* b) {
    asm volatile(
        "mma.sync.aligned.m16n8k8.row.col.f32.tf32.tf32.f32 "
        "{%0,%1,%2,%3}, {%4,%5,%6,%7}, {%8,%9}, {%0,%1,%2,%3};\n"
        : "+f"(d[0]), "+f"(d[1]), "+f"(d[2]), "+f"(d[3])
        : "r"(a[0]), "r"(a[1]), "r"(a[2]), "r"(a[3]), "r"(b[0]), "r"(b[1]));
}

// ---------------------------------------------------------------------------
// Kernel A: node prep
// ---------------------------------------------------------------------------
__global__ void node_prep_kernel(const float* __restrict__ na,
                                 const float* __restrict__ Win0,
                                 const float* __restrict__ Win1,
                                 const float* __restrict__ Wq0,
                                 const float* __restrict__ Wq1,
                                 const float* __restrict__ Wd0,
                                 const float* __restrict__ Wd1,
                                 int N) {
    __shared__ float sWin0[512], sWin1[32], sWq0[128], sWq1[8], sWd0[64], sWd1[4];
    int tid = threadIdx.x;
    for (int i = tid; i < 512; i += blockDim.x) sWin0[i] = Win0[i];
    for (int i = tid; i < 32;  i += blockDim.x) sWin1[i] = Win1[i];
    for (int i = tid; i < 128; i += blockDim.x) sWq0[i]  = Wq0[i];
    for (int i = tid; i < 8;   i += blockDim.x) sWq1[i]  = Wq1[i];
    for (int i = tid; i < 64;  i += blockDim.x) sWd0[i]  = Wd0[i];
    for (int i = tid; i < 4;   i += blockDim.x) sWd1[i]  = Wd1[i];
    __syncthreads();

    int n = blockIdx.x * blockDim.x + tid;
    if (n >= N) return;

    const float* p = na + (size_t)n * 56;
    float a0[32], a1[24];
#pragma unroll
    for (int i = 0; i < 32; i++) a0[i] = p[i];
#pragma unroll
    for (int i = 0; i < 24; i++) a1[i] = p[32 + i];

    float x0[16];
#pragma unroll
    for (int o = 0; o < 16; o++) {
        float s = 0.f;
#pragma unroll
        for (int i = 0; i < 32; i++) s = fmaf(a0[i], sWin0[i * 16 + o], s);
        x0[o] = s * 0.17677669529663687f;   // 1/sqrt(32)
    }
    float x1[12];
#pragma unroll
    for (int o = 0; o < 4; o++)
#pragma unroll
        for (int c = 0; c < 3; c++) {
            float s = 0.f;
#pragma unroll
            for (int m = 0; m < 8; m++) s = fmaf(a1[m * 3 + c], sWin1[m * 4 + o], s);
            x1[o * 3 + c] = s * 0.35355339059327373f;  // 1/sqrt(8)
        }

    float q0[8];
#pragma unroll
    for (int b = 0; b < 8; b++) {
        float s = 0.f;
#pragma unroll
        for (int o = 0; o < 16; o++) s = fmaf(x0[o], sWq0[o * 8 + b], s);
        q0[b] = s * 0.25f;                   // 1/sqrt(16)
    }
    float q1[6];
#pragma unroll
    for (int j = 0; j < 2; j++)
#pragma unroll
        for (int c = 0; c < 3; c++) {
            float s = 0.f;
#pragma unroll
            for (int o = 0; o < 4; o++) s = fmaf(x1[o * 3 + c], sWq1[o * 2 + j], s);
            q1[j * 3 + c] = s * 0.5f;        // 1/sqrt(4)
        }

#pragma unroll
    for (int j = 0; j < 8; j++) {
        float s = 0.f;
#pragma unroll
        for (int i = 0; i < 8; i++) s = fmaf(q0[i], sWd0[i * 8 + j], s);
        g_qd0[(size_t)n * 8 + j] = s;
    }
#pragma unroll
    for (int j = 0; j < 2; j++)
#pragma unroll
        for (int c = 0; c < 3; c++) {
            float s = 0.f;
#pragma unroll
            for (int i = 0; i < 2; i++) s = fmaf(q1[i * 3 + c], sWd1[i * 2 + j], s);
            g_qd1[(size_t)n * 6 + j * 3 + c] = s;
        }

#pragma unroll
    for (int o = 0; o < 16; o++) g_x0[(size_t)n * 16 + o] = x0[o];
#pragma unroll
    for (int o = 0; o < 12; o++) g_x1[(size_t)n * 12 + o] = x1[o];
}

// ---------------------------------------------------------------------------
__global__ void init_kernel(int N) {
    int i = blockIdx.x * blockDim.x + threadIdx.x;
    if (i < N * 28) g_agg[i] = 0.f;
    if (i < N) {
        g_m[i] = __int_as_float(0xff800000);  // -inf
        g_z[i] = 0.f;
    }
}

// ---------------------------------------------------------------------------
// EDGE GATHER: scatter-gather per-edge operands ONCE (vectorized loads).
// ---------------------------------------------------------------------------
__global__ void edge_gather_kernel(const float* __restrict__ edge_sh,
                                   const int* __restrict__ eidx, int E) {
    int e = blockIdx.x * blockDim.x + threadIdx.x;
    if (e >= E) return;
    int s = eidx[e], d = eidx[E + e];
    float4 sh = reinterpret_cast<const float4*>(edge_sh)[e];

    // xl0: 4x float4 (rows 64B aligned)
    const float4* x0p = reinterpret_cast<const float4*>(g_x0 + (size_t)s * 16);
    float4 v0 = x0p[0], v1 = x0p[1], v2 = x0p[2], v3 = x0p[3];
    float xl0[16] = {v0.x, v0.y, v0.z, v0.w, v1.x, v1.y, v1.z, v1.w,
                     v2.x, v2.y, v2.z, v2.w, v3.x, v3.y, v3.z, v3.w};
#pragma unroll
    for (int o = 0; o < 16; o++) g_eg[(size_t)o * E + e] = xl0[o];

    // xl1: 3x float4 (rows 48B stride, 16B aligned)
    const float4* x1p = reinterpret_cast<const float4*>(g_x1 + (size_t)s * 12);
    float4 w0 = x1p[0], w1 = x1p[1], w2 = x1p[2];
    float x1[12] = {w0.x, w0.y, w0.z, w0.w, w1.x, w1.y, w1.z, w1.w,
                    w2.x, w2.y, w2.z, w2.w};
#pragma unroll
    for (int o = 0; o < 12; o++) g_eg[(size_t)(20 + o) * E + e] = x1[o];
#pragma unroll
    for (int j = 0; j < 4; j++)
        g_eg[(size_t)(16 + j) * E + e] =
            x1[j * 3] * sh.y + x1[j * 3 + 1] * sh.z + x1[j * 3 + 2] * sh.w;

    // qd0: 2x float4 (rows 32B aligned)
    const float4* q0p = reinterpret_cast<const float4*>(g_qd0 + (size_t)d * 8);
    float4 u0 = q0p[0], u1 = q0p[1];
    float qd0[8] = {u0.x, u0.y, u0.z, u0.w, u1.x, u1.y, u1.z, u1.w};
#pragma unroll
    for (int j = 0; j < 8; j++) g_qg[(size_t)j * E + e] = qd0[j];

    // qd1: 3x float2 (rows 24B stride, 8B aligned)
    const float2* q1p = reinterpret_cast<const float2*>(g_qd1 + (size_t)d * 6);
    float2 t0 = q1p[0], t1 = q1p[1], t2 = q1p[2];
    float qd1[6] = {t0.x, t0.y, t1.x, t1.y, t2.x, t2.y};
#pragma unroll
    for (int j = 0; j < 6; j++) g_qg[(size_t)(8 + j) * E + e] = qd1[j];
}

// ---------------------------------------------------------------------------
// FRONT kernel (tensor-core): both MLPs 32->64->64, tiles of 128 edges.
// Layer-2 fragments stored DIRECTLY to global h2 (tf32(relu(bias+acc))).
// ---------------------------------------------------------------------------
#define FT_BP 68
#define FT_AP 132
#define FT_B1K 0
#define FT_B2K 2176
#define FT_B1V 6528
#define FT_B2V 8704
#define FT_b1K 13056
#define FT_b2K 13120
#define FT_b1V 13184
#define FT_b2V 13248
#define FT_A0  13312
#define FT_A1  17536
#define FT_FLOATS 25984

template <int KSTEPS, int MODE>
__device__ __forceinline__ void ft_gemm(const float* __restrict__ As,
                                        const float* __restrict__ Bs,
                                        const float* __restrict__ bias,
                                        float* __restrict__ dst,
                                        int tid, int e0t, int E) {
    int warp = tid >> 5, lane = tid & 31;
    int g = lane >> 2, tc = lane & 3;
    int e0 = warp * 16;

    float acc[8][4];
#pragma unroll
    for (int n = 0; n < 8; n++)
#pragma unroll
        for (int i = 0; i < 4; i++) acc[n][i] = 0.f;

#pragma unroll
    for (int ks = 0; ks < KSTEPS; ks++) {
        int k0 = ks * 8;
        uint32_t a[4];
        a[0] = __float_as_uint(As[(k0 + tc)     * FT_AP + e0 + g]);
        a[1] = __float_as_uint(As[(k0 + tc)     * FT_AP + e0 + g + 8]);
        a[2] = __float_as_uint(As[(k0 + tc + 4) * FT_AP + e0 + g]);
        a[3] = __float_as_uint(As[(k0 + tc + 4) * FT_AP + e0 + g + 8]);
#pragma unroll
        for (int n = 0; n < 8; n++) {
            uint32_t b[2];
            b[0] = __float_as_uint(Bs[(k0 + tc)     * FT_BP + n * 8 + g]);
            b[1] = __float_as_uint(Bs[(k0 + tc + 4) * FT_BP + n * 8 + g]);
            mma_tf32(acc[n], a, b);
        }
    }
#pragma unroll
    for (int n = 0; n < 8; n++) {
        int w0 = n * 8 + 2 * tc;
        float b0 = bias[w0], b1 = bias[w0 + 1];
        float v00 = to_tf32(frelu(b0 + acc[n][0]));
        float v10 = to_tf32(frelu(b1 + acc[n][1]));
        float v01 = to_tf32(frelu(b0 + acc[n][2]));
        float v11 = to_tf32(frelu(b1 + acc[n][3]));
        if (MODE == 0) {
            dst[w0 * FT_AP + e0 + g]           = v00;
            dst[(w0 + 1) * FT_AP + e0 + g]     = v10;
            dst[w0 * FT_AP + e0 + g + 8]       = v01;
            dst[(w0 + 1) * FT_AP + e0 + g + 8] = v11;
        } else {
            int ea = e0t + e0 + g;
            int eb = ea + 8;
            if (ea < E) {
                dst[(size_t)w0 * E + ea]       = v00;
                dst[(size_t)(w0 + 1) * E + ea] = v10;
            }
            if (eb < E) {
                dst[(size_t)w0 * E + eb]       = v01;
                dst[(size_t)(w0 + 1) * E + eb] = v11;
            }
        }
    }
}

__global__ void __launch_bounds__(256, 2)
front_kernel(const float* __restrict__ edge_attr,
             const float* __restrict__ fcW1, const float* __restrict__ fcb1,
             const float* __restrict__ fcW2, const float* __restrict__ fcb2,
             const float* __restrict__ fkW1, const float* __restrict__ fkb1,
             const float* __restrict__ fkW2, const float* __restrict__ fkb2,
             int E, int tiles) {
    extern __shared__ float sm[];
    int tid = threadIdx.x;

    for (int i = tid; i < 32 * FT_BP; i += 256) {
        int c = i / FT_BP, o = i % FT_BP;
        sm[FT_B1K + i] = (o < 64) ? to_tf32(fkW1[c * 64 + o]) : 0.f;
        sm[FT_B1V + i] = (o < 64) ? to_tf32(fcW1[c * 64 + o]) : 0.f;
    }
    for (int i = tid; i < 64 * FT_BP; i += 256) {
        int c = i / FT_BP, o = i % FT_BP;
        sm[FT_B2K + i] = (o < 64) ? to_tf32(fkW2[c * 64 + o]) : 0.f;
        sm[FT_B2V + i] = (o < 64) ? to_tf32(fcW2[c * 64 + o]) : 0.f;
    }
    for (int i = tid; i < 64; i += 256) {
        sm[FT_b1K + i] = fkb1[i];
        sm[FT_b2K + i] = fkb2[i];
        sm[FT_b1V + i] = fcb1[i];
        sm[FT_b2V + i] = fcb2[i];
    }
    __syncthreads();

    for (int tile = blockIdx.x; tile < tiles; tile += gridDim.x) {
        int e0t = tile * 128;
        for (int i = tid; i < 128 * 8; i += 256) {
            int e = i >> 3, q8 = i & 7;
            float4 v;
            if (e0t + e < E)
                v = *reinterpret_cast<const float4*>(
                        edge_attr + (size_t)(e0t + e) * 32 + 4 * q8);
            else { v.x = v.y = v.z = v.w = 0.f; }
            sm[FT_A0 + (4 * q8 + 0) * FT_AP + e] = to_tf32(v.x);
            sm[FT_A0 + (4 * q8 + 1) * FT_AP + e] = to_tf32(v.y);
            sm[FT_A0 + (4 * q8 + 2) * FT_AP + e] = to_tf32(v.z);
            sm[FT_A0 + (4 * q8 + 3) * FT_AP + e] = to_tf32(v.w);
        }
        __syncthreads();
        ft_gemm<4, 0>(sm + FT_A0, sm + FT_B1K, sm + FT_b1K, sm + FT_A1, tid, 0, 0);
        __syncthreads();
        ft_gemm<8, 1>(sm + FT_A1, sm + FT_B2K, sm + FT_b2K, g_h2k, tid, e0t, E);
        __syncthreads();
        ft_gemm<4, 0>(sm + FT_A0, sm + FT_B1V, sm + FT_b1V, sm + FT_A1, tid, 0, 0);
        __syncthreads();
        ft_gemm<8, 1>(sm + FT_A1, sm + FT_B2V, sm + FT_b2V, g_h2v, tid, e0t, E);
    }
}

// ---------------------------------------------------------------------------
// L3 tensor-core GEMM machinery (persistent tiles of 128 edges, 512 threads)
// ---------------------------------------------------------------------------
#define TE     128
#define NWP    224
#define APAD   132
#define BPAD   228
#define CPAD   132
#define L3_B_OFF    0
#define L3_A_OFF    14592
#define L3_C_OFF    23040
#define L3_BIAS_OFF 52608
#define L3_FLOATS   52832
#define L3_NT  512

__device__ __forceinline__ void l3_load_A(float* __restrict__ As,
                                          const float* __restrict__ gh2T,
                                          int e0, int E, int tid) {
    for (int i = tid; i < 64 * (TE / 4); i += L3_NT) {
        int c = i >> 5;
        int v = i & 31;
        int eb = e0 + 4 * v;
        float4 f;
        if (eb + 3 < E) {
            f = *reinterpret_cast<const float4*>(gh2T + (size_t)c * E + eb);
        } else {
            f.x = (eb + 0 < E) ? gh2T[(size_t)c * E + eb + 0] : 0.f;
            f.y = (eb + 1 < E) ? gh2T[(size_t)c * E + eb + 1] : 0.f;
            f.z = (eb + 2 < E) ? gh2T[(size_t)c * E + eb + 2] : 0.f;
            f.w = (eb + 3 < E) ? gh2T[(size_t)c * E + eb + 3] : 0.f;
        }
        *reinterpret_cast<float4*>(As + c * APAD + 4 * v) = f;
    }
}

__device__ __forceinline__ void l3_gemm_mma(const float* __restrict__ As,
                                            const float* __restrict__ Bs,
                                            float* __restrict__ Cs, int tid) {
    int warp = tid >> 5, lane = tid & 31;
    int g = lane >> 2, tc = lane & 3;
    int wg = warp >> 3;
    int e0 = (warp & 7) * 16;
    int n0 = wg * 14;

    float acc[14][4];
#pragma unroll
    for (int n = 0; n < 14; n++)
#pragma unroll
        for (int i = 0; i < 4; i++) acc[n][i] = 0.f;

#pragma unroll
    for (int k0 = 0; k0 < 64; k0 += 8) {
        uint32_t a[4];
        a[0] = __float_as_uint(As[(k0 + tc)     * APAD + e0 + g]);
        a[1] = __float_as_uint(As[(k0 + tc)     * APAD + e0 + g + 8]);
        a[2] = __float_as_uint(As[(k0 + tc + 4) * APAD + e0 + g]);
        a[3] = __float_as_uint(As[(k0 + tc + 4) * APAD + e0 + g + 8]);
#pragma unroll
        for (int n = 0; n < 14; n++) {
            uint32_t b[2];
            b[0] = __float_as_uint(Bs[(k0 + tc)     * BPAD + (n0 + n) * 8 + g]);
            b[1] = __float_as_uint(Bs[(k0 + tc + 4) * BPAD + (n0 + n) * 8 + g]);
            mma_tf32(acc[n], a, b);
        }
    }
#pragma unroll
    for (int n = 0; n < 14; n++) {
        int w0 = (n0 + n) * 8 + 2 * tc;
        Cs[w0 * CPAD + e0 + g]           = acc[n][0];
        Cs[(w0 + 1) * CPAD + e0 + g]     = acc[n][1];
        Cs[w0 * CPAD + e0 + g + 8]       = acc[n][2];
        Cs[(w0 + 1) * CPAD + e0 + g + 8] = acc[n][3];
    }
}

// ---------------------------------------------------------------------------
// L3K: persistent tensor GEMM + K contraction + logit (4 threads/edge)
// ---------------------------------------------------------------------------
__global__ void __launch_bounds__(L3_NT, 1)
l3k_kernel(const int* __restrict__ eidx,
           const float* __restrict__ edge_sh,
           const float* __restrict__ fkW3, const float* __restrict__ fkb3,
           int E, int tiles) {
    extern __shared__ float smx[];
    float* Bs  = smx + L3_B_OFF;
    float* As  = smx + L3_A_OFF;
    float* Cs  = smx + L3_C_OFF;
    float* sB3 = smx + L3_BIAS_OFF;
    int tid = threadIdx.x;

    for (int i = tid; i < 64 * BPAD; i += L3_NT) {
        int c = i / BPAD, w = i % BPAD;
        Bs[i] = (w < 200) ? to_tf32(fkW3[c * 200 + w]) : 0.f;
    }
    for (int i = tid; i < NWP; i += L3_NT)
        sB3[i] = (i < 200) ? fkb3[i] : 0.f;

    const float NORM = 0.22360679774997896f;  // 1/sqrt(20)
    const float I3   = 0.5773502691896258f;   // 1/sqrt(3)

    for (int tile = blockIdx.x; tile < tiles; tile += gridDim.x) {
        int e0 = tile * TE;
        l3_load_A(As, g_h2k, e0, E, tid);
        __syncthreads();
        l3_gemm_mma(As, Bs, Cs, tid);
        __syncthreads();

        {
            int el = tid >> 2;
            int h  = tid & 3;
            int e  = e0 + el;
            int ee = (e < E) ? e : (E - 1);
            int d = eidx[E + ee];
            float4 sh = reinterpret_cast<const float4*>(edge_sh)[ee];

            float xl0[16], ul1[4];
#pragma unroll
            for (int o = 0; o < 16; o++) xl0[o] = g_eg[(size_t)o * E + ee];
#pragma unroll
            for (int j = 0; j < 4; j++) ul1[j] = g_eg[(size_t)(16 + j) * E + ee];

            float logit = 0.f;
#pragma unroll
            for (int bb = 0; bb < 2; bb++) {
                int b = 2 * h + bb;
                float acc0 = 0.f;
#pragma unroll
                for (int a = 0; a < 16; a++) {
                    int r = a * 8 + b;
                    acc0 = fmaf(xl0[a], Cs[r * CPAD + el] + sB3[r], acc0);
                }
                float acc1 = 0.f;
#pragma unroll
                for (int a = 0; a < 4; a++) {
                    int r = 168 + a * 8 + b;
                    acc1 = fmaf(ul1[a], Cs[r * CPAD + el] + sB3[r], acc1);
                }
                float k0b = NORM * fmaf(sh.x, acc0, I3 * acc1);
                logit = fmaf(g_qg[(size_t)b * E + ee], k0b, logit);
            }
            if (h < 2) {
                int j = h;
                float c01 = 0.f;
#pragma unroll
                for (int a = 0; a < 16; a++) {
                    int r = 128 + a * 2 + j;
                    c01 = fmaf(xl0[a], Cs[r * CPAD + el] + sB3[r], c01);
                }
                float dx = 0.f, dy = 0.f, dz = 0.f;
#pragma unroll
                for (int a = 0; a < 4; a++) {
                    int r = 160 + a * 2 + j;
                    float w = Cs[r * CPAD + el] + sB3[r];
                    dx = fmaf(g_eg[(size_t)(20 + a * 3 + 0) * E + ee], w, dx);
                    dy = fmaf(g_eg[(size_t)(20 + a * 3 + 1) * E + ee], w, dy);
                    dz = fmaf(g_eg[(size_t)(20 + a * 3 + 2) * E + ee], w, dz);
                }
                float k1x = NORM * (sh.y * c01 + sh.x * dx);
                float k1y = NORM * (sh.z * c01 + sh.x * dy);
                float k1z = NORM * (sh.w * c01 + sh.x * dz);
                logit += I3 * (g_qg[(size_t)(8 + j * 3 + 0) * E + ee] * k1x +
                               g_qg[(size_t)(8 + j * 3 + 1) * E + ee] * k1y +
                               g_qg[(size_t)(8 + j * 3 + 2) * E + ee] * k1z);
            }
            logit += __shfl_xor_sync(0xffffffffu, logit, 1);
            logit += __shfl_xor_sync(0xffffffffu, logit, 2);
            logit *= 0.31622776601683794f;  // 1/sqrt(10)
            if (h == 0 && e < E) {
                g_logit[e] = logit;
                atomicMaxF(&g_m[d], logit);
            }
        }
        __syncthreads();
    }
}

// ---------------------------------------------------------------------------
// L3V (HALF = 0/1): tensor GEMM + V contraction + FUSED softmax-aggregate.
// Runs AFTER l3k, so g_m / g_logit are final: p = exp(logit - m[d]) and
// p*v goes straight into g_agg via atomics (g_v eliminated).
// ---------------------------------------------------------------------------
template <int HALF>
__device__ __forceinline__ int v_wi(int r) {
    if (r < 128) { int a = r >> 3, b = r & 7;        return a * 16 + HALF * 8 + b; }
    if (r < 160) { int t = r - 128; int a = t >> 1;  return 256 + a * 4 + HALF * 2 + (t & 1); }
    if (r < 168) { int t = r - 160; int a = t >> 1;  return 320 + a * 4 + HALF * 2 + (t & 1); }
    { int t = r - 168; int a = t >> 3, b = t & 7;    return 336 + a * 16 + HALF * 8 + b; }
}

template <int HALF>
__global__ void __launch_bounds__(L3_NT, 1)
l3v_kernel(const int* __restrict__ eidx,
           const float* __restrict__ edge_sh,
           const float* __restrict__ fcW3, const float* __restrict__ fcb3,
           int E, int tiles) {
    extern __shared__ float smx[];
    float* Bs  = smx + L3_B_OFF;
    float* As  = smx + L3_A_OFF;
    float* Cs  = smx + L3_C_OFF;
    float* sB3 = smx + L3_BIAS_OFF;
    int tid = threadIdx.x;

    for (int i = tid; i < 64 * BPAD; i += L3_NT) {
        int c = i / BPAD, w = i % BPAD;
        Bs[i] = (w < 200) ? to_tf32(fcW3[c * 400 + v_wi<HALF>(w)]) : 0.f;
    }
    for (int i = tid; i < NWP; i += L3_NT)
        sB3[i] = (i < 200) ? fcb3[v_wi<HALF>(i)] : 0.f;

    const float NORM = 0.22360679774997896f;  // 1/sqrt(20)
    const float I3   = 0.5773502691896258f;   // 1/sqrt(3)

    for (int tile = blockIdx.x; tile < tiles; tile += gridDim.x) {
        int e0 = tile * TE;
        l3_load_A(As, g_h2v, e0, E, tid);
        __syncthreads();
        l3_gemm_mma(As, Bs, Cs, tid);
        __syncthreads();

        {
            int el = tid >> 2;
            int h  = tid & 3;
            int e  = e0 + el;
            bool ok = e < E;
            int ee = ok ? e : (E - 1);
            int d = eidx[E + ee];
            float4 sh = reinterpret_cast<const float4*>(edge_sh)[ee];
            float p = __expf(g_logit[ee] - g_m[d]);

            float xl0[16], ul1[4];
#pragma unroll
            for (int o = 0; o < 16; o++) xl0[o] = g_eg[(size_t)o * E + ee];
#pragma unroll
            for (int j = 0; j < 4; j++) ul1[j] = g_eg[(size_t)(16 + j) * E + ee];

#pragma unroll
            for (int bb = 0; bb < 2; bb++) {
                int b = 2 * h + bb;
                float acc0 = 0.f;
#pragma unroll
                for (int a = 0; a < 16; a++) {
                    int r = a * 8 + b;
                    acc0 = fmaf(xl0[a], Cs[r * CPAD + el] + sB3[r], acc0);
                }
                float acc1 = 0.f;
#pragma unroll
                for (int a = 0; a < 4; a++) {
                    int r = 168 + a * 8 + b;
                    acc1 = fmaf(ul1[a], Cs[r * CPAD + el] + sB3[r], acc1);
                }
                int bg = HALF * 8 + b;
                float val = NORM * fmaf(sh.x, acc0, I3 * acc1);
                if (ok) atomicAdd(&g_agg[(size_t)d * 28 + bg], p * val);
            }
            if (h < 2) {
                int j = h;
                float c01 = 0.f;
#pragma unroll
                for (int a = 0; a < 16; a++) {
                    int r = 128 + a * 2 + j;
                    c01 = fmaf(xl0[a], Cs[r * CPAD + el] + sB3[r], c01);
                }
                float dx = 0.f, dy = 0.f, dz = 0.f;
#pragma unroll
                for (int a = 0; a < 4; a++) {
                    int r = 160 + a * 2 + j;
                    float w = Cs[r * CPAD + el] + sB3[r];
                    dx = fmaf(g_eg[(size_t)(20 + a * 3 + 0) * E + ee], w, dx);
                    dy = fmaf(g_eg[(size_t)(20 + a * 3 + 1) * E + ee], w, dy);
                    dz = fmaf(g_eg[(size_t)(20 + a * 3 + 2) * E + ee], w, dz);
                }
                int jg = HALF * 2 + j;
                if (ok) {
                    atomicAdd(&g_agg[(size_t)d * 28 + 16 + jg * 3 + 0],
                              p * (NORM * (sh.y * c01 + sh.x * dx)));
                    atomicAdd(&g_agg[(size_t)d * 28 + 16 + jg * 3 + 1],
                              p * (NORM * (sh.z * c01 + sh.x * dy)));
                    atomicAdd(&g_agg[(size_t)d * 28 + 16 + jg * 3 + 2],
                              p * (NORM * (sh.w * c01 + sh.x * dz)));
                }
            }
            if (HALF == 0 && h == 0 && ok) atomicAdd(&g_z[d], p);
        }
        __syncthreads();
    }
}

// ---------------------------------------------------------------------------
__global__ void node_out_kernel(const float* __restrict__ na,
                                const float* __restrict__ Wo0,
                                const float* __restrict__ Wo1,
                                float* __restrict__ out, int N) {
    __shared__ float sW0[512], sW1[32];
    int tid = threadIdx.x;
    for (int i = tid; i < 512; i += blockDim.x) sW0[i] = Wo0[i];
    for (int i = tid; i < 32;  i += blockDim.x) sW1[i] = Wo1[i];
    __syncthreads();

    int n = blockIdx.x * blockDim.x + tid;
    if (n >= N) return;
    float z = g_z[n];
    float zi = z > 0.f ? 1.f / z : 0.f;
    float ag[28];
#pragma unroll
    for (int j = 0; j < 28; j++) ag[j] = g_agg[(size_t)n * 28 + j] * zi;

#pragma unroll
    for (int o = 0; o < 32; o++) {
        float s = 0.f;
#pragma unroll
        for (int a = 0; a < 16; a++) s = fmaf(ag[a], sW0[a * 32 + o], s);
        out[(size_t)n * 56 + o] = fmaf(s, 0.25f, na[(size_t)n * 56 + o]);
    }
#pragma unroll
    for (int o = 0; o < 8; o++)
#pragma unroll
        for (int c = 0; c < 3; c++) {
            float s = 0.f;
#pragma unroll
            for (int a = 0; a < 4; a++) s = fmaf(ag[16 + a * 3 + c], sW1[a * 8 + o], s);
            out[(size_t)n * 56 + 32 + o * 3 + c] =
                fmaf(s, 0.5f, na[(size_t)n * 56 + 32 + o * 3 + c]);
        }
}

// ---------------------------------------------------------------------------
extern "C" void kernel_launch(void* const* d_in, const int* in_sizes, int n_in,
                              void* d_out, int out_size) {
    const float* node_attr  = (const float*)d_in[0];
    const float* edge_attr  = (const float*)d_in[1];
    const float* edge_sh    = (const float*)d_in[2];
    const int*   edge_index = (const int*)  d_in[3];
    const float* W_in0  = (const float*)d_in[4];
    const float* W_in1  = (const float*)d_in[5];
    const float* Wq0    = (const float*)d_in[6];
    const float* Wq1    = (const float*)d_in[7];
    const float* Wd0    = (const float*)d_in[8];
    const float* Wd1    = (const float*)d_in[9];
    const float* W_out0 = (const float*)d_in[10];
    const float* W_out1 = (const float*)d_in[11];
    const float* fcW1 = (const float*)d_in[12];
    const float* fcb1 = (const float*)d_in[13];
    const float* fcW2 = (const float*)d_in[14];
    const float* fcb2 = (const float*)d_in[15];
    const float* fcW3 = (const float*)d_in[16];
    const float* fcb3 = (const float*)d_in[17];
    const float* fkW1 = (const float*)d_in[18];
    const float* fkb1 = (const float*)d_in[19];
    const float* fkW2 = (const float*)d_in[20];
    const float* fkb2 = (const float*)d_in[21];
    const float* fkW3 = (const float*)d_in[22];
    const float* fkb3 = (const float*)d_in[23];
    float* out = (float*)d_out;

    int N = in_sizes[0] / 56;
    int E = in_sizes[2] / 4;

    const int FRONT_SMEM = FT_FLOATS * (int)sizeof(float);  // 103936 B
    const int L3_SMEM    = L3_FLOATS * (int)sizeof(float);  // 211328 B

    cudaFuncSetAttribute(front_kernel,
                         cudaFuncAttributeMaxDynamicSharedMemorySize, FRONT_SMEM);
    cudaFuncSetAttribute(l3k_kernel,
                         cudaFuncAttributeMaxDynamicSharedMemorySize, L3_SMEM);
    cudaFuncSetAttribute(l3v_kernel<0>,
                         cudaFuncAttributeMaxDynamicSharedMemorySize, L3_SMEM);
    cudaFuncSetAttribute(l3v_kernel<1>,
                         cudaFuncAttributeMaxDynamicSharedMemorySize, L3_SMEM);

    int tiles = (E + TE - 1) / TE;

    node_prep_kernel<<<(N + 127) / 128, 128>>>(node_attr, W_in0, W_in1, Wq0, Wq1,
                                               Wd0, Wd1, N);
    init_kernel<<<(N * 28 + 255) / 256, 256>>>(N);
    edge_gather_kernel<<<(E + 255) / 256, 256>>>(edge_sh, edge_index, E);
    front_kernel<<<NSM * 2, 256, FRONT_SMEM>>>(edge_attr,
                                               fcW1, fcb1, fcW2, fcb2,
                                               fkW1, fkb1, fkW2, fkb2, E, tiles);
    l3k_kernel<<<NSM, L3_NT, L3_SMEM>>>(edge_index, edge_sh, fkW3, fkb3, E, tiles);
    l3v_kernel<0><<<NSM, L3_NT, L3_SMEM>>>(edge_index, edge_sh, fcW3, fcb3, E, tiles);
    l3v_kernel<1><<<NSM, L3_NT, L3_SMEM>>>(edge_index, edge_sh, fcW3, fcb3, E, tiles);
    node_out_kernel<<<(N + 127) / 128, 128>>>(node_attr, W_out0, W_out1, out, N);
}